// round 1
// baseline (speedup 1.0000x reference)
#include <cuda_runtime.h>
#include <cstdint>

// Problem constants
#define B_    64
#define Q_    900
#define T_    256
#define L_    769
#define NSEL  50
#define M_    (B_ * Q_)        // 57600 rows of the GEMM
#define NPB   (Q_ * L_)        // 692100 prob entries per batch

// Scratch (static device arrays: allocation-free per harness rules)
__device__ float g_sig[(size_t)M_ * T_];    // sigmoid(logits): 59 MB
__device__ float g_prob[(size_t)M_ * L_];   // prob matrix:    177 MB

__constant__ int c_tok[80] = {
    0, 9, 19, 25, 38, 49, 55, 63, 71, 78, 94, 109, 121, 137, 145, 152,
    158, 164, 172, 180, 186, 197, 204, 212, 222, 233, 244, 254, 260, 271,
    281, 288, 300, 314, 321, 336, 353, 366, 378, 394, 403, 416, 422, 429,
    437, 445, 452, 461, 469, 480, 489, 500, 509, 519, 527, 535, 542, 550,
    558, 573, 579, 594, 603, 608, 617, 625, 634, 645, 658, 670, 677, 687,
    694, 709, 716, 724, 731, 742, 755, 768};

// ---------------------------------------------------------------------------
// Kernel 1: sigmoid precompute (bandwidth-bound, vectorized)
// ---------------------------------------------------------------------------
__global__ void sigmoid_kernel(const float* __restrict__ x, int n4) {
    int i = blockIdx.x * blockDim.x + threadIdx.x;
    if (i < n4) {
        float4 v = reinterpret_cast<const float4*>(x)[i];
        float4 r;
        r.x = 1.0f / (1.0f + __expf(-v.x));
        r.y = 1.0f / (1.0f + __expf(-v.y));
        r.z = 1.0f / (1.0f + __expf(-v.z));
        r.w = 1.0f / (1.0f + __expf(-v.w));
        reinterpret_cast<float4*>(g_sig)[i] = r;
    }
}

// ---------------------------------------------------------------------------
// Kernel 2: fp32 SIMT GEMM  C[m][l] = sum_t g_sig[m][t] * pos_map[l][t]
// Both operands are K-contiguous (NT gemm of row dot-products).
// BM=BN=128, BK=16, 256 threads, 8x8 micro-tile per thread.
// ---------------------------------------------------------------------------
#define BM 128
#define BN 128
#define BK 16

__global__ __launch_bounds__(256) void gemm_kernel(const float* __restrict__ Bmat) {
    __shared__ float As[BK][BM];
    __shared__ float Bs[BK][BN];

    const int m0  = blockIdx.x * BM;
    const int l0  = blockIdx.y * BN;
    const int tid = threadIdx.x;
    const int tx  = tid & 15;   // N direction (8 cols each)
    const int ty  = tid >> 4;   // M direction (8 rows each)

    float acc[8][8];
#pragma unroll
    for (int i = 0; i < 8; i++)
#pragma unroll
        for (int j = 0; j < 8; j++) acc[i][j] = 0.0f;

    for (int k0 = 0; k0 < T_; k0 += BK) {
        // Load A tile (128x16) — 512 float4, 2 per thread, store transposed
#pragma unroll
        for (int t = 0; t < 2; t++) {
            int f4 = tid + t * 256;
            int r  = f4 >> 2;
            int c4 = f4 & 3;
            float4 v = *reinterpret_cast<const float4*>(
                g_sig + (size_t)(m0 + r) * T_ + k0 + c4 * 4);
            As[c4 * 4 + 0][r] = v.x;
            As[c4 * 4 + 1][r] = v.y;
            As[c4 * 4 + 2][r] = v.z;
            As[c4 * 4 + 3][r] = v.w;
        }
        // Load B tile (128x16) with row guard (L=769)
#pragma unroll
        for (int t = 0; t < 2; t++) {
            int f4 = tid + t * 256;
            int r  = f4 >> 2;
            int c4 = f4 & 3;
            int l  = l0 + r;
            float4 v = make_float4(0.f, 0.f, 0.f, 0.f);
            if (l < L_)
                v = *reinterpret_cast<const float4*>(
                    Bmat + (size_t)l * T_ + k0 + c4 * 4);
            Bs[c4 * 4 + 0][r] = v.x;
            Bs[c4 * 4 + 1][r] = v.y;
            Bs[c4 * 4 + 2][r] = v.z;
            Bs[c4 * 4 + 3][r] = v.w;
        }
        __syncthreads();

#pragma unroll
        for (int k = 0; k < BK; k++) {
            float ra[8], rb[8];
            *reinterpret_cast<float4*>(&ra[0]) =
                *reinterpret_cast<const float4*>(&As[k][ty * 8]);
            *reinterpret_cast<float4*>(&ra[4]) =
                *reinterpret_cast<const float4*>(&As[k][ty * 8 + 4]);
            *reinterpret_cast<float4*>(&rb[0]) =
                *reinterpret_cast<const float4*>(&Bs[k][tx * 8]);
            *reinterpret_cast<float4*>(&rb[4]) =
                *reinterpret_cast<const float4*>(&Bs[k][tx * 8 + 4]);
#pragma unroll
            for (int i = 0; i < 8; i++)
#pragma unroll
                for (int j = 0; j < 8; j++) acc[i][j] += ra[i] * rb[j];
        }
        __syncthreads();
    }

    // Store (scalar: 769 is odd so rows have mixed alignment)
#pragma unroll
    for (int i = 0; i < 8; i++) {
        int m = m0 + ty * 8 + i;
#pragma unroll
        for (int j = 0; j < 8; j++) {
            int l = l0 + tx * 8 + j;
            if (l < L_) g_prob[(size_t)m * L_ + l] = acc[i][j];
        }
    }
}

// ---------------------------------------------------------------------------
// Kernel 3: exact per-batch top-50 via 2-level 13-bit radix select + epilogue
// One block (1024 threads) per batch. Positive floats => uint bits monotone.
// ---------------------------------------------------------------------------
__global__ __launch_bounds__(1024) void select_kernel(
    const float* __restrict__ bbox,   // (B,Q,4) cxcywh
    const float* __restrict__ tsz,    // (B,2)  [h, w]
    float* __restrict__ out)
{
    const int b    = blockIdx.x;
    const float* base = g_prob + (size_t)b * NPB;
    const int tid  = threadIdx.x;
    const int lane = tid & 31;
    const unsigned SENT = 0xFFFFFFFFu;

    __shared__ union {
        struct { unsigned hist[8192]; unsigned chunk[1024]; } h;   // 36 KB
        struct { float cv[2048]; int ci[2048]; } c;                // 16 KB
    } sm;
    __shared__ unsigned s_b1, s_above1, s_b2;
    __shared__ int s_ccnt;

    // ---- Phase 1: histogram of bits[31:19] (8192 bins) ----
    for (int i = tid; i < 8192; i += 1024) sm.h.hist[i] = 0;
    __syncthreads();
    for (int i0 = 0; i0 < NPB; i0 += 1024) {
        int i = i0 + tid;
        unsigned bin = SENT;
        if (i < NPB) bin = __float_as_uint(base[i]) >> 19;
        unsigned mm = __match_any_sync(0xFFFFFFFFu, bin);
        if (bin != SENT && lane == (__ffs(mm) - 1))
            atomicAdd(&sm.h.hist[bin], (unsigned)__popc(mm));
    }
    __syncthreads();
    // find largest bin b1 with suffix count >= NSEL
    {
        unsigned c = 0;
#pragma unroll
        for (int k = 0; k < 8; k++) c += sm.h.hist[tid * 8 + k];
        sm.h.chunk[tid] = c;
        __syncthreads();
        for (int off = 1; off < 1024; off <<= 1) {
            unsigned add = (tid + off < 1024) ? sm.h.chunk[tid + off] : 0u;
            __syncthreads();
            sm.h.chunk[tid] += add;
            __syncthreads();
        }
        unsigned above = (tid < 1023) ? sm.h.chunk[tid + 1] : 0u;
        if (above < NSEL && above + c >= NSEL) {
            unsigned run = above;
            for (int k = 7; k >= 0; k--) {
                unsigned h = sm.h.hist[tid * 8 + k];
                if (run + h >= NSEL) { s_b1 = tid * 8 + k; s_above1 = run; break; }
                run += h;
            }
        }
    }
    __syncthreads();
    const unsigned b1      = s_b1;
    const unsigned target2 = NSEL - s_above1;   // >= 1

    // ---- Phase 2: histogram of bits[18:6] among elements in bin b1 ----
    for (int i = tid; i < 8192; i += 1024) sm.h.hist[i] = 0;
    __syncthreads();
    for (int i0 = 0; i0 < NPB; i0 += 1024) {
        int i = i0 + tid;
        unsigned bin = SENT;
        if (i < NPB) {
            unsigned key = __float_as_uint(base[i]);
            if ((key >> 19) == b1) bin = (key >> 6) & 8191u;
        }
        unsigned mm = __match_any_sync(0xFFFFFFFFu, bin);
        if (bin != SENT && lane == (__ffs(mm) - 1))
            atomicAdd(&sm.h.hist[bin], (unsigned)__popc(mm));
    }
    __syncthreads();
    {
        unsigned c = 0;
#pragma unroll
        for (int k = 0; k < 8; k++) c += sm.h.hist[tid * 8 + k];
        sm.h.chunk[tid] = c;
        __syncthreads();
        for (int off = 1; off < 1024; off <<= 1) {
            unsigned add = (tid + off < 1024) ? sm.h.chunk[tid + off] : 0u;
            __syncthreads();
            sm.h.chunk[tid] += add;
            __syncthreads();
        }
        unsigned above = (tid < 1023) ? sm.h.chunk[tid + 1] : 0u;
        if (above < target2 && above + c >= target2) {
            unsigned run = above;
            for (int k = 7; k >= 0; k--) {
                unsigned h = sm.h.hist[tid * 8 + k];
                if (run + h >= target2) { s_b2 = tid * 8 + k; break; }
                run += h;
            }
        }
    }
    __syncthreads();
    const unsigned P26 = (b1 << 13) | s_b2;   // 26-bit threshold prefix

    // ---- Phase 3: collect candidates (count >= 50, expected ~50-60) ----
    if (tid == 0) s_ccnt = 0;
    __syncthreads();    // also fences hist before union reuse
    for (int i0 = 0; i0 < NPB; i0 += 1024) {
        int i = i0 + tid;
        if (i < NPB) {
            float v = base[i];
            unsigned key = __float_as_uint(v);
            if ((key >> 6) >= P26) {
                int p = atomicAdd(&s_ccnt, 1);
                if (p < 2048) { sm.c.cv[p] = v; sm.c.ci[p] = i; }
            }
        }
    }
    __syncthreads();
    int K = s_ccnt < 2048 ? s_ccnt : 2048;

    // ---- Phase 4: exact rank (value desc, index asc) + epilogue ----
    for (int j = tid; j < K; j += 1024) {
        float vj = sm.c.cv[j];
        int   ij = sm.c.ci[j];
        int rank = 0;
        for (int i = 0; i < K; i++) {
            float vi = sm.c.cv[i];
            int   ii = sm.c.ci[i];
            if (vi > vj || (vi == vj && ii < ij)) rank++;
        }
        if (rank < NSEL) {
            int o = b * NSEL + rank;
            out[o] = vj;                              // topk_vals
            int q = ij / L_;
            int l = ij - q * L_;
            int label = 0;
#pragma unroll
            for (int t = 0; t < 80; t++)
                if (c_tok[t] == l) label = t;
            out[B_ * NSEL + o] = (float)label;        // class_labels
            const float* bb = bbox + (size_t)(b * Q_ + q) * 4;
            float cx = bb[0], cy = bb[1], w = bb[2], h = bb[3];
            float ih = tsz[2 * b + 0], iw = tsz[2 * b + 1];
            float* ob = out + 2 * B_ * NSEL + (size_t)o * 4;   // boxes
            ob[0] = (cx - 0.5f * w) * iw;
            ob[1] = (cy - 0.5f * h) * ih;
            ob[2] = (cx + 0.5f * w) * iw;
            ob[3] = (cy + 0.5f * h) * ih;
        }
    }
}

// ---------------------------------------------------------------------------
extern "C" void kernel_launch(void* const* d_in, const int* in_sizes, int n_in,
                              void* d_out, int out_size) {
    const float* logits = (const float*)d_in[0];   // (64,900,256)
    const float* bbox   = (const float*)d_in[1];   // (64,900,4)
    const float* posmap = (const float*)d_in[2];   // (769,256)
    const float* tsz    = (const float*)d_in[3];   // (64,2)
    float* out = (float*)d_out;

    const int n4 = (M_ * T_) / 4;
    sigmoid_kernel<<<(n4 + 255) / 256, 256>>>(logits, n4);

    dim3 grid(M_ / BM, (L_ + BN - 1) / BN);   // 450 x 7
    gemm_kernel<<<grid, 256>>>(posmap);

    select_kernel<<<B_, 1024>>>(bbox, tsz, out);
}

// round 5
// speedup vs baseline: 2.9617x; 2.9617x over previous
#include <cuda_runtime.h>
#include <cuda_fp16.h>
#include <cuda_bf16.h>
#include <cstdint>

// Problem constants
#define B_    64
#define Q_    900
#define T_    256
#define L_    769
#define LP    772            // padded row stride for half prob
#define NSEL  50
#define M_    (B_ * Q_)      // 57600
#define NBIN  8192
#define CCAP  4096
#define MARGIN 2.0f

// Scratch (static device globals; allocation-free)
__device__ float          g_sig[(size_t)M_ * T_];      // fp32 sigmoid, 59 MB (rescore)
__device__ __nv_bfloat16  g_sig_b[(size_t)M_ * T_];    // bf16 sigmoid, 29.5 MB (gemm)
__device__ __nv_bfloat16  g_pos_b[(size_t)L_ * T_];    // bf16 posmap
__device__ __half         g_prob_h[(size_t)M_ * LP];   // approx prob fp16, 89 MB
__device__ unsigned       g_hist[B_][NBIN];
__device__ float          g_tau[B_];
__device__ int            g_ccnt[B_];
__device__ int            g_cand[B_][CCAP];

__constant__ int c_tok[80] = {
    0, 9, 19, 25, 38, 49, 55, 63, 71, 78, 94, 109, 121, 137, 145, 152,
    158, 164, 172, 180, 186, 197, 204, 212, 222, 233, 244, 254, 260, 271,
    281, 288, 300, 314, 321, 336, 353, 366, 378, 394, 403, 416, 422, 429,
    437, 445, 452, 461, 469, 480, 489, 500, 509, 519, 527, 535, 542, 550,
    558, 573, 579, 594, 603, 608, 617, 625, 634, 645, 658, 670, 677, 687,
    694, 709, 716, 724, 731, 742, 755, 768};

// ---------------------------------------------------------------------------
// Helpers
// ---------------------------------------------------------------------------
__device__ __forceinline__ uint32_t smem_u32(const void* p) {
    uint32_t a;
    asm("{ .reg .u64 t; cvta.to.shared.u64 t, %1; cvt.u32.u64 %0, t; }" : "=r"(a) : "l"(p));
    return a;
}
__device__ __forceinline__ void cp_async16(uint32_t dst, const void* src, bool valid) {
    int sz = valid ? 16 : 0;   // src-size 0 => zero-fill 16B
    asm volatile("cp.async.cg.shared.global [%0], [%1], 16, %2;\n"
                 :: "r"(dst), "l"(src), "r"(sz));
}
__device__ __forceinline__ void cp_commit() { asm volatile("cp.async.commit_group;"); }
template <int N> __device__ __forceinline__ void cp_wait() {
    asm volatile("cp.async.wait_group %0;" :: "n"(N));
}
__device__ __forceinline__ void ldmatrix_x4(uint32_t* f, uint32_t addr) {
    asm volatile("ldmatrix.sync.aligned.m8n8.x4.shared.b16 {%0,%1,%2,%3}, [%4];"
                 : "=r"(f[0]), "=r"(f[1]), "=r"(f[2]), "=r"(f[3]) : "r"(addr));
}
__device__ __forceinline__ void mma_bf16(float* d, const uint32_t* a,
                                         uint32_t b0, uint32_t b1) {
    asm volatile(
        "mma.sync.aligned.m16n8k16.row.col.f32.bf16.bf16.f32 "
        "{%0,%1,%2,%3}, {%4,%5,%6,%7}, {%8,%9}, {%0,%1,%2,%3};"
        : "+f"(d[0]), "+f"(d[1]), "+f"(d[2]), "+f"(d[3])
        : "r"(a[0]), "r"(a[1]), "r"(a[2]), "r"(a[3]), "r"(b0), "r"(b1));
}

// ---------------------------------------------------------------------------
// Kernel 0: zero hist + counters
// ---------------------------------------------------------------------------
__global__ void zero_kernel() {
    int i = blockIdx.x * blockDim.x + threadIdx.x;
    if (i < B_ * NBIN) ((unsigned*)g_hist)[i] = 0;
    if (i < B_) g_ccnt[i] = 0;
}

// ---------------------------------------------------------------------------
// Kernel 1: sigmoid -> fp32 + bf16
// ---------------------------------------------------------------------------
__global__ void sigmoid_kernel(const float* __restrict__ x, int n4) {
    int i = blockIdx.x * blockDim.x + threadIdx.x;
    if (i < n4) {
        float4 v = reinterpret_cast<const float4*>(x)[i];
        float4 r;
        r.x = 1.0f / (1.0f + __expf(-v.x));
        r.y = 1.0f / (1.0f + __expf(-v.y));
        r.z = 1.0f / (1.0f + __expf(-v.z));
        r.w = 1.0f / (1.0f + __expf(-v.w));
        reinterpret_cast<float4*>(g_sig)[i] = r;
        __nv_bfloat162* o = reinterpret_cast<__nv_bfloat162*>(g_sig_b) + 2 * i;
        o[0] = __floats2bfloat162_rn(r.x, r.y);
        o[1] = __floats2bfloat162_rn(r.z, r.w);
    }
}

// ---------------------------------------------------------------------------
// Kernel 1b: posmap fp32 -> bf16
// ---------------------------------------------------------------------------
__global__ void posconv_kernel(const float* __restrict__ p, int n2) {
    int i = blockIdx.x * blockDim.x + threadIdx.x;
    if (i < n2) {
        float2 v = reinterpret_cast<const float2*>(p)[i];
        reinterpret_cast<__nv_bfloat162*>(g_pos_b)[i] = __floats2bfloat162_rn(v.x, v.y);
    }
}

// ---------------------------------------------------------------------------
// Kernel 2: bf16 mma.sync GEMM, CTA 128x128, BK=32, 4-buffer cp.async pipeline
// smem stage: A 128x32 bf16 (8KB) + B 128x32 bf16 (8KB); 4 stages = 64KB
// 8 warps as 4(m) x 2(n); warp tile 32x64; mma m16n8k16
// ---------------------------------------------------------------------------
#define STG_BYTES 16384
#define NSTG 8   // 256/32 k-stages

__global__ __launch_bounds__(256) void gemm_kernel() {
    extern __shared__ char dsm[];
    const uint32_t sbase = smem_u32(dsm);
    const int tid  = threadIdx.x;
    const int wid  = tid >> 5;
    const int lane = tid & 31;
    const int wm   = wid & 3;      // 0..3 (m)
    const int wn   = wid >> 2;     // 0..1 (n)
    const int m0   = blockIdx.x * 128;
    const int l0   = blockIdx.y * 128;

    float acc[2][8][4];
#pragma unroll
    for (int a = 0; a < 2; a++)
#pragma unroll
        for (int b = 0; b < 8; b++)
#pragma unroll
            for (int c = 0; c < 4; c++) acc[a][b][c] = 0.0f;

    auto load_stage = [&](int s) {
        const uint32_t base = sbase + (s & 3) * STG_BYTES;
        const int k0 = s * 32;
#pragma unroll
        for (int t = 0; t < 2; t++) {              // A: 512 chunks of 16B
            int ch = tid + t * 256;
            int r  = ch >> 2;
            int cc = ch & 3;
            int ph = cc ^ ((r >> 1) & 3);
            cp_async16(base + r * 64 + ph * 16,
                       g_sig_b + (size_t)(m0 + r) * T_ + k0 + cc * 8, true);
        }
#pragma unroll
        for (int t = 0; t < 2; t++) {              // B
            int ch = tid + t * 256;
            int r  = ch >> 2;
            int cc = ch & 3;
            int ph = cc ^ ((r >> 1) & 3);
            bool ok = (l0 + r) < L_;
            cp_async16(base + 8192 + r * 64 + ph * 16,
                       g_pos_b + (size_t)(l0 + r) * T_ + k0 + cc * 8, ok);
        }
        cp_commit();
    };

    load_stage(0);
    load_stage(1);

    const int j  = lane >> 3;   // ldmatrix sub-matrix index
    const int r8 = lane & 7;

    for (int s = 0; s < NSTG; s++) {
        // Prefetch s+2 FIRST, then wait so that stage s is actually retired.
        // Pending groups at the wait: {s, s+1, s+2} -> wait_group 2 retires s.
        // Buffer (s+2)&3 was last read at stage s-2; every warp passed the
        // barrier of iteration s-1 (which is after compute s-2) -> safe.
        if (s + 2 < NSTG) { load_stage(s + 2); cp_wait<2>(); }
        else if (s + 1 < NSTG) cp_wait<1>();
        else cp_wait<0>();
        __syncthreads();

        const uint32_t ab = sbase + (s & 3) * STG_BYTES;
        const uint32_t bb = ab + 8192;

#pragma unroll
        for (int ks = 0; ks < 2; ks++) {
            uint32_t Af[2][4];
#pragma unroll
            for (int mt = 0; mt < 2; mt++) {
                int rl = wm * 32 + mt * 16 + ((j & 1) << 3) + r8;
                int cc = ks * 2 + (j >> 1);
                int ph = cc ^ ((rl >> 1) & 3);
                ldmatrix_x4(Af[mt], ab + rl * 64 + ph * 16);
            }
#pragma unroll
            for (int np = 0; np < 4; np++) {
                uint32_t Bf[4];
                int nl = wn * 64 + np * 16 + ((j >> 1) << 3) + r8;
                int cc = ks * 2 + (j & 1);
                int ph = cc ^ ((nl >> 1) & 3);
                ldmatrix_x4(Bf, bb + nl * 64 + ph * 16);
#pragma unroll
                for (int mt = 0; mt < 2; mt++) {
                    mma_bf16(acc[mt][2 * np],     Af[mt], Bf[0], Bf[1]);
                    mma_bf16(acc[mt][2 * np + 1], Af[mt], Bf[2], Bf[3]);
                }
            }
        }
    }

    // Epilogue -> fp16 prob
    const int g  = lane >> 2;
    const int t4 = lane & 3;
#pragma unroll
    for (int mt = 0; mt < 2; mt++) {
#pragma unroll
        for (int nt = 0; nt < 8; nt++) {
            int row = m0 + wm * 32 + mt * 16 + g;
            int col = l0 + wn * 64 + nt * 8 + t4 * 2;
            float v0 = acc[mt][nt][0], v1 = acc[mt][nt][1];
            float v2 = acc[mt][nt][2], v3 = acc[mt][nt][3];
            if (col + 1 < L_) {
                *reinterpret_cast<__half2*>(g_prob_h + (size_t)row * LP + col) =
                    __floats2half2_rn(v0, v1);
                *reinterpret_cast<__half2*>(g_prob_h + (size_t)(row + 8) * LP + col) =
                    __floats2half2_rn(v2, v3);
            } else if (col < L_) {
                g_prob_h[(size_t)row * LP + col] = __float2half(v0);
                g_prob_h[(size_t)(row + 8) * LP + col] = __float2half(v2);
            }
        }
    }
}

// ---------------------------------------------------------------------------
// Kernel 3: per-batch histogram of half bits[15:3]  (grid 64 x 8)
// ---------------------------------------------------------------------------
__global__ __launch_bounds__(256) void hist_kernel() {
    __shared__ unsigned h[NBIN];
    const int b    = blockIdx.x;
    const int part = blockIdx.y;
    const int tid  = threadIdx.x;
    for (int i = tid; i < NBIN; i += 256) h[i] = 0;
    __syncthreads();

    int r0 = part * 113;
    int r1 = min(r0 + 113, Q_);
    for (int r = r0; r < r1; r++) {
        const __half* row = g_prob_h + (size_t)(b * Q_ + r) * LP;
        for (int l = tid; l < L_; l += 256) {
            unsigned short bits = __half_as_ushort(row[l]);
            atomicAdd(&h[bits >> 3], 1u);
        }
    }
    __syncthreads();
    for (int i = tid; i < NBIN; i += 256)
        if (h[i]) atomicAdd(&g_hist[b][i], h[i]);
}

// ---------------------------------------------------------------------------
// Kernel 4: per-batch threshold (grid 64, block 256)
// ---------------------------------------------------------------------------
__global__ __launch_bounds__(256) void thresh_kernel() {
    const int b   = blockIdx.x;
    const int tid = threadIdx.x;
    __shared__ unsigned chunk[256];
    unsigned c = 0;
    unsigned local[32];
#pragma unroll
    for (int k = 0; k < 32; k++) {
        local[k] = g_hist[b][tid * 32 + k];
        c += local[k];
    }
    chunk[tid] = c;
    __syncthreads();
    for (int off = 1; off < 256; off <<= 1) {
        unsigned add = (tid + off < 256) ? chunk[tid + off] : 0u;
        __syncthreads();
        chunk[tid] += add;
        __syncthreads();
    }
    unsigned above = (tid < 255) ? chunk[tid + 1] : 0u;
    if (above < NSEL && above + c >= NSEL) {
        unsigned run = above;
        for (int k = 31; k >= 0; k--) {
            if (run + local[k] >= NSEL) {
                unsigned bin = tid * 32 + k;
                float lo = __half2float(__ushort_as_half((unsigned short)(bin << 3)));
                g_tau[b] = lo - MARGIN;
                break;
            }
            run += local[k];
        }
    }
}

// ---------------------------------------------------------------------------
// Kernel 5: collect candidates above tau (grid 57600)
// ---------------------------------------------------------------------------
__global__ __launch_bounds__(256) void collect_kernel() {
    const int m = blockIdx.x;
    const int b = m / Q_;
    const int q = m - b * Q_;
    const float tau = g_tau[b];
    const __half* row = g_prob_h + (size_t)m * LP;
    for (int l = threadIdx.x; l < L_; l += 256) {
        if (__half2float(row[l]) >= tau) {
            int p = atomicAdd(&g_ccnt[b], 1);
            if (p < CCAP) g_cand[b][p] = q * L_ + l;
        }
    }
}

// ---------------------------------------------------------------------------
// Kernel 6: fp32 rescore + exact top-50 + epilogue (grid 64)
// ---------------------------------------------------------------------------
__global__ __launch_bounds__(1024) void final_kernel(
    const float* __restrict__ bbox, const float* __restrict__ tsz,
    float* __restrict__ out, const float* __restrict__ posmap)
{
    const int b    = blockIdx.x;
    const int tid  = threadIdx.x;
    const int wid  = tid >> 5;
    const int lane = tid & 31;
    __shared__ float s_cv[CCAP];
    __shared__ int   s_ci[CCAP];

    int K = g_ccnt[b];
    if (K > CCAP) K = CCAP;

    for (int c = wid; c < K; c += 32) {
        int idx = g_cand[b][c];
        int q = idx / L_;
        int l = idx - q * L_;
        const float4* a = reinterpret_cast<const float4*>(
            g_sig + (size_t)(b * Q_ + q) * T_ + lane * 8);
        const float4* p = reinterpret_cast<const float4*>(
            posmap + (size_t)l * T_ + lane * 8);
        float4 a0 = a[0], a1 = a[1], p0 = p[0], p1 = p[1];
        float s = a0.x * p0.x + a0.y * p0.y + a0.z * p0.z + a0.w * p0.w
                + a1.x * p1.x + a1.y * p1.y + a1.z * p1.z + a1.w * p1.w;
#pragma unroll
        for (int o = 16; o > 0; o >>= 1) s += __shfl_xor_sync(0xFFFFFFFFu, s, o);
        if (lane == 0) { s_cv[c] = s; s_ci[c] = idx; }
    }
    __syncthreads();

    for (int jj = tid; jj < K; jj += 1024) {
        float vj = s_cv[jj];
        int   ij = s_ci[jj];
        int rank = 0;
        for (int i = 0; i < K; i++) {
            float vi = s_cv[i];
            int   ii = s_ci[i];
            if (vi > vj || (vi == vj && ii < ij)) rank++;
        }
        if (rank < NSEL) {
            int o = b * NSEL + rank;
            out[o] = vj;
            int q = ij / L_;
            int l = ij - q * L_;
            int label = 0;
#pragma unroll
            for (int t = 0; t < 80; t++)
                if (c_tok[t] == l) label = t;
            out[B_ * NSEL + o] = (float)label;
            const float* bb = bbox + (size_t)(b * Q_ + q) * 4;
            float cx = bb[0], cy = bb[1], w = bb[2], h = bb[3];
            float ih = tsz[2 * b + 0], iw = tsz[2 * b + 1];
            float* ob = out + 2 * B_ * NSEL + (size_t)o * 4;
            ob[0] = (cx - 0.5f * w) * iw;
            ob[1] = (cy - 0.5f * h) * ih;
            ob[2] = (cx + 0.5f * w) * iw;
            ob[3] = (cy + 0.5f * h) * ih;
        }
    }
}

// ---------------------------------------------------------------------------
extern "C" void kernel_launch(void* const* d_in, const int* in_sizes, int n_in,
                              void* d_out, int out_size) {
    const float* logits = (const float*)d_in[0];
    const float* bbox   = (const float*)d_in[1];
    const float* posmap = (const float*)d_in[2];
    const float* tsz    = (const float*)d_in[3];
    float* out = (float*)d_out;

    cudaFuncSetAttribute(gemm_kernel,
        cudaFuncAttributeMaxDynamicSharedMemorySize, 4 * STG_BYTES);

    zero_kernel<<<(B_ * NBIN + 1023) / 1024, 1024>>>();

    const int n4 = (M_ * T_) / 4;
    sigmoid_kernel<<<(n4 + 255) / 256, 256>>>(logits, n4);
    posconv_kernel<<<(L_ * T_ / 2 + 255) / 256, 256>>>(posmap, L_ * T_ / 2);

    dim3 ggrid(M_ / 128, (L_ + 127) / 128);   // 450 x 7
    gemm_kernel<<<ggrid, 256, 4 * STG_BYTES>>>();

    dim3 hgrid(B_, 8);
    hist_kernel<<<hgrid, 256>>>();
    thresh_kernel<<<B_, 256>>>();
    collect_kernel<<<M_, 256>>>();
    final_kernel<<<B_, 1024>>>(bbox, tsz, out, posmap);
}

// round 8
// speedup vs baseline: 3.8348x; 1.2948x over previous
#include <cuda_runtime.h>
#include <cuda_fp16.h>
#include <cuda_bf16.h>
#include <cstdint>

// Problem constants
#define B_    64
#define Q_    900
#define T_    256
#define L_    769
#define LP    776            // padded row stride (16B-aligned rows of half)
#define NSEL  50
#define M_    (B_ * Q_)      // 57600
#define CCAP  8192
#define NTH   16             // threshold ladder size
#define CMIN  512u           // minimum candidate count for a valid threshold

// Scratch (static device globals; allocation-free)
__device__ __nv_bfloat16  g_sig_b[(size_t)M_ * T_];    // bf16 sigmoid, 29.5 MB
__device__ __nv_bfloat16  g_pos_b[(size_t)L_ * T_];    // bf16 posmap
__device__ __half         g_prob_h[(size_t)M_ * LP];   // approx prob fp16, 89 MB
__device__ unsigned       g_maxbits[B_];               // per-batch max (uint-ordered)
__device__ unsigned       g_lcnt[B_][NTH];             // ladder counts
__device__ float          g_tau[B_];
__device__ int            g_ccnt[B_];
__device__ int            g_cand[B_][CCAP];

__constant__ int c_tok[80] = {
    0, 9, 19, 25, 38, 49, 55, 63, 71, 78, 94, 109, 121, 137, 145, 152,
    158, 164, 172, 180, 186, 197, 204, 212, 222, 233, 244, 254, 260, 271,
    281, 288, 300, 314, 321, 336, 353, 366, 378, 394, 403, 416, 422, 429,
    437, 445, 452, 461, 469, 480, 489, 500, 509, 519, 527, 535, 542, 550,
    558, 573, 579, 594, 603, 608, 617, 625, 634, 645, 658, 670, 677, 687,
    694, 709, 716, 724, 731, 742, 755, 768};

// ---------------------------------------------------------------------------
// Helpers
// ---------------------------------------------------------------------------
__device__ __forceinline__ uint32_t smem_u32(const void* p) {
    uint32_t a;
    asm("{ .reg .u64 t; cvta.to.shared.u64 t, %1; cvt.u32.u64 %0, t; }" : "=r"(a) : "l"(p));
    return a;
}
__device__ __forceinline__ void cp_async16(uint32_t dst, const void* src, bool valid) {
    int sz = valid ? 16 : 0;   // src-size 0 => zero-fill 16B
    asm volatile("cp.async.cg.shared.global [%0], [%1], 16, %2;\n"
                 :: "r"(dst), "l"(src), "r"(sz));
}
__device__ __forceinline__ void cp_commit() { asm volatile("cp.async.commit_group;"); }
template <int N> __device__ __forceinline__ void cp_wait() {
    asm volatile("cp.async.wait_group %0;" :: "n"(N));
}
__device__ __forceinline__ void ldmatrix_x4(uint32_t* f, uint32_t addr) {
    asm volatile("ldmatrix.sync.aligned.m8n8.x4.shared.b16 {%0,%1,%2,%3}, [%4];"
                 : "=r"(f[0]), "=r"(f[1]), "=r"(f[2]), "=r"(f[3]) : "r"(addr));
}
__device__ __forceinline__ void mma_bf16(float* d, const uint32_t* a,
                                         uint32_t b0, uint32_t b1) {
    asm volatile(
        "mma.sync.aligned.m16n8k16.row.col.f32.bf16.bf16.f32 "
        "{%0,%1,%2,%3}, {%4,%5,%6,%7}, {%8,%9}, {%0,%1,%2,%3};"
        : "+f"(d[0]), "+f"(d[1]), "+f"(d[2]), "+f"(d[3])
        : "r"(a[0]), "r"(a[1]), "r"(a[2]), "r"(a[3]), "r"(b0), "r"(b1));
}
__device__ __forceinline__ float sigf(float x) {
    return 1.0f / (1.0f + __expf(-x));
}

// ---------------------------------------------------------------------------
// Kernel 0: reset counters + fill pad columns (769..775) with -inf
// ---------------------------------------------------------------------------
__global__ void zero_kernel() {
    int i = blockIdx.x * blockDim.x + threadIdx.x;
    if (i < M_) {
        uint4 ninf = make_uint4(0xFC00FC00u, 0xFC00FC00u, 0xFC00FC00u, 0xFC00FC00u);
        *reinterpret_cast<uint4*>(g_prob_h + (size_t)i * LP + 768) = ninf;
    }
    if (i < B_) { g_ccnt[i] = 0; g_maxbits[i] = 0u; }
    if (i < B_ * NTH) ((unsigned*)g_lcnt)[i] = 0u;
}

// ---------------------------------------------------------------------------
// Kernel 1: sigmoid -> bf16
// ---------------------------------------------------------------------------
__global__ void sigmoid_kernel(const float* __restrict__ x, int n4) {
    int i = blockIdx.x * blockDim.x + threadIdx.x;
    if (i < n4) {
        float4 v = reinterpret_cast<const float4*>(x)[i];
        __nv_bfloat162* o = reinterpret_cast<__nv_bfloat162*>(g_sig_b) + 2 * i;
        o[0] = __floats2bfloat162_rn(sigf(v.x), sigf(v.y));
        o[1] = __floats2bfloat162_rn(sigf(v.z), sigf(v.w));
    }
}

// ---------------------------------------------------------------------------
// Kernel 1b: posmap fp32 -> bf16
// ---------------------------------------------------------------------------
__global__ void posconv_kernel(const float* __restrict__ p, int n2) {
    int i = blockIdx.x * blockDim.x + threadIdx.x;
    if (i < n2) {
        float2 v = reinterpret_cast<const float2*>(p)[i];
        reinterpret_cast<__nv_bfloat162*>(g_pos_b)[i] = __floats2bfloat162_rn(v.x, v.y);
    }
}

// ---------------------------------------------------------------------------
// Kernel 2: bf16 mma.sync GEMM, CTA 128x128, BK=32, 4-buffer cp.async
// Epilogue also reduces the per-batch max into g_maxbits.
// ---------------------------------------------------------------------------
#define STG_BYTES 16384
#define NSTG 8   // 256/32 k-stages

__global__ __launch_bounds__(256) void gemm_kernel() {
    extern __shared__ char dsm[];
    const uint32_t sbase = smem_u32(dsm);
    __shared__ unsigned s_mx0, s_mx1;
    const int tid  = threadIdx.x;
    const int wid  = tid >> 5;
    const int lane = tid & 31;
    const int wm   = wid & 3;      // 0..3 (m)
    const int wn   = wid >> 2;     // 0..1 (n)
    const int m0   = blockIdx.x * 128;
    const int l0   = blockIdx.y * 128;

    if (tid == 0) { s_mx0 = 0u; s_mx1 = 0u; }

    float acc[2][8][4];
#pragma unroll
    for (int a = 0; a < 2; a++)
#pragma unroll
        for (int b = 0; b < 8; b++)
#pragma unroll
            for (int c = 0; c < 4; c++) acc[a][b][c] = 0.0f;

    auto load_stage = [&](int s) {
        const uint32_t base = sbase + (s & 3) * STG_BYTES;
        const int k0 = s * 32;
#pragma unroll
        for (int t = 0; t < 2; t++) {              // A
            int ch = tid + t * 256;
            int r  = ch >> 2;
            int cc = ch & 3;
            int ph = cc ^ ((r >> 1) & 3);
            cp_async16(base + r * 64 + ph * 16,
                       g_sig_b + (size_t)(m0 + r) * T_ + k0 + cc * 8, true);
        }
#pragma unroll
        for (int t = 0; t < 2; t++) {              // B
            int ch = tid + t * 256;
            int r  = ch >> 2;
            int cc = ch & 3;
            int ph = cc ^ ((r >> 1) & 3);
            bool ok = (l0 + r) < L_;
            cp_async16(base + 8192 + r * 64 + ph * 16,
                       g_pos_b + (size_t)(l0 + r) * T_ + k0 + cc * 8, ok);
        }
        cp_commit();
    };

    load_stage(0);
    load_stage(1);

    const int j  = lane >> 3;
    const int r8 = lane & 7;

    for (int s = 0; s < NSTG; s++) {
        // Pending groups at the wait: {s, s+1, s+2} -> wait_group 2 retires s.
        if (s + 2 < NSTG) { load_stage(s + 2); cp_wait<2>(); }
        else if (s + 1 < NSTG) cp_wait<1>();
        else cp_wait<0>();
        __syncthreads();

        const uint32_t ab = sbase + (s & 3) * STG_BYTES;
        const uint32_t bb = ab + 8192;

#pragma unroll
        for (int ks = 0; ks < 2; ks++) {
            uint32_t Af[2][4];
#pragma unroll
            for (int mt = 0; mt < 2; mt++) {
                int rl = wm * 32 + mt * 16 + ((j & 1) << 3) + r8;
                int cc = ks * 2 + (j >> 1);
                int ph = cc ^ ((rl >> 1) & 3);
                ldmatrix_x4(Af[mt], ab + rl * 64 + ph * 16);
            }
#pragma unroll
            for (int np = 0; np < 4; np++) {
                uint32_t Bf[4];
                int nl = wn * 64 + np * 16 + ((j >> 1) << 3) + r8;
                int cc = ks * 2 + (j & 1);
                int ph = cc ^ ((nl >> 1) & 3);
                ldmatrix_x4(Bf, bb + nl * 64 + ph * 16);
#pragma unroll
                for (int mt = 0; mt < 2; mt++) {
                    mma_bf16(acc[mt][2 * np],     Af[mt], Bf[0], Bf[1]);
                    mma_bf16(acc[mt][2 * np + 1], Af[mt], Bf[2], Bf[3]);
                }
            }
        }
    }

    // ---- epilogue: store fp16 prob + per-batch max ----
    const int g  = lane >> 2;
    const int t4 = lane & 3;
    const int b0  = m0 / Q_;
    const int bnd = (b0 + 1) * Q_;
    float mx0 = 0.0f, mx1 = 0.0f;   // prob > 0 always; 0 is a safe identity
#pragma unroll
    for (int mt = 0; mt < 2; mt++) {
        const int row = m0 + wm * 32 + mt * 16 + g;
#pragma unroll
        for (int nt = 0; nt < 8; nt++) {
            int col = l0 + wn * 64 + nt * 8 + t4 * 2;
            float v0 = acc[mt][nt][0], v1 = acc[mt][nt][1];
            float v2 = acc[mt][nt][2], v3 = acc[mt][nt][3];
            float a01 = fmaxf(v0, v1), a23 = fmaxf(v2, v3);
            if (row     >= bnd) mx1 = fmaxf(mx1, a01); else mx0 = fmaxf(mx0, a01);
            if (row + 8 >= bnd) mx1 = fmaxf(mx1, a23); else mx0 = fmaxf(mx0, a23);
            if (col + 1 < L_) {
                *reinterpret_cast<__half2*>(g_prob_h + (size_t)row * LP + col) =
                    __floats2half2_rn(v0, v1);
                *reinterpret_cast<__half2*>(g_prob_h + (size_t)(row + 8) * LP + col) =
                    __floats2half2_rn(v2, v3);
            } else if (col < L_) {
                g_prob_h[(size_t)row * LP + col] = __float2half(v0);
                g_prob_h[(size_t)(row + 8) * LP + col] = __float2half(v2);
            }
        }
    }
#pragma unroll
    for (int o = 16; o > 0; o >>= 1) {
        mx0 = fmaxf(mx0, __shfl_xor_sync(0xFFFFFFFFu, mx0, o));
        mx1 = fmaxf(mx1, __shfl_xor_sync(0xFFFFFFFFu, mx1, o));
    }
    __syncthreads();
    if (lane == 0) {
        atomicMax(&s_mx0, __float_as_uint(mx0));
        if (bnd < m0 + 128) atomicMax(&s_mx1, __float_as_uint(mx1));
    }
    __syncthreads();
    if (tid == 0) {
        atomicMax(&g_maxbits[b0], s_mx0);
        if (bnd < m0 + 128) atomicMax(&g_maxbits[b0 + 1], s_mx1);
    }
}

// ---------------------------------------------------------------------------
// Kernel 3a: threshold-ladder counting.  grid (64, 12).
// Counts elements >= t_k, t_k = max - 0.5*(k+1), k=0..15.
// Chunk-max prefilter skips uint4 chunks entirely below t_15.
// ---------------------------------------------------------------------------
#define ROWS_PER_PART 75
#define CH_PER_ROW    97

__global__ __launch_bounds__(256) void count_kernel() {
    const int b    = blockIdx.x;
    const int part = blockIdx.y;
    const int tid  = threadIdx.x;
    const float mx = __uint_as_float(g_maxbits[b]);
    const float tlo = mx - 0.5f * NTH;

    unsigned c[NTH];
#pragma unroll
    for (int k = 0; k < NTH; k++) c[k] = 0u;

    const int n = ROWS_PER_PART * CH_PER_ROW;
    for (int i = tid; i < n; i += 256) {
        int r = i / CH_PER_ROW;
        int cc = i - r * CH_PER_ROW;
        int q = part * ROWS_PER_PART + r;
        const uint4 v = reinterpret_cast<const uint4*>(
            g_prob_h + (size_t)(b * Q_ + q) * LP)[cc];
        __half2 h0 = *reinterpret_cast<const __half2*>(&v.x);
        __half2 h1 = *reinterpret_cast<const __half2*>(&v.y);
        __half2 h2 = *reinterpret_cast<const __half2*>(&v.z);
        __half2 h3 = *reinterpret_cast<const __half2*>(&v.w);
        __half2 m2 = __hmax2(__hmax2(h0, h1), __hmax2(h2, h3));
        float fm = fmaxf(__low2float(m2), __high2float(m2));
        if (fm >= tlo) {
            float2 e0 = __half22float2(h0), e1 = __half22float2(h1);
            float2 e2 = __half22float2(h2), e3 = __half22float2(h3);
            float e[8] = {e0.x, e0.y, e1.x, e1.y, e2.x, e2.y, e3.x, e3.y};
#pragma unroll
            for (int k = 0; k < NTH; k++) {
                float t = mx - 0.5f * (k + 1);
#pragma unroll
                for (int j2 = 0; j2 < 8; j2++) c[k] += (e[j2] >= t) ? 1u : 0u;
            }
        }
    }

    // warp reduce, then shared, then global
    __shared__ unsigned sc[NTH];
    if (tid < NTH) sc[tid] = 0u;
    __syncthreads();
#pragma unroll
    for (int k = 0; k < NTH; k++) {
        unsigned x = c[k];
#pragma unroll
        for (int o = 16; o > 0; o >>= 1) x += __shfl_xor_sync(0xFFFFFFFFu, x, o);
        if ((tid & 31) == 0 && x) atomicAdd(&sc[k], x);
    }
    __syncthreads();
    if (tid < NTH && sc[tid]) atomicAdd(&g_lcnt[b][tid], sc[tid]);
}

// ---------------------------------------------------------------------------
// Kernel 3b: pick tau = largest threshold with count >= CMIN.
// ---------------------------------------------------------------------------
__global__ void pick_kernel() {
    int b = threadIdx.x;
    if (b < B_) {
        float mx = __uint_as_float(g_maxbits[b]);
        float tau = mx - 0.5f * NTH;
#pragma unroll
        for (int k = 0; k < NTH; k++) {
            if (g_lcnt[b][k] >= CMIN) { tau = mx - 0.5f * (k + 1); break; }
        }
        g_tau[b] = tau;
    }
}

// ---------------------------------------------------------------------------
// Kernel 4: vectorized collect with the calibrated tau.
// ---------------------------------------------------------------------------
__global__ __launch_bounds__(256) void collect_kernel() {
    const int b    = blockIdx.x;
    const int part = blockIdx.y;
    const __half tau = __float2half_rd(g_tau[b]);

    const int n = ROWS_PER_PART * CH_PER_ROW;
    for (int i = threadIdx.x; i < n; i += 256) {
        int r = i / CH_PER_ROW;
        int c = i - r * CH_PER_ROW;
        int q = part * ROWS_PER_PART + r;
        const uint4 v = reinterpret_cast<const uint4*>(
            g_prob_h + (size_t)(b * Q_ + q) * LP)[c];
        __half2 h0 = *reinterpret_cast<const __half2*>(&v.x);
        __half2 h1 = *reinterpret_cast<const __half2*>(&v.y);
        __half2 h2 = *reinterpret_cast<const __half2*>(&v.z);
        __half2 h3 = *reinterpret_cast<const __half2*>(&v.w);
        __half2 m2 = __hmax2(__hmax2(h0, h1), __hmax2(h2, h3));
        __half  m  = __hmax(__low2half(m2), __high2half(m2));
        if (__hge(m, tau)) {
            __half e[8] = {__low2half(h0), __high2half(h0),
                           __low2half(h1), __high2half(h1),
                           __low2half(h2), __high2half(h2),
                           __low2half(h3), __high2half(h3)};
#pragma unroll
            for (int k = 0; k < 8; k++) {
                if (__hge(e[k], tau)) {
                    int p = atomicAdd(&g_ccnt[b], 1);
                    if (p < CCAP) g_cand[b][p] = q * L_ + c * 8 + k;
                }
            }
        }
    }
}

// ---------------------------------------------------------------------------
// Kernel 4b: rescue — only if a batch collected < 64 candidates.
// ---------------------------------------------------------------------------
__global__ __launch_bounds__(256) void rescue_kernel() {
    const int b = blockIdx.x;
    if (g_ccnt[b] >= 64) return;
    const float tau  = g_tau[b];
    const float tau2 = tau - 8.0f;
    for (int i = threadIdx.x; i < Q_ * L_; i += 256) {
        int q = i / L_;
        int l = i - q * L_;
        float v = __half2float(g_prob_h[(size_t)(b * Q_ + q) * LP + l]);
        if (v >= tau2 && v < tau) {
            int p = atomicAdd(&g_ccnt[b], 1);
            if (p < CCAP) g_cand[b][p] = i;
        }
    }
}

// ---------------------------------------------------------------------------
// Kernel 5: fp32 rescore + exact top-50 + epilogue (grid 64)
// ---------------------------------------------------------------------------
__global__ __launch_bounds__(1024) void final_kernel(
    const float* __restrict__ logits, const float* __restrict__ bbox,
    const float* __restrict__ tsz, float* __restrict__ out,
    const float* __restrict__ posmap)
{
    extern __shared__ char fsm[];
    float* s_cv = reinterpret_cast<float*>(fsm);
    int*   s_ci = reinterpret_cast<int*>(fsm + CCAP * 4);

    const int b    = blockIdx.x;
    const int tid  = threadIdx.x;
    const int wid  = tid >> 5;
    const int lane = tid & 31;

    int K = g_ccnt[b];
    if (K > CCAP) K = CCAP;

    // rescore: one warp per candidate
    for (int c = wid; c < K; c += 32) {
        int idx = g_cand[b][c];
        int q = idx / L_;
        int l = idx - q * L_;
        const float4* a = reinterpret_cast<const float4*>(
            logits + (size_t)(b * Q_ + q) * T_ + lane * 8);
        const float4* p = reinterpret_cast<const float4*>(
            posmap + (size_t)l * T_ + lane * 8);
        float4 a0 = a[0], a1 = a[1], p0 = p[0], p1 = p[1];
        float s = sigf(a0.x) * p0.x + sigf(a0.y) * p0.y
                + sigf(a0.z) * p0.z + sigf(a0.w) * p0.w
                + sigf(a1.x) * p1.x + sigf(a1.y) * p1.y
                + sigf(a1.z) * p1.z + sigf(a1.w) * p1.w;
#pragma unroll
        for (int o = 16; o > 0; o >>= 1) s += __shfl_xor_sync(0xFFFFFFFFu, s, o);
        if (lane == 0) { s_cv[c] = s; s_ci[c] = idx; }
    }
    __syncthreads();

    // exact rank (value desc, index asc) + epilogue
    for (int jj = tid; jj < K; jj += 1024) {
        float vj = s_cv[jj];
        int   ij = s_ci[jj];
        int rank = 0;
        for (int i = 0; i < K; i++) {
            float vi = s_cv[i];
            int   ii = s_ci[i];
            if (vi > vj || (vi == vj && ii < ij)) rank++;
        }
        if (rank < NSEL) {
            int o = b * NSEL + rank;
            out[o] = vj;
            int q = ij / L_;
            int l = ij - q * L_;
            int label = 0;
#pragma unroll
            for (int t = 0; t < 80; t++)
                if (c_tok[t] == l) label = t;
            out[B_ * NSEL + o] = (float)label;
            const float* bb = bbox + (size_t)(b * Q_ + q) * 4;
            float cx = bb[0], cy = bb[1], w = bb[2], h = bb[3];
            float ih = tsz[2 * b + 0], iw = tsz[2 * b + 1];
            float* ob = out + 2 * B_ * NSEL + (size_t)o * 4;
            ob[0] = (cx - 0.5f * w) * iw;
            ob[1] = (cy - 0.5f * h) * ih;
            ob[2] = (cx + 0.5f * w) * iw;
            ob[3] = (cy + 0.5f * h) * ih;
        }
    }
}

// ---------------------------------------------------------------------------
extern "C" void kernel_launch(void* const* d_in, const int* in_sizes, int n_in,
                              void* d_out, int out_size) {
    const float* logits = (const float*)d_in[0];
    const float* bbox   = (const float*)d_in[1];
    const float* posmap = (const float*)d_in[2];
    const float* tsz    = (const float*)d_in[3];
    float* out = (float*)d_out;

    cudaFuncSetAttribute(gemm_kernel,
        cudaFuncAttributeMaxDynamicSharedMemorySize, 4 * STG_BYTES);
    cudaFuncSetAttribute(final_kernel,
        cudaFuncAttributeMaxDynamicSharedMemorySize, CCAP * 8);

    zero_kernel<<<(M_ + 255) / 256, 256>>>();

    const int n4 = (M_ * T_) / 4;
    sigmoid_kernel<<<(n4 + 255) / 256, 256>>>(logits, n4);
    posconv_kernel<<<(L_ * T_ / 2 + 255) / 256, 256>>>(posmap, L_ * T_ / 2);

    dim3 ggrid(M_ / 128, (L_ + 127) / 128);   // 450 x 7
    gemm_kernel<<<ggrid, 256, 4 * STG_BYTES>>>();

    dim3 cgrid(B_, 12);
    count_kernel<<<cgrid, 256>>>();
    pick_kernel<<<1, B_>>>();
    collect_kernel<<<cgrid, 256>>>();
    rescue_kernel<<<B_, 256>>>();
    final_kernel<<<B_, 1024, CCAP * 8>>>(logits, bbox, tsz, out, posmap);
}

// round 9
// speedup vs baseline: 5.2847x; 1.3781x over previous
#include <cuda_runtime.h>
#include <cuda_fp16.h>
#include <cuda_bf16.h>
#include <cstdint>

// Problem constants
#define B_    64
#define Q_    900
#define T_    256
#define L_    769
#define LP    776            // padded row stride (16B-aligned rows of half)
#define NSEL  50
#define M_    (B_ * Q_)      // 57600
#define CCAP  8192
#define NSL   32             // sampled ladder levels (0.25 steps, down to max-8)
#define SMIN  96u            // sampled-count threshold (est 16x = 1536)
#define RS2_CAP 2048

// Scratch (static device globals; allocation-free)
__device__ __nv_bfloat16  g_sig_b[(size_t)M_ * T_];    // bf16 sigmoid, 29.5 MB
__device__ __nv_bfloat16  g_pos_b[(size_t)L_ * T_];    // bf16 posmap
__device__ __half         g_prob_h[(size_t)M_ * LP];   // approx prob fp16, 89 MB
__device__ unsigned       g_maxbits[B_];               // per-batch max (uint-ordered)
__device__ unsigned       g_scnt[B_][NSL];             // sampled differential hist
__device__ float          g_tau[B_];
__device__ int            g_ccnt[B_];
__device__ int            g_cand[B_][CCAP];            // candidate flat idx (q*L+l)
__device__ __half         g_cval[B_][CCAP];            // candidate approx value

__constant__ int c_tok[80] = {
    0, 9, 19, 25, 38, 49, 55, 63, 71, 78, 94, 109, 121, 137, 145, 152,
    158, 164, 172, 180, 186, 197, 204, 212, 222, 233, 244, 254, 260, 271,
    281, 288, 300, 314, 321, 336, 353, 366, 378, 394, 403, 416, 422, 429,
    437, 445, 452, 461, 469, 480, 489, 500, 509, 519, 527, 535, 542, 550,
    558, 573, 579, 594, 603, 608, 617, 625, 634, 645, 658, 670, 677, 687,
    694, 709, 716, 724, 731, 742, 755, 768};

// ---------------------------------------------------------------------------
// Helpers
// ---------------------------------------------------------------------------
__device__ __forceinline__ uint32_t smem_u32(const void* p) {
    uint32_t a;
    asm("{ .reg .u64 t; cvta.to.shared.u64 t, %1; cvt.u32.u64 %0, t; }" : "=r"(a) : "l"(p));
    return a;
}
__device__ __forceinline__ void cp_async16(uint32_t dst, const void* src, bool valid) {
    int sz = valid ? 16 : 0;   // src-size 0 => zero-fill 16B
    asm volatile("cp.async.cg.shared.global [%0], [%1], 16, %2;\n"
                 :: "r"(dst), "l"(src), "r"(sz));
}
__device__ __forceinline__ void cp_commit() { asm volatile("cp.async.commit_group;"); }
template <int N> __device__ __forceinline__ void cp_wait() {
    asm volatile("cp.async.wait_group %0;" :: "n"(N));
}
__device__ __forceinline__ void ldmatrix_x4(uint32_t* f, uint32_t addr) {
    asm volatile("ldmatrix.sync.aligned.m8n8.x4.shared.b16 {%0,%1,%2,%3}, [%4];"
                 : "=r"(f[0]), "=r"(f[1]), "=r"(f[2]), "=r"(f[3]) : "r"(addr));
}
__device__ __forceinline__ void mma_bf16(float* d, const uint32_t* a,
                                         uint32_t b0, uint32_t b1) {
    asm volatile(
        "mma.sync.aligned.m16n8k16.row.col.f32.bf16.bf16.f32 "
        "{%0,%1,%2,%3}, {%4,%5,%6,%7}, {%8,%9}, {%0,%1,%2,%3};"
        : "+f"(d[0]), "+f"(d[1]), "+f"(d[2]), "+f"(d[3])
        : "r"(a[0]), "r"(a[1]), "r"(a[2]), "r"(a[3]), "r"(b0), "r"(b1));
}
__device__ __forceinline__ float sigf(float x) {
    return 1.0f / (1.0f + __expf(-x));
}

// ---------------------------------------------------------------------------
// Kernel 0: reset counters + fill pad columns (769..775) with -inf
// ---------------------------------------------------------------------------
__global__ void zero_kernel() {
    int i = blockIdx.x * blockDim.x + threadIdx.x;
    if (i < M_) {
        uint4 ninf = make_uint4(0xFC00FC00u, 0xFC00FC00u, 0xFC00FC00u, 0xFC00FC00u);
        *reinterpret_cast<uint4*>(g_prob_h + (size_t)i * LP + 768) = ninf;
    }
    if (i < B_) { g_ccnt[i] = 0; g_maxbits[i] = 0u; }
    if (i < B_ * NSL) ((unsigned*)g_scnt)[i] = 0u;
}

// ---------------------------------------------------------------------------
// Kernel 1: sigmoid -> bf16
// ---------------------------------------------------------------------------
__global__ void sigmoid_kernel(const float* __restrict__ x, int n4) {
    int i = blockIdx.x * blockDim.x + threadIdx.x;
    if (i < n4) {
        float4 v = reinterpret_cast<const float4*>(x)[i];
        __nv_bfloat162* o = reinterpret_cast<__nv_bfloat162*>(g_sig_b) + 2 * i;
        o[0] = __floats2bfloat162_rn(sigf(v.x), sigf(v.y));
        o[1] = __floats2bfloat162_rn(sigf(v.z), sigf(v.w));
    }
}

__global__ void posconv_kernel(const float* __restrict__ p, int n2) {
    int i = blockIdx.x * blockDim.x + threadIdx.x;
    if (i < n2) {
        float2 v = reinterpret_cast<const float2*>(p)[i];
        reinterpret_cast<__nv_bfloat162*>(g_pos_b)[i] = __floats2bfloat162_rn(v.x, v.y);
    }
}

// ---------------------------------------------------------------------------
// Kernel 2: bf16 mma.sync GEMM, CTA 128x128, BK=32, 6-buffer depth-3 pipeline
// ---------------------------------------------------------------------------
#define STG_BYTES 16384
#define NSTG 8   // 256/32 k-stages
#define NBUF 6

__global__ __launch_bounds__(256) void gemm_kernel() {
    extern __shared__ char dsm[];
    const uint32_t sbase = smem_u32(dsm);
    __shared__ unsigned s_mx0, s_mx1;
    const int tid  = threadIdx.x;
    const int wid  = tid >> 5;
    const int lane = tid & 31;
    const int wm   = wid & 3;      // 0..3 (m)
    const int wn   = wid >> 2;     // 0..1 (n)
    const int m0   = blockIdx.x * 128;
    const int l0   = blockIdx.y * 128;

    if (tid == 0) { s_mx0 = 0u; s_mx1 = 0u; }

    float acc[2][8][4];
#pragma unroll
    for (int a = 0; a < 2; a++)
#pragma unroll
        for (int b = 0; b < 8; b++)
#pragma unroll
            for (int c = 0; c < 4; c++) acc[a][b][c] = 0.0f;

    auto load_stage = [&](int s) {
        const uint32_t base = sbase + (s % NBUF) * STG_BYTES;
        const int k0 = s * 32;
#pragma unroll
        for (int t = 0; t < 2; t++) {              // A
            int ch = tid + t * 256;
            int r  = ch >> 2;
            int cc = ch & 3;
            int ph = cc ^ ((r >> 1) & 3);
            cp_async16(base + r * 64 + ph * 16,
                       g_sig_b + (size_t)(m0 + r) * T_ + k0 + cc * 8, true);
        }
#pragma unroll
        for (int t = 0; t < 2; t++) {              // B
            int ch = tid + t * 256;
            int r  = ch >> 2;
            int cc = ch & 3;
            int ph = cc ^ ((r >> 1) & 3);
            bool ok = (l0 + r) < L_;
            cp_async16(base + 8192 + r * 64 + ph * 16,
                       g_pos_b + (size_t)(l0 + r) * T_ + k0 + cc * 8, ok);
        }
        cp_commit();
    };

    load_stage(0);
    load_stage(1);
    load_stage(2);

    const int j  = lane >> 3;
    const int r8 = lane & 7;

    for (int s = 0; s < NSTG; s++) {
        // Depth-3 prefetch: after issuing load(s+3), pending = {s..s+3},
        // wait_group 3 retires stage s. Buffer (s+3)%6 last read at s-3 (done).
        if (s + 3 < NSTG)      { load_stage(s + 3); cp_wait<3>(); }
        else if (s + 2 < NSTG) cp_wait<2>();
        else if (s + 1 < NSTG) cp_wait<1>();
        else                   cp_wait<0>();
        __syncthreads();

        const uint32_t ab = sbase + (s % NBUF) * STG_BYTES;
        const uint32_t bb = ab + 8192;

#pragma unroll
        for (int ks = 0; ks < 2; ks++) {
            uint32_t Af[2][4];
#pragma unroll
            for (int mt = 0; mt < 2; mt++) {
                int rl = wm * 32 + mt * 16 + ((j & 1) << 3) + r8;
                int cc = ks * 2 + (j >> 1);
                int ph = cc ^ ((rl >> 1) & 3);
                ldmatrix_x4(Af[mt], ab + rl * 64 + ph * 16);
            }
#pragma unroll
            for (int np = 0; np < 4; np++) {
                uint32_t Bf[4];
                int nl = wn * 64 + np * 16 + ((j >> 1) << 3) + r8;
                int cc = ks * 2 + (j & 1);
                int ph = cc ^ ((nl >> 1) & 3);
                ldmatrix_x4(Bf, bb + nl * 64 + ph * 16);
#pragma unroll
                for (int mt = 0; mt < 2; mt++) {
                    mma_bf16(acc[mt][2 * np],     Af[mt], Bf[0], Bf[1]);
                    mma_bf16(acc[mt][2 * np + 1], Af[mt], Bf[2], Bf[3]);
                }
            }
        }
    }

    // ---- epilogue: store fp16 prob + per-batch max ----
    const int g  = lane >> 2;
    const int t4 = lane & 3;
    const int b0  = m0 / Q_;
    const int bnd = (b0 + 1) * Q_;
    float mx0 = 0.0f, mx1 = 0.0f;
#pragma unroll
    for (int mt = 0; mt < 2; mt++) {
        const int row = m0 + wm * 32 + mt * 16 + g;
#pragma unroll
        for (int nt = 0; nt < 8; nt++) {
            int col = l0 + wn * 64 + nt * 8 + t4 * 2;
            float v0 = acc[mt][nt][0], v1 = acc[mt][nt][1];
            float v2 = acc[mt][nt][2], v3 = acc[mt][nt][3];
            float a01 = fmaxf(v0, v1), a23 = fmaxf(v2, v3);
            if (row     >= bnd) mx1 = fmaxf(mx1, a01); else mx0 = fmaxf(mx0, a01);
            if (row + 8 >= bnd) mx1 = fmaxf(mx1, a23); else mx0 = fmaxf(mx0, a23);
            if (col + 1 < L_) {
                *reinterpret_cast<__half2*>(g_prob_h + (size_t)row * LP + col) =
                    __floats2half2_rn(v0, v1);
                *reinterpret_cast<__half2*>(g_prob_h + (size_t)(row + 8) * LP + col) =
                    __floats2half2_rn(v2, v3);
            } else if (col < L_) {
                g_prob_h[(size_t)row * LP + col] = __float2half(v0);
                g_prob_h[(size_t)(row + 8) * LP + col] = __float2half(v2);
            }
        }
    }
#pragma unroll
    for (int o = 16; o > 0; o >>= 1) {
        mx0 = fmaxf(mx0, __shfl_xor_sync(0xFFFFFFFFu, mx0, o));
        mx1 = fmaxf(mx1, __shfl_xor_sync(0xFFFFFFFFu, mx1, o));
    }
    __syncthreads();
    if (lane == 0) {
        atomicMax(&s_mx0, __float_as_uint(mx0));
        if (bnd < m0 + 128) atomicMax(&s_mx1, __float_as_uint(mx1));
    }
    __syncthreads();
    if (tid == 0) {
        atomicMax(&g_maxbits[b0], s_mx0);
        if (bnd < m0 + 128) atomicMax(&g_maxbits[b0 + 1], s_mx1);
    }
}

// ---------------------------------------------------------------------------
// Kernel 3: sampled ladder (1/16 of chunks). grid 64.
// Differential hist: bin k holds count of v in (mx-0.25(k+1), mx-0.25k].
// ---------------------------------------------------------------------------
#define CH_PER_ROW 97
#define NCHUNK (Q_ * CH_PER_ROW)        // 87300
#define NSAMP  ((NCHUNK + 15) / 16)     // 5457

__global__ __launch_bounds__(256) void sample_kernel() {
    const int b   = blockIdx.x;
    const int tid = threadIdx.x;
    const float mx = __uint_as_float(g_maxbits[b]);
    __shared__ unsigned h[NSL];
    if (tid < NSL) h[tid] = 0u;
    __syncthreads();

    for (int i = tid; i < NSAMP; i += 256) {
        int ci = i * 16;
        if (ci >= NCHUNK) break;
        int q = ci / CH_PER_ROW;
        int c = ci - q * CH_PER_ROW;
        const uint4 v = reinterpret_cast<const uint4*>(
            g_prob_h + (size_t)(b * Q_ + q) * LP)[c];
        __half2 hh[4] = {*reinterpret_cast<const __half2*>(&v.x),
                         *reinterpret_cast<const __half2*>(&v.y),
                         *reinterpret_cast<const __half2*>(&v.z),
                         *reinterpret_cast<const __half2*>(&v.w)};
#pragma unroll
        for (int e = 0; e < 4; e++) {
            float2 f2 = __half22float2(hh[e]);
            float fs[2] = {f2.x, f2.y};
#pragma unroll
            for (int u = 0; u < 2; u++) {
                float f = fs[u];
                if (f > mx - 8.0f) {
                    int k = (int)((mx - f) * 4.0f);
                    k = k < 0 ? 0 : (k > NSL - 1 ? NSL - 1 : k);
                    atomicAdd(&h[k], 1u);
                }
            }
        }
    }
    __syncthreads();
    if (tid < NSL && h[tid]) atomicAdd(&g_scnt[b][tid], h[tid]);
}

// ---------------------------------------------------------------------------
// Kernel 3b: pick tau from sampled ladder (cumulative from top).
// ---------------------------------------------------------------------------
__global__ void pick_kernel() {
    int b = threadIdx.x;
    if (b < B_) {
        float mx = __uint_as_float(g_maxbits[b]);
        float tau = mx - 8.0f;
        unsigned cum = 0;
        for (int k = 0; k < NSL; k++) {
            cum += g_scnt[b][k];
            if (cum >= SMIN) { tau = mx - 0.25f * (k + 1); break; }
        }
        g_tau[b] = tau;
    }
}

// ---------------------------------------------------------------------------
// Kernel 4: vectorized collect (stores idx + approx value). grid (64, 12).
// ---------------------------------------------------------------------------
#define ROWS_PER_PART 75

__global__ __launch_bounds__(256) void collect_kernel() {
    const int b    = blockIdx.x;
    const int part = blockIdx.y;
    const __half tau = __float2half_rd(g_tau[b]);

    const int n = ROWS_PER_PART * CH_PER_ROW;
    for (int i = threadIdx.x; i < n; i += 256) {
        int r = i / CH_PER_ROW;
        int c = i - r * CH_PER_ROW;
        int q = part * ROWS_PER_PART + r;
        const uint4 v = reinterpret_cast<const uint4*>(
            g_prob_h + (size_t)(b * Q_ + q) * LP)[c];
        __half2 h0 = *reinterpret_cast<const __half2*>(&v.x);
        __half2 h1 = *reinterpret_cast<const __half2*>(&v.y);
        __half2 h2 = *reinterpret_cast<const __half2*>(&v.z);
        __half2 h3 = *reinterpret_cast<const __half2*>(&v.w);
        __half2 m2 = __hmax2(__hmax2(h0, h1), __hmax2(h2, h3));
        __half  m  = __hmax(__low2half(m2), __high2half(m2));
        if (__hge(m, tau)) {
            __half e[8] = {__low2half(h0), __high2half(h0),
                           __low2half(h1), __high2half(h1),
                           __low2half(h2), __high2half(h2),
                           __low2half(h3), __high2half(h3)};
#pragma unroll
            for (int k = 0; k < 8; k++) {
                if (__hge(e[k], tau)) {
                    int p = atomicAdd(&g_ccnt[b], 1);
                    if (p < CCAP) {
                        g_cand[b][p] = q * L_ + c * 8 + k;
                        g_cval[b][p] = e[k];
                    }
                }
            }
        }
    }
}

// ---------------------------------------------------------------------------
// Kernel 4b: fixup — re-collect if K overflowed or is too small. Normally noop.
// ---------------------------------------------------------------------------
__global__ __launch_bounds__(1024) void fixup_kernel() {
    const int b   = blockIdx.x;
    const int tid = threadIdx.x;
    int K = g_ccnt[b];
    if (K >= 64 && K <= CCAP) return;
    float tau = g_tau[b] + (K > CCAP ? 0.25f : -4.0f);
    __syncthreads();
    if (tid == 0) { g_tau[b] = tau; g_ccnt[b] = 0; }
    __syncthreads();
    const __half htau = __float2half_rd(tau);
    for (int i = tid; i < Q_ * L_; i += 1024) {
        int q = i / L_;
        int l = i - q * L_;
        __half v = g_prob_h[(size_t)(b * Q_ + q) * LP + l];
        if (__hge(v, htau)) {
            int p = atomicAdd(&g_ccnt[b], 1);
            if (p < CCAP) { g_cand[b][p] = i; g_cval[b][p] = v; }
        }
    }
}

// ---------------------------------------------------------------------------
// Kernel 5: approx-select + fp32 rescore + exact-select + rank + epilogue.
// grid 64, block 1024, dynamic smem 96KB (3 x CCAP x 4B, aliased by phase).
// ---------------------------------------------------------------------------
__global__ __launch_bounds__(1024) void final_kernel(
    const float* __restrict__ logits, const float* __restrict__ bbox,
    const float* __restrict__ tsz, float* __restrict__ out,
    const float* __restrict__ posmap)
{
    extern __shared__ char fsm[];
    float* s_av  = reinterpret_cast<float*>(fsm);                 // [CCAP] approx
    int*   s_idx = reinterpret_cast<int*>(fsm + CCAP * 4);        // [CCAP]
    int*   r_idx = reinterpret_cast<int*>(fsm + CCAP * 8);        // [CCAP]
    float* r_ev  = s_av;                                          // alias (phase D+)
    __shared__ unsigned hist[128];
    __shared__ int   s_rcnt, s_r2cnt;
    __shared__ float s_tr, s_estar;
    __shared__ int   r2_idx[RS2_CAP];
    __shared__ float r2_ev[RS2_CAP];

    const int b    = blockIdx.x;
    const int tid  = threadIdx.x;
    const int wid  = tid >> 5;
    const int lane = tid & 31;
    const float tau = g_tau[b];

    int K = g_ccnt[b];
    if (K > CCAP) K = CCAP;

    // Phase A: load candidates + approx histogram over [tau, tau+8)
    for (int i = tid; i < 128; i += 1024) hist[i] = 0u;
    if (tid == 0) { s_rcnt = 0; s_r2cnt = 0; }
    __syncthreads();
    for (int c = tid; c < K; c += 1024) {
        float v = __half2float(g_cval[b][c]);
        s_av[c]  = v;
        s_idx[c] = g_cand[b][c];
        int bin = (int)((v - tau) * 16.0f);
        bin = bin < 0 ? 0 : (bin > 127 ? 127 : bin);
        atomicAdd(&hist[bin], 1u);
    }
    __syncthreads();

    // Phase B: approx 50th edge; rescore threshold = edge - 1.0 (>= 2*delta)
    if (tid == 0) {
        unsigned cum = 0;
        int bstar = 0;
        for (int k = 127; k >= 0; k--) {
            cum += hist[k];
            if (cum >= NSEL) { bstar = k; break; }
        }
        s_tr = tau + bstar * (1.0f / 16.0f) - 1.0f;
    }
    __syncthreads();
    const float tr = s_tr;

    // Phase C: compact rescore set
    for (int c = tid; c < K; c += 1024) {
        if (s_av[c] >= tr) {
            int p = atomicAdd(&s_rcnt, 1);
            if (p < CCAP) r_idx[p] = s_idx[c];
        }
    }
    __syncthreads();
    int R = s_rcnt < CCAP ? s_rcnt : CCAP;

    // Phase D: fp32 rescore (one warp per candidate); r_ev aliases s_av
    for (int c = wid; c < R; c += 32) {
        int idx = r_idx[c];
        int q = idx / L_;
        int l = idx - q * L_;
        const float4* a = reinterpret_cast<const float4*>(
            logits + (size_t)(b * Q_ + q) * T_ + lane * 8);
        const float4* p = reinterpret_cast<const float4*>(
            posmap + (size_t)l * T_ + lane * 8);
        float4 a0 = a[0], a1 = a[1], p0 = p[0], p1 = p[1];
        float s = sigf(a0.x) * p0.x + sigf(a0.y) * p0.y
                + sigf(a0.z) * p0.z + sigf(a0.w) * p0.w
                + sigf(a1.x) * p1.x + sigf(a1.y) * p1.y
                + sigf(a1.z) * p1.z + sigf(a1.w) * p1.w;
#pragma unroll
        for (int o = 16; o > 0; o >>= 1) s += __shfl_xor_sync(0xFFFFFFFFu, s, o);
        if (lane == 0) r_ev[c] = s;
    }
    __syncthreads();

    // Phase E: exact histogram over [tr-1, tr+7); find exact 50th edge
    for (int i = tid; i < 128; i += 1024) hist[i] = 0u;
    __syncthreads();
    const float base = tr - 1.0f;
    for (int c = tid; c < R; c += 1024) {
        int bin = (int)((r_ev[c] - base) * 16.0f);
        bin = bin < 0 ? 0 : (bin > 127 ? 127 : bin);
        atomicAdd(&hist[bin], 1u);
    }
    __syncthreads();
    if (tid == 0) {
        unsigned cum = 0;
        int eb = 0;
        for (int k = 127; k >= 0; k--) {
            cum += hist[k];
            if (cum >= NSEL) { eb = k; break; }
        }
        s_estar = base + eb * (1.0f / 16.0f);
    }
    __syncthreads();
    const float estar = s_estar;

    // Phase F: compact exact finalists (count >= 50, includes all ties)
    for (int c = tid; c < R; c += 1024) {
        if (r_ev[c] >= estar) {
            int p = atomicAdd(&s_r2cnt, 1);
            if (p < RS2_CAP) { r2_idx[p] = r_idx[c]; r2_ev[p] = r_ev[c]; }
        }
    }
    __syncthreads();
    int R2 = s_r2cnt < RS2_CAP ? s_r2cnt : RS2_CAP;

    // Phase G: exact rank (value desc, index asc) + epilogue
    for (int jj = tid; jj < R2; jj += 1024) {
        float vj = r2_ev[jj];
        int   ij = r2_idx[jj];
        int rank = 0;
        for (int i = 0; i < R2; i++) {
            float vi = r2_ev[i];
            int   ii = r2_idx[i];
            if (vi > vj || (vi == vj && ii < ij)) rank++;
        }
        if (rank < NSEL) {
            int o = b * NSEL + rank;
            out[o] = vj;
            int q = ij / L_;
            int l = ij - q * L_;
            int label = 0;
#pragma unroll
            for (int t = 0; t < 80; t++)
                if (c_tok[t] == l) label = t;
            out[B_ * NSEL + o] = (float)label;
            const float* bb = bbox + (size_t)(b * Q_ + q) * 4;
            float cx = bb[0], cy = bb[1], w = bb[2], h = bb[3];
            float ih = tsz[2 * b + 0], iw = tsz[2 * b + 1];
            float* ob = out + 2 * B_ * NSEL + (size_t)o * 4;
            ob[0] = (cx - 0.5f * w) * iw;
            ob[1] = (cy - 0.5f * h) * ih;
            ob[2] = (cx + 0.5f * w) * iw;
            ob[3] = (cy + 0.5f * h) * ih;
        }
    }
}

// ---------------------------------------------------------------------------
extern "C" void kernel_launch(void* const* d_in, const int* in_sizes, int n_in,
                              void* d_out, int out_size) {
    const float* logits = (const float*)d_in[0];
    const float* bbox   = (const float*)d_in[1];
    const float* posmap = (const float*)d_in[2];
    const float* tsz    = (const float*)d_in[3];
    float* out = (float*)d_out;

    cudaFuncSetAttribute(gemm_kernel,
        cudaFuncAttributeMaxDynamicSharedMemorySize, NBUF * STG_BYTES);
    cudaFuncSetAttribute(final_kernel,
        cudaFuncAttributeMaxDynamicSharedMemorySize, CCAP * 12);

    zero_kernel<<<(M_ + 255) / 256, 256>>>();

    const int n4 = (M_ * T_) / 4;
    sigmoid_kernel<<<(n4 + 255) / 256, 256>>>(logits, n4);
    posconv_kernel<<<(L_ * T_ / 2 + 255) / 256, 256>>>(posmap, L_ * T_ / 2);

    dim3 ggrid(M_ / 128, (L_ + 127) / 128);   // 450 x 7
    gemm_kernel<<<ggrid, 256, NBUF * STG_BYTES>>>();

    sample_kernel<<<B_, 256>>>();
    pick_kernel<<<1, B_>>>();
    dim3 cgrid(B_, 12);
    collect_kernel<<<cgrid, 256>>>();
    fixup_kernel<<<B_, 1024>>>();
    final_kernel<<<B_, 1024, CCAP * 12>>>(logits, bbox, tsz, out, posmap);
}

// round 10
// speedup vs baseline: 5.8472x; 1.1064x over previous
#include <cuda_runtime.h>
#include <cuda_fp16.h>
#include <cuda_bf16.h>
#include <cstdint>

// Problem constants
#define B_    64
#define Q_    900
#define T_    256
#define L_    769
#define LP    776            // padded row stride (16B-aligned rows of half)
#define NSEL  50
#define M_    (B_ * Q_)      // 57600
#define CCAP  8192
#define NSL   32             // ladder levels (0.25 steps, down to max-8)
#define CMINC 256u           // min chunk count above tau
#define RS2_CAP 2048
#define NCH   97             // 8-wide chunks per row (769 -> 97)
#define CPAD  104            // padded cmax row stride (16B aligned)

// Scratch (static device globals; allocation-free)
__device__ __nv_bfloat16  g_sig_b[(size_t)M_ * T_];    // bf16 sigmoid, 29.5 MB
__device__ __nv_bfloat16  g_pos_b[(size_t)L_ * T_];    // bf16 posmap
__device__ __half         g_prob_h[(size_t)M_ * LP];   // approx prob fp16, 89 MB
__device__ __half         g_cmax[(size_t)M_ * CPAD];   // per-chunk max, 12 MB
__device__ unsigned       g_maxbits[B_];               // per-batch max (uint bits)
__device__ unsigned       g_scnt[B_][NSL];             // chunk ladder counts
__device__ float          g_tau[B_];
__device__ int            g_ccnt[B_];
__device__ int            g_cand[B_][CCAP];            // candidate flat idx (q*L+l)
__device__ __half         g_cval[B_][CCAP];            // candidate approx value

__constant__ int c_tok[80] = {
    0, 9, 19, 25, 38, 49, 55, 63, 71, 78, 94, 109, 121, 137, 145, 152,
    158, 164, 172, 180, 186, 197, 204, 212, 222, 233, 244, 254, 260, 271,
    281, 288, 300, 314, 321, 336, 353, 366, 378, 394, 403, 416, 422, 429,
    437, 445, 452, 461, 469, 480, 489, 500, 509, 519, 527, 535, 542, 550,
    558, 573, 579, 594, 603, 608, 617, 625, 634, 645, 658, 670, 677, 687,
    694, 709, 716, 724, 731, 742, 755, 768};

// ---------------------------------------------------------------------------
// Helpers
// ---------------------------------------------------------------------------
__device__ __forceinline__ uint32_t smem_u32(const void* p) {
    uint32_t a;
    asm("{ .reg .u64 t; cvta.to.shared.u64 t, %1; cvt.u32.u64 %0, t; }" : "=r"(a) : "l"(p));
    return a;
}
__device__ __forceinline__ void cp_async16(uint32_t dst, const void* src, bool valid) {
    int sz = valid ? 16 : 0;   // src-size 0 => zero-fill 16B
    asm volatile("cp.async.cg.shared.global [%0], [%1], 16, %2;\n"
                 :: "r"(dst), "l"(src), "r"(sz));
}
__device__ __forceinline__ void cp_commit() { asm volatile("cp.async.commit_group;"); }
template <int N> __device__ __forceinline__ void cp_wait() {
    asm volatile("cp.async.wait_group %0;" :: "n"(N));
}
__device__ __forceinline__ void ldmatrix_x4(uint32_t* f, uint32_t addr) {
    asm volatile("ldmatrix.sync.aligned.m8n8.x4.shared.b16 {%0,%1,%2,%3}, [%4];"
                 : "=r"(f[0]), "=r"(f[1]), "=r"(f[2]), "=r"(f[3]) : "r"(addr));
}
__device__ __forceinline__ void mma_bf16(float* d, const uint32_t* a,
                                         uint32_t b0, uint32_t b1) {
    asm volatile(
        "mma.sync.aligned.m16n8k16.row.col.f32.bf16.bf16.f32 "
        "{%0,%1,%2,%3}, {%4,%5,%6,%7}, {%8,%9}, {%0,%1,%2,%3};"
        : "+f"(d[0]), "+f"(d[1]), "+f"(d[2]), "+f"(d[3])
        : "r"(a[0]), "r"(a[1]), "r"(a[2]), "r"(a[3]), "r"(b0), "r"(b1));
}
__device__ __forceinline__ float sigf(float x) {
    return 1.0f / (1.0f + __expf(-x));
}

// ---------------------------------------------------------------------------
// Kernel 0: reset counters + -inf pads (prob cols 768..775, cmax 96..103)
// ---------------------------------------------------------------------------
__global__ void zero_kernel() {
    int i = blockIdx.x * blockDim.x + threadIdx.x;
    uint4 ninf = make_uint4(0xFC00FC00u, 0xFC00FC00u, 0xFC00FC00u, 0xFC00FC00u);
    if (i < M_) {
        *reinterpret_cast<uint4*>(g_prob_h + (size_t)i * LP + 768) = ninf;
        *reinterpret_cast<uint4*>(g_cmax   + (size_t)i * CPAD + 96) = ninf;
    }
    if (i < B_) { g_ccnt[i] = 0; g_maxbits[i] = 0u; }
    if (i < B_ * NSL) ((unsigned*)g_scnt)[i] = 0u;
}

// ---------------------------------------------------------------------------
// Kernel 1: sigmoid -> bf16 ; 1b: posmap -> bf16
// ---------------------------------------------------------------------------
__global__ void sigmoid_kernel(const float* __restrict__ x, int n4) {
    int i = blockIdx.x * blockDim.x + threadIdx.x;
    if (i < n4) {
        float4 v = reinterpret_cast<const float4*>(x)[i];
        __nv_bfloat162* o = reinterpret_cast<__nv_bfloat162*>(g_sig_b) + 2 * i;
        o[0] = __floats2bfloat162_rn(sigf(v.x), sigf(v.y));
        o[1] = __floats2bfloat162_rn(sigf(v.z), sigf(v.w));
    }
}

__global__ void posconv_kernel(const float* __restrict__ p, int n2) {
    int i = blockIdx.x * blockDim.x + threadIdx.x;
    if (i < n2) {
        float2 v = reinterpret_cast<const float2*>(p)[i];
        reinterpret_cast<__nv_bfloat162*>(g_pos_b)[i] = __floats2bfloat162_rn(v.x, v.y);
    }
}

// ---------------------------------------------------------------------------
// Kernel 2: bf16 mma.sync GEMM, CTA 128x128, BK=32, 6-buffer pipeline,
// software-pipelined B ldmatrix; epilogue writes prob + chunk-max + batch max.
// ---------------------------------------------------------------------------
#define STG_BYTES 16384
#define NSTG 8   // 256/32 k-stages
#define NBUF 6

__global__ __launch_bounds__(256) void gemm_kernel() {
    extern __shared__ char dsm[];
    const uint32_t sbase = smem_u32(dsm);
    __shared__ unsigned s_mx0, s_mx1;
    const int tid  = threadIdx.x;
    const int wid  = tid >> 5;
    const int lane = tid & 31;
    const int wm   = wid & 3;      // 0..3 (m)
    const int wn   = wid >> 2;     // 0..1 (n)
    const int m0   = blockIdx.x * 128;
    const int l0   = blockIdx.y * 128;

    if (tid == 0) { s_mx0 = 0u; s_mx1 = 0u; }

    float acc[2][8][4];
#pragma unroll
    for (int a = 0; a < 2; a++)
#pragma unroll
        for (int b = 0; b < 8; b++)
#pragma unroll
            for (int c = 0; c < 4; c++) acc[a][b][c] = 0.0f;

    auto load_stage = [&](int s) {
        const uint32_t base = sbase + (s % NBUF) * STG_BYTES;
        const int k0 = s * 32;
#pragma unroll
        for (int t = 0; t < 2; t++) {              // A
            int ch = tid + t * 256;
            int r  = ch >> 2;
            int cc = ch & 3;
            int ph = cc ^ ((r >> 1) & 3);
            cp_async16(base + r * 64 + ph * 16,
                       g_sig_b + (size_t)(m0 + r) * T_ + k0 + cc * 8, true);
        }
#pragma unroll
        for (int t = 0; t < 2; t++) {              // B
            int ch = tid + t * 256;
            int r  = ch >> 2;
            int cc = ch & 3;
            int ph = cc ^ ((r >> 1) & 3);
            bool ok = (l0 + r) < L_;
            cp_async16(base + 8192 + r * 64 + ph * 16,
                       g_pos_b + (size_t)(l0 + r) * T_ + k0 + cc * 8, ok);
        }
        cp_commit();
    };

    load_stage(0);
    load_stage(1);
    load_stage(2);

    const int j  = lane >> 3;
    const int r8 = lane & 7;

    for (int s = 0; s < NSTG; s++) {
        if (s + 3 < NSTG)      { load_stage(s + 3); cp_wait<3>(); }
        else if (s + 2 < NSTG) cp_wait<2>();
        else if (s + 1 < NSTG) cp_wait<1>();
        else                   cp_wait<0>();
        __syncthreads();

        const uint32_t ab = sbase + (s % NBUF) * STG_BYTES;
        const uint32_t bb = ab + 8192;

        auto ldB = [&](uint32_t* f, int ks, int np) {
            int nl = wn * 64 + np * 16 + ((j >> 1) << 3) + r8;
            int cc = ks * 2 + (j & 1);
            int ph = cc ^ ((nl >> 1) & 3);
            ldmatrix_x4(f, bb + nl * 64 + ph * 16);
        };

        // Software pipeline: Bf double-buffered one ldmatrix ahead.
        uint32_t Bf[2][4];
        ldB(Bf[0], 0, 0);
#pragma unroll
        for (int ks = 0; ks < 2; ks++) {
            uint32_t Af[2][4];
#pragma unroll
            for (int mt = 0; mt < 2; mt++) {
                int rl = wm * 32 + mt * 16 + ((j & 1) << 3) + r8;
                int cc = ks * 2 + (j >> 1);
                int ph = cc ^ ((rl >> 1) & 3);
                ldmatrix_x4(Af[mt], ab + rl * 64 + ph * 16);
            }
#pragma unroll
            for (int np = 0; np < 4; np++) {
                const int cur = (ks * 4 + np) & 1;
                int nn = np + 1, nk = ks;
                if (nn == 4) { nn = 0; nk = 1; }
                if (!(ks == 1 && np == 3)) ldB(Bf[cur ^ 1], nk, nn);
#pragma unroll
                for (int mt = 0; mt < 2; mt++) {
                    mma_bf16(acc[mt][2 * np],     Af[mt], Bf[cur][0], Bf[cur][1]);
                    mma_bf16(acc[mt][2 * np + 1], Af[mt], Bf[cur][2], Bf[cur][3]);
                }
            }
        }
    }

    // ---- epilogue: prob fp16 + chunk-max + per-batch max ----
    const int g  = lane >> 2;
    const int t4 = lane & 3;
    const int b0  = m0 / Q_;
    const int bnd = (b0 + 1) * Q_;
    const float NINF = -1e30f;
    float mx0 = 0.0f, mx1 = 0.0f;
#pragma unroll
    for (int mt = 0; mt < 2; mt++) {
        const int row = m0 + wm * 32 + mt * 16 + g;
#pragma unroll
        for (int nt = 0; nt < 8; nt++) {
            int col = l0 + wn * 64 + nt * 8 + t4 * 2;
            float v0 = acc[mt][nt][0], v1 = acc[mt][nt][1];
            float v2 = acc[mt][nt][2], v3 = acc[mt][nt][3];
            float a01 = fmaxf(v0, v1), a23 = fmaxf(v2, v3);
            if (row     >= bnd) mx1 = fmaxf(mx1, a01); else mx0 = fmaxf(mx0, a01);
            if (row + 8 >= bnd) mx1 = fmaxf(mx1, a23); else mx0 = fmaxf(mx0, a23);

            // chunk-max: mask invalid cols, reduce across the 4-lane t4 group
            float m01 = fmaxf(col < L_ ? v0 : NINF, col + 1 < L_ ? v1 : NINF);
            float m23 = fmaxf(col < L_ ? v2 : NINF, col + 1 < L_ ? v3 : NINF);
            m01 = fmaxf(m01, __shfl_xor_sync(0xFFFFFFFFu, m01, 1));
            m01 = fmaxf(m01, __shfl_xor_sync(0xFFFFFFFFu, m01, 2));
            m23 = fmaxf(m23, __shfl_xor_sync(0xFFFFFFFFu, m23, 1));
            m23 = fmaxf(m23, __shfl_xor_sync(0xFFFFFFFFu, m23, 2));
            int ch = (l0 >> 3) + wn * 8 + nt;
            if (t4 == 0 && ch < NCH) {
                g_cmax[(size_t)row * CPAD + ch]       = __float2half(m01);
                g_cmax[(size_t)(row + 8) * CPAD + ch] = __float2half(m23);
            }

            if (col + 1 < L_) {
                *reinterpret_cast<__half2*>(g_prob_h + (size_t)row * LP + col) =
                    __floats2half2_rn(v0, v1);
                *reinterpret_cast<__half2*>(g_prob_h + (size_t)(row + 8) * LP + col) =
                    __floats2half2_rn(v2, v3);
            } else if (col < L_) {
                g_prob_h[(size_t)row * LP + col] = __float2half(v0);
                g_prob_h[(size_t)(row + 8) * LP + col] = __float2half(v2);
            }
        }
    }
#pragma unroll
    for (int o = 16; o > 0; o >>= 1) {
        mx0 = fmaxf(mx0, __shfl_xor_sync(0xFFFFFFFFu, mx0, o));
        mx1 = fmaxf(mx1, __shfl_xor_sync(0xFFFFFFFFu, mx1, o));
    }
    __syncthreads();
    if (lane == 0) {
        atomicMax(&s_mx0, __float_as_uint(mx0));
        if (bnd < m0 + 128) atomicMax(&s_mx1, __float_as_uint(mx1));
    }
    __syncthreads();
    if (tid == 0) {
        atomicMax(&g_maxbits[b0], s_mx0);
        if (bnd < m0 + 128) atomicMax(&g_maxbits[b0 + 1], s_mx1);
    }
}

// ---------------------------------------------------------------------------
// Kernel 3: exact ladder over chunk-maxes (12MB). grid (64, 4).
// ---------------------------------------------------------------------------
__global__ __launch_bounds__(256) void cmax_scan_kernel() {
    const int b    = blockIdx.x;
    const int part = blockIdx.y;
    const int tid  = threadIdx.x;
    const float mx = __uint_as_float(g_maxbits[b]);
    const float lo = mx - 8.0f;
    __shared__ unsigned h[NSL];
    if (tid < NSL) h[tid] = 0u;
    __syncthreads();

    const int r0 = part * 225;                  // 4 x 225 = 900 rows
    const int n  = 225 * (CPAD / 8);            // uint4 per part (13 per row)
    for (int i = tid; i < n; i += 256) {
        int r  = i / 13;
        int c4 = i - r * 13;
        const uint4 v = reinterpret_cast<const uint4*>(
            g_cmax + (size_t)(b * Q_ + r0 + r) * CPAD)[c4];
        const __half2* hh = reinterpret_cast<const __half2*>(&v);
#pragma unroll
        for (int e = 0; e < 4; e++) {
            float2 f2 = __half22float2(hh[e]);
            float fs[2] = {f2.x, f2.y};
#pragma unroll
            for (int u = 0; u < 2; u++) {
                float f = fs[u];
                if (f > lo) {
                    int k = (int)((mx - f) * 4.0f);
                    k = k < 0 ? 0 : (k > NSL - 1 ? NSL - 1 : k);
                    atomicAdd(&h[k], 1u);
                }
            }
        }
    }
    __syncthreads();
    if (tid < NSL && h[tid]) atomicAdd(&g_scnt[b][tid], h[tid]);
}

// ---------------------------------------------------------------------------
// Kernel 3b: tau = level where cumulative chunk count >= CMINC
// ---------------------------------------------------------------------------
__global__ void pick_kernel() {
    int b = threadIdx.x;
    if (b < B_) {
        float mx = __uint_as_float(g_maxbits[b]);
        float tau = mx - 8.0f;
        unsigned cum = 0;
        for (int k = 0; k < NSL; k++) {
            cum += g_scnt[b][k];
            if (cum >= CMINC) { tau = mx - 0.25f * (k + 1); break; }
        }
        g_tau[b] = tau;
    }
}

// ---------------------------------------------------------------------------
// Kernel 4: cmax-gated collect. grid (64, 12).
// ---------------------------------------------------------------------------
#define ROWS_PER_PART 75

__global__ __launch_bounds__(256) void collect_kernel() {
    const int b    = blockIdx.x;
    const int part = blockIdx.y;
    const __half tau = __float2half_rd(g_tau[b]);

    const int n = ROWS_PER_PART * NCH;
    for (int i = threadIdx.x; i < n; i += 256) {
        int r = i / NCH;
        int c = i - r * NCH;
        int q = part * ROWS_PER_PART + r;
        __half cm = g_cmax[(size_t)(b * Q_ + q) * CPAD + c];
        if (__hge(cm, tau)) {
            const uint4 v = reinterpret_cast<const uint4*>(
                g_prob_h + (size_t)(b * Q_ + q) * LP)[c];
            const __half2* hh = reinterpret_cast<const __half2*>(&v);
#pragma unroll
            for (int e = 0; e < 4; e++) {
                __half lo = __low2half(hh[e]), hi = __high2half(hh[e]);
                if (__hge(lo, tau)) {
                    int p = atomicAdd(&g_ccnt[b], 1);
                    if (p < CCAP) {
                        g_cand[b][p] = q * L_ + c * 8 + e * 2;
                        g_cval[b][p] = lo;
                    }
                }
                if (__hge(hi, tau)) {
                    int p = atomicAdd(&g_ccnt[b], 1);
                    if (p < CCAP) {
                        g_cand[b][p] = q * L_ + c * 8 + e * 2 + 1;
                        g_cval[b][p] = hi;
                    }
                }
            }
        }
    }
}

// ---------------------------------------------------------------------------
// Kernel 4b: fixup loop — re-collect until 64 <= K <= CCAP (normally noop).
// ---------------------------------------------------------------------------
__global__ __launch_bounds__(1024) void fixup_kernel() {
    const int b   = blockIdx.x;
    const int tid = threadIdx.x;
    __shared__ float s_tau;
    for (int iter = 0; iter < 8; iter++) {
        __syncthreads();
        int K = g_ccnt[b];
        if (K >= 64 && K <= CCAP) return;
        if (tid == 0) {
            float t = g_tau[b] + (K > CCAP ? 0.25f : -2.0f);
            g_tau[b] = t;
            g_ccnt[b] = 0;
            s_tau = t;
        }
        __syncthreads();
        const __half htau = __float2half_rd(s_tau);
        for (int i = tid; i < Q_ * L_; i += 1024) {
            int q = i / L_;
            int l = i - q * L_;
            __half v = g_prob_h[(size_t)(b * Q_ + q) * LP + l];
            if (__hge(v, htau)) {
                int p = atomicAdd(&g_ccnt[b], 1);
                if (p < CCAP) { g_cand[b][p] = i; g_cval[b][p] = v; }
            }
        }
    }
}

// ---------------------------------------------------------------------------
// Kernel 5: approx-select + fp32 rescore + exact-select + rank + epilogue.
// ---------------------------------------------------------------------------
__global__ __launch_bounds__(1024) void final_kernel(
    const float* __restrict__ logits, const float* __restrict__ bbox,
    const float* __restrict__ tsz, float* __restrict__ out,
    const float* __restrict__ posmap)
{
    extern __shared__ char fsm[];
    float* s_av  = reinterpret_cast<float*>(fsm);                 // [CCAP]
    int*   s_idx = reinterpret_cast<int*>(fsm + CCAP * 4);        // [CCAP]
    int*   r_idx = reinterpret_cast<int*>(fsm + CCAP * 8);        // [CCAP]
    float* r_ev  = s_av;                                          // alias
    __shared__ unsigned hist[128];
    __shared__ int   s_rcnt, s_r2cnt;
    __shared__ float s_tr, s_estar;
    __shared__ int   r2_idx[RS2_CAP];
    __shared__ float r2_ev[RS2_CAP];

    const int b    = blockIdx.x;
    const int tid  = threadIdx.x;
    const int wid  = tid >> 5;
    const int lane = tid & 31;
    const float tau = g_tau[b];

    int K = g_ccnt[b];
    if (K > CCAP) K = CCAP;

    // Phase A: load candidates + approx histogram over [tau, tau+8)
    for (int i = tid; i < 128; i += 1024) hist[i] = 0u;
    if (tid == 0) { s_rcnt = 0; s_r2cnt = 0; }
    __syncthreads();
    for (int c = tid; c < K; c += 1024) {
        float v = __half2float(g_cval[b][c]);
        s_av[c]  = v;
        s_idx[c] = g_cand[b][c];
        int bin = (int)((v - tau) * 16.0f);
        bin = bin < 0 ? 0 : (bin > 127 ? 127 : bin);
        atomicAdd(&hist[bin], 1u);
    }
    __syncthreads();

    // Phase B: approx 50th edge; rescore threshold = edge - 1.0
    if (tid == 0) {
        unsigned cum = 0;
        int bstar = 0;
        for (int k = 127; k >= 0; k--) {
            cum += hist[k];
            if (cum >= NSEL) { bstar = k; break; }
        }
        s_tr = tau + bstar * (1.0f / 16.0f) - 1.0f;
    }
    __syncthreads();
    const float tr = s_tr;

    // Phase C: compact rescore set
    for (int c = tid; c < K; c += 1024) {
        if (s_av[c] >= tr) {
            int p = atomicAdd(&s_rcnt, 1);
            if (p < CCAP) r_idx[p] = s_idx[c];
        }
    }
    __syncthreads();
    int R = s_rcnt < CCAP ? s_rcnt : CCAP;

    // Phase D: fp32 rescore (one warp per candidate)
    for (int c = wid; c < R; c += 32) {
        int idx = r_idx[c];
        int q = idx / L_;
        int l = idx - q * L_;
        const float4* a = reinterpret_cast<const float4*>(
            logits + (size_t)(b * Q_ + q) * T_ + lane * 8);
        const float4* p = reinterpret_cast<const float4*>(
            posmap + (size_t)l * T_ + lane * 8);
        float4 a0 = a[0], a1 = a[1], p0 = p[0], p1 = p[1];
        float s = sigf(a0.x) * p0.x + sigf(a0.y) * p0.y
                + sigf(a0.z) * p0.z + sigf(a0.w) * p0.w
                + sigf(a1.x) * p1.x + sigf(a1.y) * p1.y
                + sigf(a1.z) * p1.z + sigf(a1.w) * p1.w;
#pragma unroll
        for (int o = 16; o > 0; o >>= 1) s += __shfl_xor_sync(0xFFFFFFFFu, s, o);
        if (lane == 0) r_ev[c] = s;
    }
    __syncthreads();

    // Phase E: exact histogram over [tr-1, tr+7); exact 50th edge
    for (int i = tid; i < 128; i += 1024) hist[i] = 0u;
    __syncthreads();
    const float base = tr - 1.0f;
    for (int c = tid; c < R; c += 1024) {
        int bin = (int)((r_ev[c] - base) * 16.0f);
        bin = bin < 0 ? 0 : (bin > 127 ? 127 : bin);
        atomicAdd(&hist[bin], 1u);
    }
    __syncthreads();
    if (tid == 0) {
        unsigned cum = 0;
        int eb = 0;
        for (int k = 127; k >= 0; k--) {
            cum += hist[k];
            if (cum >= NSEL) { eb = k; break; }
        }
        s_estar = base + eb * (1.0f / 16.0f);
    }
    __syncthreads();
    const float estar = s_estar;

    // Phase F: compact exact finalists
    for (int c = tid; c < R; c += 1024) {
        if (r_ev[c] >= estar) {
            int p = atomicAdd(&s_r2cnt, 1);
            if (p < RS2_CAP) { r2_idx[p] = r_idx[c]; r2_ev[p] = r_ev[c]; }
        }
    }
    __syncthreads();
    int R2 = s_r2cnt < RS2_CAP ? s_r2cnt : RS2_CAP;

    // Phase G: exact rank (value desc, index asc) + epilogue
    for (int jj = tid; jj < R2; jj += 1024) {
        float vj = r2_ev[jj];
        int   ij = r2_idx[jj];
        int rank = 0;
        for (int i = 0; i < R2; i++) {
            float vi = r2_ev[i];
            int   ii = r2_idx[i];
            if (vi > vj || (vi == vj && ii < ij)) rank++;
        }
        if (rank < NSEL) {
            int o = b * NSEL + rank;
            out[o] = vj;
            int q = ij / L_;
            int l = ij - q * L_;
            int label = 0;
#pragma unroll
            for (int t = 0; t < 80; t++)
                if (c_tok[t] == l) label = t;
            out[B_ * NSEL + o] = (float)label;
            const float* bb = bbox + (size_t)(b * Q_ + q) * 4;
            float cx = bb[0], cy = bb[1], w = bb[2], h = bb[3];
            float ih = tsz[2 * b + 0], iw = tsz[2 * b + 1];
            float* ob = out + 2 * B_ * NSEL + (size_t)o * 4;
            ob[0] = (cx - 0.5f * w) * iw;
            ob[1] = (cy - 0.5f * h) * ih;
            ob[2] = (cx + 0.5f * w) * iw;
            ob[3] = (cy + 0.5f * h) * ih;
        }
    }
}

// ---------------------------------------------------------------------------
extern "C" void kernel_launch(void* const* d_in, const int* in_sizes, int n_in,
                              void* d_out, int out_size) {
    const float* logits = (const float*)d_in[0];
    const float* bbox   = (const float*)d_in[1];
    const float* posmap = (const float*)d_in[2];
    const float* tsz    = (const float*)d_in[3];
    float* out = (float*)d_out;

    cudaFuncSetAttribute(gemm_kernel,
        cudaFuncAttributeMaxDynamicSharedMemorySize, NBUF * STG_BYTES);
    cudaFuncSetAttribute(final_kernel,
        cudaFuncAttributeMaxDynamicSharedMemorySize, CCAP * 12);

    zero_kernel<<<(M_ + 255) / 256, 256>>>();

    const int n4 = (M_ * T_) / 4;
    sigmoid_kernel<<<(n4 + 255) / 256, 256>>>(logits, n4);
    posconv_kernel<<<(L_ * T_ / 2 + 255) / 256, 256>>>(posmap, L_ * T_ / 2);

    dim3 ggrid(M_ / 128, (L_ + 127) / 128);   // 450 x 7
    gemm_kernel<<<ggrid, 256, NBUF * STG_BYTES>>>();

    dim3 sgrid(B_, 4);
    cmax_scan_kernel<<<sgrid, 256>>>();
    pick_kernel<<<1, B_>>>();
    dim3 cgrid(B_, 12);
    collect_kernel<<<cgrid, 256>>>();
    fixup_kernel<<<B_, 1024>>>();
    final_kernel<<<B_, 1024, CCAP * 12>>>(logits, bbox, tsz, out, posmap);
}

// round 11
// speedup vs baseline: 5.9938x; 1.0251x over previous
#include <cuda_runtime.h>
#include <cuda_fp16.h>
#include <cuda_bf16.h>
#include <cstdint>

// Problem constants
#define B_    64
#define Q_    900
#define T_    256
#define L_    769
#define LP    776            // padded row stride (16B-aligned rows of half)
#define NSEL  50
#define M_    (B_ * Q_)      // 57600
#define CCAP  8192
#define NSL   32             // ladder levels (0.25 steps, down to max-8)
#define CMINC 256u           // min chunk count above tau
#define RS2_CAP 2048
#define NCH   97             // 8-wide chunks per row (769 -> 97)
#define CPAD  104            // padded cmax row stride (16B aligned)

// Scratch (static device globals; allocation-free)
__device__ __nv_bfloat16  g_sig_b[(size_t)M_ * T_];    // bf16 sigmoid, 29.5 MB
__device__ __nv_bfloat16  g_pos_b[(size_t)L_ * T_];    // bf16 posmap
__device__ __half         g_prob_h[(size_t)M_ * LP];   // approx prob fp16, 89 MB
__device__ __half         g_cmax[(size_t)M_ * CPAD];   // per-chunk max, 12 MB
__device__ unsigned       g_maxbits[B_];               // per-batch max (uint bits)
__device__ unsigned       g_scnt[B_][NSL];             // chunk ladder counts
__device__ float          g_tau[B_];
__device__ int            g_ccnt[B_];
__device__ int            g_cand[B_][CCAP];            // candidate flat idx (q*L+l)
__device__ __half         g_cval[B_][CCAP];            // candidate approx value

__constant__ int c_tok[80] = {
    0, 9, 19, 25, 38, 49, 55, 63, 71, 78, 94, 109, 121, 137, 145, 152,
    158, 164, 172, 180, 186, 197, 204, 212, 222, 233, 244, 254, 260, 271,
    281, 288, 300, 314, 321, 336, 353, 366, 378, 394, 403, 416, 422, 429,
    437, 445, 452, 461, 469, 480, 489, 500, 509, 519, 527, 535, 542, 550,
    558, 573, 579, 594, 603, 608, 617, 625, 634, 645, 658, 670, 677, 687,
    694, 709, 716, 724, 731, 742, 755, 768};

// ---------------------------------------------------------------------------
// Helpers
// ---------------------------------------------------------------------------
__device__ __forceinline__ uint32_t smem_u32(const void* p) {
    uint32_t a;
    asm("{ .reg .u64 t; cvta.to.shared.u64 t, %1; cvt.u32.u64 %0, t; }" : "=r"(a) : "l"(p));
    return a;
}
__device__ __forceinline__ void cp_async16(uint32_t dst, const void* src, bool valid) {
    int sz = valid ? 16 : 0;   // src-size 0 => zero-fill 16B
    asm volatile("cp.async.cg.shared.global [%0], [%1], 16, %2;\n"
                 :: "r"(dst), "l"(src), "r"(sz));
}
__device__ __forceinline__ void cp_commit() { asm volatile("cp.async.commit_group;"); }
template <int N> __device__ __forceinline__ void cp_wait() {
    asm volatile("cp.async.wait_group %0;" :: "n"(N));
}
__device__ __forceinline__ void ldmatrix_x4(uint32_t* f, uint32_t addr) {
    asm volatile("ldmatrix.sync.aligned.m8n8.x4.shared.b16 {%0,%1,%2,%3}, [%4];"
                 : "=r"(f[0]), "=r"(f[1]), "=r"(f[2]), "=r"(f[3]) : "r"(addr));
}
__device__ __forceinline__ void mma_bf16(float* d, const uint32_t* a,
                                         uint32_t b0, uint32_t b1) {
    asm volatile(
        "mma.sync.aligned.m16n8k16.row.col.f32.bf16.bf16.f32 "
        "{%0,%1,%2,%3}, {%4,%5,%6,%7}, {%8,%9}, {%0,%1,%2,%3};"
        : "+f"(d[0]), "+f"(d[1]), "+f"(d[2]), "+f"(d[3])
        : "r"(a[0]), "r"(a[1]), "r"(a[2]), "r"(a[3]), "r"(b0), "r"(b1));
}
__device__ __forceinline__ float sigf(float x) {
    return 1.0f / (1.0f + __expf(-x));
}

// ---------------------------------------------------------------------------
// Kernel 0: reset counters + -inf pads (prob cols 768..775, cmax 96..103)
// ---------------------------------------------------------------------------
__global__ void zero_kernel() {
    int i = blockIdx.x * blockDim.x + threadIdx.x;
    uint4 ninf = make_uint4(0xFC00FC00u, 0xFC00FC00u, 0xFC00FC00u, 0xFC00FC00u);
    if (i < M_) {
        *reinterpret_cast<uint4*>(g_prob_h + (size_t)i * LP + 768) = ninf;
        *reinterpret_cast<uint4*>(g_cmax   + (size_t)i * CPAD + 96) = ninf;
    }
    if (i < B_) { g_ccnt[i] = 0; g_maxbits[i] = 0u; }
    if (i < B_ * NSL) ((unsigned*)g_scnt)[i] = 0u;
}

// ---------------------------------------------------------------------------
// Kernel 1: sigmoid -> bf16 ; 1b: posmap -> bf16
// ---------------------------------------------------------------------------
__global__ void sigmoid_kernel(const float* __restrict__ x, int n4) {
    int i = blockIdx.x * blockDim.x + threadIdx.x;
    if (i < n4) {
        float4 v = reinterpret_cast<const float4*>(x)[i];
        __nv_bfloat162* o = reinterpret_cast<__nv_bfloat162*>(g_sig_b) + 2 * i;
        o[0] = __floats2bfloat162_rn(sigf(v.x), sigf(v.y));
        o[1] = __floats2bfloat162_rn(sigf(v.z), sigf(v.w));
    }
}

__global__ void posconv_kernel(const float* __restrict__ p, int n2) {
    int i = blockIdx.x * blockDim.x + threadIdx.x;
    if (i < n2) {
        float2 v = reinterpret_cast<const float2*>(p)[i];
        reinterpret_cast<__nv_bfloat162*>(g_pos_b)[i] = __floats2bfloat162_rn(v.x, v.y);
    }
}

// ---------------------------------------------------------------------------
// Kernel 2: bf16 mma.sync GEMM, CTA 128x128, BK=32, 6-buffer depth-3 pipeline.
// Round-9 mainloop structure with all ldmatrix swizzle offsets hoisted into
// registers (per-stage address = buffer base + precomputed offset, 1 IADD).
// Epilogue writes prob fp16 + per-chunk max + per-batch max.
// ---------------------------------------------------------------------------
#define STG_BYTES 16384
#define NSTG 8   // 256/32 k-stages
#define NBUF 6

__global__ __launch_bounds__(256) void gemm_kernel() {
    extern __shared__ char dsm[];
    const uint32_t sbase = smem_u32(dsm);
    __shared__ unsigned s_mx0, s_mx1;
    const int tid  = threadIdx.x;
    const int wid  = tid >> 5;
    const int lane = tid & 31;
    const int wm   = wid & 3;      // 0..3 (m)
    const int wn   = wid >> 2;     // 0..1 (n)
    const int m0   = blockIdx.x * 128;
    const int l0   = blockIdx.y * 128;

    if (tid == 0) { s_mx0 = 0u; s_mx1 = 0u; }

    float acc[2][8][4];
#pragma unroll
    for (int a = 0; a < 2; a++)
#pragma unroll
        for (int b = 0; b < 8; b++)
#pragma unroll
            for (int c = 0; c < 4; c++) acc[a][b][c] = 0.0f;

    auto load_stage = [&](int s) {
        const uint32_t base = sbase + (s % NBUF) * STG_BYTES;
        const int k0 = s * 32;
#pragma unroll
        for (int t = 0; t < 2; t++) {              // A
            int ch = tid + t * 256;
            int r  = ch >> 2;
            int cc = ch & 3;
            int ph = cc ^ ((r >> 1) & 3);
            cp_async16(base + r * 64 + ph * 16,
                       g_sig_b + (size_t)(m0 + r) * T_ + k0 + cc * 8, true);
        }
#pragma unroll
        for (int t = 0; t < 2; t++) {              // B
            int ch = tid + t * 256;
            int r  = ch >> 2;
            int cc = ch & 3;
            int ph = cc ^ ((r >> 1) & 3);
            bool ok = (l0 + r) < L_;
            cp_async16(base + 8192 + r * 64 + ph * 16,
                       g_pos_b + (size_t)(l0 + r) * T_ + k0 + cc * 8, ok);
        }
        cp_commit();
    };

    load_stage(0);
    load_stage(1);
    load_stage(2);

    const int j  = lane >> 3;
    const int r8 = lane & 7;

    // Precompute all swizzled ldmatrix offsets (relative to stage buffer base).
    uint32_t offA[2][2];   // [ks][mt]
    uint32_t offB[2][4];   // [ks][np] (includes +8192 B-tile base)
#pragma unroll
    for (int ks = 0; ks < 2; ks++) {
#pragma unroll
        for (int mt = 0; mt < 2; mt++) {
            int rl = wm * 32 + mt * 16 + ((j & 1) << 3) + r8;
            int cc = ks * 2 + (j >> 1);
            int ph = cc ^ ((rl >> 1) & 3);
            offA[ks][mt] = rl * 64 + ph * 16;
        }
#pragma unroll
        for (int np = 0; np < 4; np++) {
            int nl = wn * 64 + np * 16 + ((j >> 1) << 3) + r8;
            int cc = ks * 2 + (j & 1);
            int ph = cc ^ ((nl >> 1) & 3);
            offB[ks][np] = 8192 + nl * 64 + ph * 16;
        }
    }

    for (int s = 0; s < NSTG; s++) {
        if (s + 3 < NSTG)      { load_stage(s + 3); cp_wait<3>(); }
        else if (s + 2 < NSTG) cp_wait<2>();
        else if (s + 1 < NSTG) cp_wait<1>();
        else                   cp_wait<0>();
        __syncthreads();

        const uint32_t bufb = sbase + (s % NBUF) * STG_BYTES;

#pragma unroll
        for (int ks = 0; ks < 2; ks++) {
            uint32_t Af[2][4];
#pragma unroll
            for (int mt = 0; mt < 2; mt++)
                ldmatrix_x4(Af[mt], bufb + offA[ks][mt]);
#pragma unroll
            for (int np = 0; np < 4; np++) {
                uint32_t Bf[4];
                ldmatrix_x4(Bf, bufb + offB[ks][np]);
#pragma unroll
                for (int mt = 0; mt < 2; mt++) {
                    mma_bf16(acc[mt][2 * np],     Af[mt], Bf[0], Bf[1]);
                    mma_bf16(acc[mt][2 * np + 1], Af[mt], Bf[2], Bf[3]);
                }
            }
        }
    }

    // ---- epilogue: prob fp16 + chunk-max + per-batch max ----
    const int g  = lane >> 2;
    const int t4 = lane & 3;
    const int b0  = m0 / Q_;
    const int bnd = (b0 + 1) * Q_;
    const float NINF = -1e30f;
    float mx0 = 0.0f, mx1 = 0.0f;
#pragma unroll
    for (int mt = 0; mt < 2; mt++) {
        const int row = m0 + wm * 32 + mt * 16 + g;
#pragma unroll
        for (int nt = 0; nt < 8; nt++) {
            int col = l0 + wn * 64 + nt * 8 + t4 * 2;
            float v0 = acc[mt][nt][0], v1 = acc[mt][nt][1];
            float v2 = acc[mt][nt][2], v3 = acc[mt][nt][3];
            float a01 = fmaxf(v0, v1), a23 = fmaxf(v2, v3);
            if (row     >= bnd) mx1 = fmaxf(mx1, a01); else mx0 = fmaxf(mx0, a01);
            if (row + 8 >= bnd) mx1 = fmaxf(mx1, a23); else mx0 = fmaxf(mx0, a23);

            // chunk-max: mask invalid cols, reduce across the 4-lane t4 group
            float m01 = fmaxf(col < L_ ? v0 : NINF, col + 1 < L_ ? v1 : NINF);
            float m23 = fmaxf(col < L_ ? v2 : NINF, col + 1 < L_ ? v3 : NINF);
            m01 = fmaxf(m01, __shfl_xor_sync(0xFFFFFFFFu, m01, 1));
            m01 = fmaxf(m01, __shfl_xor_sync(0xFFFFFFFFu, m01, 2));
            m23 = fmaxf(m23, __shfl_xor_sync(0xFFFFFFFFu, m23, 1));
            m23 = fmaxf(m23, __shfl_xor_sync(0xFFFFFFFFu, m23, 2));
            int ch = (l0 >> 3) + wn * 8 + nt;
            if (t4 == 0 && ch < NCH) {
                g_cmax[(size_t)row * CPAD + ch]       = __float2half(m01);
                g_cmax[(size_t)(row + 8) * CPAD + ch] = __float2half(m23);
            }

            if (col + 1 < L_) {
                *reinterpret_cast<__half2*>(g_prob_h + (size_t)row * LP + col) =
                    __floats2half2_rn(v0, v1);
                *reinterpret_cast<__half2*>(g_prob_h + (size_t)(row + 8) * LP + col) =
                    __floats2half2_rn(v2, v3);
            } else if (col < L_) {
                g_prob_h[(size_t)row * LP + col] = __float2half(v0);
                g_prob_h[(size_t)(row + 8) * LP + col] = __float2half(v2);
            }
        }
    }
#pragma unroll
    for (int o = 16; o > 0; o >>= 1) {
        mx0 = fmaxf(mx0, __shfl_xor_sync(0xFFFFFFFFu, mx0, o));
        mx1 = fmaxf(mx1, __shfl_xor_sync(0xFFFFFFFFu, mx1, o));
    }
    __syncthreads();
    if (lane == 0) {
        atomicMax(&s_mx0, __float_as_uint(mx0));
        if (bnd < m0 + 128) atomicMax(&s_mx1, __float_as_uint(mx1));
    }
    __syncthreads();
    if (tid == 0) {
        atomicMax(&g_maxbits[b0], s_mx0);
        if (bnd < m0 + 128) atomicMax(&g_maxbits[b0 + 1], s_mx1);
    }
}

// ---------------------------------------------------------------------------
// Kernel 3: exact ladder over chunk-maxes (12MB). grid (64, 4).
// ---------------------------------------------------------------------------
__global__ __launch_bounds__(256) void cmax_scan_kernel() {
    const int b    = blockIdx.x;
    const int part = blockIdx.y;
    const int tid  = threadIdx.x;
    const float mx = __uint_as_float(g_maxbits[b]);
    const float lo = mx - 8.0f;
    __shared__ unsigned h[NSL];
    if (tid < NSL) h[tid] = 0u;
    __syncthreads();

    const int r0 = part * 225;                  // 4 x 225 = 900 rows
    const int n  = 225 * (CPAD / 8);            // uint4 per part (13 per row)
    for (int i = tid; i < n; i += 256) {
        int r  = i / 13;
        int c4 = i - r * 13;
        const uint4 v = reinterpret_cast<const uint4*>(
            g_cmax + (size_t)(b * Q_ + r0 + r) * CPAD)[c4];
        const __half2* hh = reinterpret_cast<const __half2*>(&v);
#pragma unroll
        for (int e = 0; e < 4; e++) {
            float2 f2 = __half22float2(hh[e]);
            float fs[2] = {f2.x, f2.y};
#pragma unroll
            for (int u = 0; u < 2; u++) {
                float f = fs[u];
                if (f > lo) {
                    int k = (int)((mx - f) * 4.0f);
                    k = k < 0 ? 0 : (k > NSL - 1 ? NSL - 1 : k);
                    atomicAdd(&h[k], 1u);
                }
            }
        }
    }
    __syncthreads();
    if (tid < NSL && h[tid]) atomicAdd(&g_scnt[b][tid], h[tid]);
}

// ---------------------------------------------------------------------------
// Kernel 3b: tau = level where cumulative chunk count >= CMINC
// ---------------------------------------------------------------------------
__global__ void pick_kernel() {
    int b = threadIdx.x;
    if (b < B_) {
        float mx = __uint_as_float(g_maxbits[b]);
        float tau = mx - 8.0f;
        unsigned cum = 0;
        for (int k = 0; k < NSL; k++) {
            cum += g_scnt[b][k];
            if (cum >= CMINC) { tau = mx - 0.25f * (k + 1); break; }
        }
        g_tau[b] = tau;
    }
}

// ---------------------------------------------------------------------------
// Kernel 4: cmax-gated collect. grid (64, 12).
// ---------------------------------------------------------------------------
#define ROWS_PER_PART 75

__global__ __launch_bounds__(256) void collect_kernel() {
    const int b    = blockIdx.x;
    const int part = blockIdx.y;
    const __half tau = __float2half_rd(g_tau[b]);

    const int n = ROWS_PER_PART * NCH;
    for (int i = threadIdx.x; i < n; i += 256) {
        int r = i / NCH;
        int c = i - r * NCH;
        int q = part * ROWS_PER_PART + r;
        __half cm = g_cmax[(size_t)(b * Q_ + q) * CPAD + c];
        if (__hge(cm, tau)) {
            const uint4 v = reinterpret_cast<const uint4*>(
                g_prob_h + (size_t)(b * Q_ + q) * LP)[c];
            const __half2* hh = reinterpret_cast<const __half2*>(&v);
#pragma unroll
            for (int e = 0; e < 4; e++) {
                __half lo = __low2half(hh[e]), hi = __high2half(hh[e]);
                if (__hge(lo, tau)) {
                    int p = atomicAdd(&g_ccnt[b], 1);
                    if (p < CCAP) {
                        g_cand[b][p] = q * L_ + c * 8 + e * 2;
                        g_cval[b][p] = lo;
                    }
                }
                if (__hge(hi, tau)) {
                    int p = atomicAdd(&g_ccnt[b], 1);
                    if (p < CCAP) {
                        g_cand[b][p] = q * L_ + c * 8 + e * 2 + 1;
                        g_cval[b][p] = hi;
                    }
                }
            }
        }
    }
}

// ---------------------------------------------------------------------------
// Kernel 4b: fixup loop — re-collect until 64 <= K <= CCAP (normally noop).
// ---------------------------------------------------------------------------
__global__ __launch_bounds__(1024) void fixup_kernel() {
    const int b   = blockIdx.x;
    const int tid = threadIdx.x;
    __shared__ float s_tau;
    for (int iter = 0; iter < 8; iter++) {
        __syncthreads();
        int K = g_ccnt[b];
        if (K >= 64 && K <= CCAP) return;
        if (tid == 0) {
            float t = g_tau[b] + (K > CCAP ? 0.25f : -2.0f);
            g_tau[b] = t;
            g_ccnt[b] = 0;
            s_tau = t;
        }
        __syncthreads();
        const __half htau = __float2half_rd(s_tau);
        for (int i = tid; i < Q_ * L_; i += 1024) {
            int q = i / L_;
            int l = i - q * L_;
            __half v = g_prob_h[(size_t)(b * Q_ + q) * LP + l];
            if (__hge(v, htau)) {
                int p = atomicAdd(&g_ccnt[b], 1);
                if (p < CCAP) { g_cand[b][p] = i; g_cval[b][p] = v; }
            }
        }
    }
}

// ---------------------------------------------------------------------------
// Kernel 5: approx-select + fp32 rescore + exact-select + rank + epilogue.
// ---------------------------------------------------------------------------
__global__ __launch_bounds__(1024) void final_kernel(
    const float* __restrict__ logits, const float* __restrict__ bbox,
    const float* __restrict__ tsz, float* __restrict__ out,
    const float* __restrict__ posmap)
{
    extern __shared__ char fsm[];
    float* s_av  = reinterpret_cast<float*>(fsm);                 // [CCAP]
    int*   s_idx = reinterpret_cast<int*>(fsm + CCAP * 4);        // [CCAP]
    int*   r_idx = reinterpret_cast<int*>(fsm + CCAP * 8);        // [CCAP]
    float* r_ev  = s_av;                                          // alias
    __shared__ unsigned hist[128];
    __shared__ int   s_rcnt, s_r2cnt;
    __shared__ float s_tr, s_estar;
    __shared__ int   r2_idx[RS2_CAP];
    __shared__ float r2_ev[RS2_CAP];

    const int b    = blockIdx.x;
    const int tid  = threadIdx.x;
    const int wid  = tid >> 5;
    const int lane = tid & 31;
    const float tau = g_tau[b];

    int K = g_ccnt[b];
    if (K > CCAP) K = CCAP;

    // Phase A: load candidates + approx histogram over [tau, tau+8)
    for (int i = tid; i < 128; i += 1024) hist[i] = 0u;
    if (tid == 0) { s_rcnt = 0; s_r2cnt = 0; }
    __syncthreads();
    for (int c = tid; c < K; c += 1024) {
        float v = __half2float(g_cval[b][c]);
        s_av[c]  = v;
        s_idx[c] = g_cand[b][c];
        int bin = (int)((v - tau) * 16.0f);
        bin = bin < 0 ? 0 : (bin > 127 ? 127 : bin);
        atomicAdd(&hist[bin], 1u);
    }
    __syncthreads();

    // Phase B: approx 50th edge; rescore threshold = edge - 1.0
    if (tid == 0) {
        unsigned cum = 0;
        int bstar = 0;
        for (int k = 127; k >= 0; k--) {
            cum += hist[k];
            if (cum >= NSEL) { bstar = k; break; }
        }
        s_tr = tau + bstar * (1.0f / 16.0f) - 1.0f;
    }
    __syncthreads();
    const float tr = s_tr;

    // Phase C: compact rescore set
    for (int c = tid; c < K; c += 1024) {
        if (s_av[c] >= tr) {
            int p = atomicAdd(&s_rcnt, 1);
            if (p < CCAP) r_idx[p] = s_idx[c];
        }
    }
    __syncthreads();
    int R = s_rcnt < CCAP ? s_rcnt : CCAP;

    // Phase D: fp32 rescore (one warp per candidate)
    for (int c = wid; c < R; c += 32) {
        int idx = r_idx[c];
        int q = idx / L_;
        int l = idx - q * L_;
        const float4* a = reinterpret_cast<const float4*>(
            logits + (size_t)(b * Q_ + q) * T_ + lane * 8);
        const float4* p = reinterpret_cast<const float4*>(
            posmap + (size_t)l * T_ + lane * 8);
        float4 a0 = a[0], a1 = a[1], p0 = p[0], p1 = p[1];
        float s = sigf(a0.x) * p0.x + sigf(a0.y) * p0.y
                + sigf(a0.z) * p0.z + sigf(a0.w) * p0.w
                + sigf(a1.x) * p1.x + sigf(a1.y) * p1.y
                + sigf(a1.z) * p1.z + sigf(a1.w) * p1.w;
#pragma unroll
        for (int o = 16; o > 0; o >>= 1) s += __shfl_xor_sync(0xFFFFFFFFu, s, o);
        if (lane == 0) r_ev[c] = s;
    }
    __syncthreads();

    // Phase E: exact histogram over [tr-1, tr+7); exact 50th edge
    for (int i = tid; i < 128; i += 1024) hist[i] = 0u;
    __syncthreads();
    const float base = tr - 1.0f;
    for (int c = tid; c < R; c += 1024) {
        int bin = (int)((r_ev[c] - base) * 16.0f);
        bin = bin < 0 ? 0 : (bin > 127 ? 127 : bin);
        atomicAdd(&hist[bin], 1u);
    }
    __syncthreads();
    if (tid == 0) {
        unsigned cum = 0;
        int eb = 0;
        for (int k = 127; k >= 0; k--) {
            cum += hist[k];
            if (cum >= NSEL) { eb = k; break; }
        }
        s_estar = base + eb * (1.0f / 16.0f);
    }
    __syncthreads();
    const float estar = s_estar;

    // Phase F: compact exact finalists
    for (int c = tid; c < R; c += 1024) {
        if (r_ev[c] >= estar) {
            int p = atomicAdd(&s_r2cnt, 1);
            if (p < RS2_CAP) { r2_idx[p] = r_idx[c]; r2_ev[p] = r_ev[c]; }
        }
    }
    __syncthreads();
    int R2 = s_r2cnt < RS2_CAP ? s_r2cnt : RS2_CAP;

    // Phase G: exact rank (value desc, index asc) + epilogue
    for (int jj = tid; jj < R2; jj += 1024) {
        float vj = r2_ev[jj];
        int   ij = r2_idx[jj];
        int rank = 0;
        for (int i = 0; i < R2; i++) {
            float vi = r2_ev[i];
            int   ii = r2_idx[i];
            if (vi > vj || (vi == vj && ii < ij)) rank++;
        }
        if (rank < NSEL) {
            int o = b * NSEL + rank;
            out[o] = vj;
            int q = ij / L_;
            int l = ij - q * L_;
            int label = 0;
#pragma unroll
            for (int t = 0; t < 80; t++)
                if (c_tok[t] == l) label = t;
            out[B_ * NSEL + o] = (float)label;
            const float* bb = bbox + (size_t)(b * Q_ + q) * 4;
            float cx = bb[0], cy = bb[1], w = bb[2], h = bb[3];
            float ih = tsz[2 * b + 0], iw = tsz[2 * b + 1];
            float* ob = out + 2 * B_ * NSEL + (size_t)o * 4;
            ob[0] = (cx - 0.5f * w) * iw;
            ob[1] = (cy - 0.5f * h) * ih;
            ob[2] = (cx + 0.5f * w) * iw;
            ob[3] = (cy + 0.5f * h) * ih;
        }
    }
}

// ---------------------------------------------------------------------------
extern "C" void kernel_launch(void* const* d_in, const int* in_sizes, int n_in,
                              void* d_out, int out_size) {
    const float* logits = (const float*)d_in[0];
    const float* bbox   = (const float*)d_in[1];
    const float* posmap = (const float*)d_in[2];
    const float* tsz    = (const float*)d_in[3];
    float* out = (float*)d_out;

    cudaFuncSetAttribute(gemm_kernel,
        cudaFuncAttributeMaxDynamicSharedMemorySize, NBUF * STG_BYTES);
    cudaFuncSetAttribute(final_kernel,
        cudaFuncAttributeMaxDynamicSharedMemorySize, CCAP * 12);

    zero_kernel<<<(M_ + 255) / 256, 256>>>();

    const int n4 = (M_ * T_) / 4;
    sigmoid_kernel<<<(n4 + 255) / 256, 256>>>(logits, n4);
    posconv_kernel<<<(L_ * T_ / 2 + 255) / 256, 256>>>(posmap, L_ * T_ / 2);

    dim3 ggrid(M_ / 128, (L_ + 127) / 128);   // 450 x 7
    gemm_kernel<<<ggrid, 256, NBUF * STG_BYTES>>>();

    dim3 sgrid(B_, 4);
    cmax_scan_kernel<<<sgrid, 256>>>();
    pick_kernel<<<1, B_>>>();
    dim3 cgrid(B_, 12);
    collect_kernel<<<cgrid, 256>>>();
    fixup_kernel<<<B_, 1024>>>();
    final_kernel<<<B_, 1024, CCAP * 12>>>(logits, bbox, tsz, out, posmap);
}

// round 13
// speedup vs baseline: 6.5437x; 1.0917x over previous
#include <cuda_runtime.h>
#include <cuda_fp16.h>
#include <cuda_bf16.h>
#include <cstdint>

// Problem constants
#define B_    64
#define Q_    900
#define T_    256
#define L_    769
#define LP    776            // padded row stride (16B-aligned rows of half)
#define NSEL  50
#define M_    (B_ * Q_)      // 57600
#define CCAP  8192
#define NSL   32             // ladder levels (0.25 steps, down to max-8)
#define CMINC 256u           // min chunk count above tau
#define RS2_CAP 2048
#define NCH   97             // 8-wide chunks per row (769 -> 97)
#define CPAD  104            // padded cmax row stride (16B aligned)

// Scratch (static device globals; allocation-free)
__device__ __nv_bfloat16  g_sig_b[(size_t)M_ * T_];    // bf16 sigmoid, 29.5 MB
__device__ __nv_bfloat16  g_pos_b[(size_t)L_ * T_];    // bf16 posmap
__device__ __half         g_prob_h[(size_t)M_ * LP];   // approx prob fp16, 89 MB
__device__ __half         g_cmax[(size_t)M_ * CPAD];   // per-chunk max, 12 MB
__device__ unsigned       g_maxbits[B_];               // per-batch max (uint bits)
__device__ unsigned       g_scnt[B_][NSL];             // chunk ladder counts
__device__ float          g_tau[B_];
__device__ int            g_ccnt[B_];
__device__ int            g_cand[B_][CCAP];            // candidate flat idx (q*L+l)
__device__ __half         g_cval[B_][CCAP];            // candidate approx value

__constant__ int c_tok[80] = {
    0, 9, 19, 25, 38, 49, 55, 63, 71, 78, 94, 109, 121, 137, 145, 152,
    158, 164, 172, 180, 186, 197, 204, 212, 222, 233, 244, 254, 260, 271,
    281, 288, 300, 314, 321, 336, 353, 366, 378, 394, 403, 416, 422, 429,
    437, 445, 452, 461, 469, 480, 489, 500, 509, 519, 527, 535, 542, 550,
    558, 573, 579, 594, 603, 608, 617, 625, 634, 645, 658, 670, 677, 687,
    694, 709, 716, 724, 731, 742, 755, 768};

// ---------------------------------------------------------------------------
// Helpers
// ---------------------------------------------------------------------------
__device__ __forceinline__ uint32_t smem_u32(const void* p) {
    uint32_t a;
    asm("{ .reg .u64 t; cvta.to.shared.u64 t, %1; cvt.u32.u64 %0, t; }" : "=r"(a) : "l"(p));
    return a;
}
__device__ __forceinline__ void cp_async16(uint32_t dst, const void* src, bool valid) {
    int sz = valid ? 16 : 0;   // src-size 0 => zero-fill 16B
    asm volatile("cp.async.cg.shared.global [%0], [%1], 16, %2;\n"
                 :: "r"(dst), "l"(src), "r"(sz));
}
__device__ __forceinline__ void cp_commit() { asm volatile("cp.async.commit_group;"); }
template <int N> __device__ __forceinline__ void cp_wait() {
    asm volatile("cp.async.wait_group %0;" :: "n"(N));
}
__device__ __forceinline__ void ldmatrix_x4(uint32_t* f, uint32_t addr) {
    asm volatile("ldmatrix.sync.aligned.m8n8.x4.shared.b16 {%0,%1,%2,%3}, [%4];"
                 : "=r"(f[0]), "=r"(f[1]), "=r"(f[2]), "=r"(f[3]) : "r"(addr));
}
__device__ __forceinline__ void mma_bf16(float* d, const uint32_t* a,
                                         uint32_t b0, uint32_t b1) {
    asm volatile(
        "mma.sync.aligned.m16n8k16.row.col.f32.bf16.bf16.f32 "
        "{%0,%1,%2,%3}, {%4,%5,%6,%7}, {%8,%9}, {%0,%1,%2,%3};"
        : "+f"(d[0]), "+f"(d[1]), "+f"(d[2]), "+f"(d[3])
        : "r"(a[0]), "r"(a[1]), "r"(a[2]), "r"(a[3]), "r"(b0), "r"(b1));
}
__device__ __forceinline__ float sigf(float x) {
    return 1.0f / (1.0f + __expf(-x));
}

// ---------------------------------------------------------------------------
// Kernel 0: reset counters + -inf pads (prob cols 768..775, cmax 96..103)
// ---------------------------------------------------------------------------
__global__ void zero_kernel() {
    int i = blockIdx.x * blockDim.x + threadIdx.x;
    uint4 ninf = make_uint4(0xFC00FC00u, 0xFC00FC00u, 0xFC00FC00u, 0xFC00FC00u);
    if (i < M_) {
        *reinterpret_cast<uint4*>(g_prob_h + (size_t)i * LP + 768) = ninf;
        *reinterpret_cast<uint4*>(g_cmax   + (size_t)i * CPAD + 96) = ninf;
    }
    if (i < B_) { g_ccnt[i] = 0; g_maxbits[i] = 0u; }
    if (i < B_ * NSL) ((unsigned*)g_scnt)[i] = 0u;
}

// ---------------------------------------------------------------------------
// Kernel 1: sigmoid -> bf16 ; 1b: posmap -> bf16
// ---------------------------------------------------------------------------
__global__ void sigmoid_kernel(const float* __restrict__ x, int n4) {
    int i = blockIdx.x * blockDim.x + threadIdx.x;
    if (i < n4) {
        float4 v = reinterpret_cast<const float4*>(x)[i];
        __nv_bfloat162* o = reinterpret_cast<__nv_bfloat162*>(g_sig_b) + 2 * i;
        o[0] = __floats2bfloat162_rn(sigf(v.x), sigf(v.y));
        o[1] = __floats2bfloat162_rn(sigf(v.z), sigf(v.w));
    }
}

__global__ void posconv_kernel(const float* __restrict__ p, int n2) {
    int i = blockIdx.x * blockDim.x + threadIdx.x;
    if (i < n2) {
        float2 v = reinterpret_cast<const float2*>(p)[i];
        reinterpret_cast<__nv_bfloat162*>(g_pos_b)[i] = __floats2bfloat162_rn(v.x, v.y);
    }
}

// ---------------------------------------------------------------------------
// Kernel 2: bf16 mma.sync GEMM, CTA 128x128, BK=32, 6-buffer depth-3 pipeline.
// Round-9 mainloop (inline ldmatrix offsets). Epilogue: prob fp16 stores +
// chunk-max staged through smem for coalesced 16B writes + per-batch max.
// ---------------------------------------------------------------------------
#define STG_BYTES 16384
#define NSTG 8   // 256/32 k-stages
#define NBUF 6

__global__ __launch_bounds__(256) void gemm_kernel() {
    extern __shared__ char dsm[];
    const uint32_t sbase = smem_u32(dsm);
    __shared__ unsigned s_mx0, s_mx1;
    const int tid  = threadIdx.x;
    const int wid  = tid >> 5;
    const int lane = tid & 31;
    const int wm   = wid & 3;      // 0..3 (m)
    const int wn   = wid >> 2;     // 0..1 (n)
    const int m0   = blockIdx.x * 128;
    const int l0   = blockIdx.y * 128;

    if (tid == 0) { s_mx0 = 0u; s_mx1 = 0u; }

    float acc[2][8][4];
#pragma unroll
    for (int a = 0; a < 2; a++)
#pragma unroll
        for (int b = 0; b < 8; b++)
#pragma unroll
            for (int c = 0; c < 4; c++) acc[a][b][c] = 0.0f;

    auto load_stage = [&](int s) {
        const uint32_t base = sbase + (s % NBUF) * STG_BYTES;
        const int k0 = s * 32;
#pragma unroll
        for (int t = 0; t < 2; t++) {              // A
            int ch = tid + t * 256;
            int r  = ch >> 2;
            int cc = ch & 3;
            int ph = cc ^ ((r >> 1) & 3);
            cp_async16(base + r * 64 + ph * 16,
                       g_sig_b + (size_t)(m0 + r) * T_ + k0 + cc * 8, true);
        }
#pragma unroll
        for (int t = 0; t < 2; t++) {              // B
            int ch = tid + t * 256;
            int r  = ch >> 2;
            int cc = ch & 3;
            int ph = cc ^ ((r >> 1) & 3);
            bool ok = (l0 + r) < L_;
            cp_async16(base + 8192 + r * 64 + ph * 16,
                       g_pos_b + (size_t)(l0 + r) * T_ + k0 + cc * 8, ok);
        }
        cp_commit();
    };

    load_stage(0);
    load_stage(1);
    load_stage(2);

    const int j  = lane >> 3;
    const int r8 = lane & 7;

    for (int s = 0; s < NSTG; s++) {
        if (s + 3 < NSTG)      { load_stage(s + 3); cp_wait<3>(); }
        else if (s + 2 < NSTG) cp_wait<2>();
        else if (s + 1 < NSTG) cp_wait<1>();
        else                   cp_wait<0>();
        __syncthreads();

        const uint32_t ab = sbase + (s % NBUF) * STG_BYTES;
        const uint32_t bb = ab + 8192;

#pragma unroll
        for (int ks = 0; ks < 2; ks++) {
            uint32_t Af[2][4];
#pragma unroll
            for (int mt = 0; mt < 2; mt++) {
                int rl = wm * 32 + mt * 16 + ((j & 1) << 3) + r8;
                int cc = ks * 2 + (j >> 1);
                int ph = cc ^ ((rl >> 1) & 3);
                ldmatrix_x4(Af[mt], ab + rl * 64 + ph * 16);
            }
#pragma unroll
            for (int np = 0; np < 4; np++) {
                uint32_t Bf[4];
                int nl = wn * 64 + np * 16 + ((j >> 1) << 3) + r8;
                int cc = ks * 2 + (j & 1);
                int ph = cc ^ ((nl >> 1) & 3);
                ldmatrix_x4(Bf, bb + nl * 64 + ph * 16);
#pragma unroll
                for (int mt = 0; mt < 2; mt++) {
                    mma_bf16(acc[mt][2 * np],     Af[mt], Bf[0], Bf[1]);
                    mma_bf16(acc[mt][2 * np + 1], Af[mt], Bf[2], Bf[3]);
                }
            }
        }
    }

    // ---- epilogue: prob fp16 + staged chunk-max + per-batch max ----
    // cmax stage tile lives in pipeline buffer 0 (dead: last stage reads buf 1).
    __half* cmstage = reinterpret_cast<__half*>(dsm);   // [128][16] halves, 4KB

    const int g  = lane >> 2;
    const int t4 = lane & 3;
    const int b0  = m0 / Q_;
    const int bnd = (b0 + 1) * Q_;
    const float NINF = -1e30f;
    float mx0 = 0.0f, mx1 = 0.0f;
#pragma unroll
    for (int mt = 0; mt < 2; mt++) {
        const int row = m0 + wm * 32 + mt * 16 + g;
        const int rl  = wm * 32 + mt * 16 + g;      // local row 0..127
#pragma unroll
        for (int nt = 0; nt < 8; nt++) {
            int col = l0 + wn * 64 + nt * 8 + t4 * 2;
            float v0 = acc[mt][nt][0], v1 = acc[mt][nt][1];
            float v2 = acc[mt][nt][2], v3 = acc[mt][nt][3];
            float a01 = fmaxf(v0, v1), a23 = fmaxf(v2, v3);
            if (row     >= bnd) mx1 = fmaxf(mx1, a01); else mx0 = fmaxf(mx0, a01);
            if (row + 8 >= bnd) mx1 = fmaxf(mx1, a23); else mx0 = fmaxf(mx0, a23);

            // chunk-max: mask invalid cols, reduce across the 4-lane t4 group
            float m01 = fmaxf(col < L_ ? v0 : NINF, col + 1 < L_ ? v1 : NINF);
            float m23 = fmaxf(col < L_ ? v2 : NINF, col + 1 < L_ ? v3 : NINF);
            m01 = fmaxf(m01, __shfl_xor_sync(0xFFFFFFFFu, m01, 1));
            m01 = fmaxf(m01, __shfl_xor_sync(0xFFFFFFFFu, m01, 2));
            m23 = fmaxf(m23, __shfl_xor_sync(0xFFFFFFFFu, m23, 1));
            m23 = fmaxf(m23, __shfl_xor_sync(0xFFFFFFFFu, m23, 2));
            if (t4 == 0) {
                int chl = wn * 8 + nt;               // 0..15
                cmstage[rl * 16 + chl]       = __float2half(m01);
                cmstage[(rl + 8) * 16 + chl] = __float2half(m23);
            }

            if (col + 1 < L_) {
                *reinterpret_cast<__half2*>(g_prob_h + (size_t)row * LP + col) =
                    __floats2half2_rn(v0, v1);
                *reinterpret_cast<__half2*>(g_prob_h + (size_t)(row + 8) * LP + col) =
                    __floats2half2_rn(v2, v3);
            } else if (col < L_) {
                g_prob_h[(size_t)row * LP + col] = __float2half(v0);
                g_prob_h[(size_t)(row + 8) * LP + col] = __float2half(v2);
            }
        }
    }
#pragma unroll
    for (int o = 16; o > 0; o >>= 1) {
        mx0 = fmaxf(mx0, __shfl_xor_sync(0xFFFFFFFFu, mx0, o));
        mx1 = fmaxf(mx1, __shfl_xor_sync(0xFFFFFFFFu, mx1, o));
    }
    __syncthreads();   // cmstage fully written; s_mx init visible
    // coalesced cmax writeout: thread -> (row = tid>>1, 8-chunk half = tid&1)
    {
        int r    = tid >> 1;
        int hf   = tid & 1;
        int chb  = (l0 >> 3) + hf * 8;       // global chunk base
        if (chb + 8 <= CPAD) {               // skip 104..111 on last block
            uint4 v = *reinterpret_cast<uint4*>(cmstage + r * 16 + hf * 8);
            *reinterpret_cast<uint4*>(g_cmax + (size_t)(m0 + r) * CPAD + chb) = v;
        }
    }
    if (lane == 0) {
        atomicMax(&s_mx0, __float_as_uint(mx0));
        if (bnd < m0 + 128) atomicMax(&s_mx1, __float_as_uint(mx1));
    }
    __syncthreads();
    if (tid == 0) {
        atomicMax(&g_maxbits[b0], s_mx0);
        if (bnd < m0 + 128) atomicMax(&g_maxbits[b0 + 1], s_mx1);
    }
}

// ---------------------------------------------------------------------------
// Kernel 3: exact ladder over chunk-maxes (12MB). grid (64, 4).
// ---------------------------------------------------------------------------
__global__ __launch_bounds__(256) void cmax_scan_kernel() {
    const int b    = blockIdx.x;
    const int part = blockIdx.y;
    const int tid  = threadIdx.x;
    const float mx = __uint_as_float(g_maxbits[b]);
    const float lo = mx - 8.0f;
    __shared__ unsigned h[NSL];
    if (tid < NSL) h[tid] = 0u;
    __syncthreads();

    const int r0 = part * 225;                  // 4 x 225 = 900 rows
    const int n  = 225 * (CPAD / 8);            // uint4 per part (13 per row)
    for (int i = tid; i < n; i += 256) {
        int r  = i / 13;
        int c4 = i - r * 13;
        const uint4 v = reinterpret_cast<const uint4*>(
            g_cmax + (size_t)(b * Q_ + r0 + r) * CPAD)[c4];
        const __half2* hh = reinterpret_cast<const __half2*>(&v);
#pragma unroll
        for (int e = 0; e < 4; e++) {
            float2 f2 = __half22float2(hh[e]);
            float fs[2] = {f2.x, f2.y};
#pragma unroll
            for (int u = 0; u < 2; u++) {
                float f = fs[u];
                if (f > lo) {
                    int k = (int)((mx - f) * 4.0f);
                    k = k < 0 ? 0 : (k > NSL - 1 ? NSL - 1 : k);
                    atomicAdd(&h[k], 1u);
                }
            }
        }
    }
    __syncthreads();
    if (tid < NSL && h[tid]) atomicAdd(&g_scnt[b][tid], h[tid]);
}

// ---------------------------------------------------------------------------
// Kernel 3b: tau = level where cumulative chunk count >= CMINC
// ---------------------------------------------------------------------------
__global__ void pick_kernel() {
    int b = threadIdx.x;
    if (b < B_) {
        float mx = __uint_as_float(g_maxbits[b]);
        float tau = mx - 8.0f;
        unsigned cum = 0;
        for (int k = 0; k < NSL; k++) {
            cum += g_scnt[b][k];
            if (cum >= CMINC) { tau = mx - 0.25f * (k + 1); break; }
        }
        g_tau[b] = tau;
    }
}

// ---------------------------------------------------------------------------
// Kernel 4: cmax-gated collect. grid (64, 12).
// ---------------------------------------------------------------------------
#define ROWS_PER_PART 75

__global__ __launch_bounds__(256) void collect_kernel() {
    const int b    = blockIdx.x;
    const int part = blockIdx.y;
    const __half tau = __float2half_rd(g_tau[b]);

    const int n = ROWS_PER_PART * NCH;
    for (int i = threadIdx.x; i < n; i += 256) {
        int r = i / NCH;
        int c = i - r * NCH;
        int q = part * ROWS_PER_PART + r;
        __half cm = g_cmax[(size_t)(b * Q_ + q) * CPAD + c];
        if (__hge(cm, tau)) {
            const uint4 v = reinterpret_cast<const uint4*>(
                g_prob_h + (size_t)(b * Q_ + q) * LP)[c];
            const __half2* hh = reinterpret_cast<const __half2*>(&v);
#pragma unroll
            for (int e = 0; e < 4; e++) {
                __half lo = __low2half(hh[e]), hi = __high2half(hh[e]);
                if (__hge(lo, tau)) {
                    int p = atomicAdd(&g_ccnt[b], 1);
                    if (p < CCAP) {
                        g_cand[b][p] = q * L_ + c * 8 + e * 2;
                        g_cval[b][p] = lo;
                    }
                }
                if (__hge(hi, tau)) {
                    int p = atomicAdd(&g_ccnt[b], 1);
                    if (p < CCAP) {
                        g_cand[b][p] = q * L_ + c * 8 + e * 2 + 1;
                        g_cval[b][p] = hi;
                    }
                }
            }
        }
    }
}

// ---------------------------------------------------------------------------
// Kernel 4b: fixup loop — re-collect until 64 <= K <= CCAP (normally noop).
// ---------------------------------------------------------------------------
__global__ __launch_bounds__(1024) void fixup_kernel() {
    const int b   = blockIdx.x;
    const int tid = threadIdx.x;
    __shared__ float s_tau;
    for (int iter = 0; iter < 8; iter++) {
        __syncthreads();
        int K = g_ccnt[b];
        if (K >= 64 && K <= CCAP) return;
        if (tid == 0) {
            float t = g_tau[b] + (K > CCAP ? 0.25f : -2.0f);
            g_tau[b] = t;
            g_ccnt[b] = 0;
            s_tau = t;
        }
        __syncthreads();
        const __half htau = __float2half_rd(s_tau);
        for (int i = tid; i < Q_ * L_; i += 1024) {
            int q = i / L_;
            int l = i - q * L_;
            __half v = g_prob_h[(size_t)(b * Q_ + q) * LP + l];
            if (__hge(v, htau)) {
                int p = atomicAdd(&g_ccnt[b], 1);
                if (p < CCAP) { g_cand[b][p] = i; g_cval[b][p] = v; }
            }
        }
    }
}

// ---------------------------------------------------------------------------
// Kernel 5: approx-select + fp32 rescore + exact-select + rank + epilogue.
// ---------------------------------------------------------------------------
__global__ __launch_bounds__(1024) void final_kernel(
    const float* __restrict__ logits, const float* __restrict__ bbox,
    const float* __restrict__ tsz, float* __restrict__ out,
    const float* __restrict__ posmap)
{
    extern __shared__ char fsm[];
    float* s_av  = reinterpret_cast<float*>(fsm);                 // [CCAP]
    int*   s_idx = reinterpret_cast<int*>(fsm + CCAP * 4);        // [CCAP]
    int*   r_idx = reinterpret_cast<int*>(fsm + CCAP * 8);        // [CCAP]
    float* r_ev  = s_av;                                          // alias
    __shared__ unsigned hist[128];
    __shared__ int   s_rcnt, s_r2cnt;
    __shared__ float s_tr, s_estar;
    __shared__ int   r2_idx[RS2_CAP];
    __shared__ float r2_ev[RS2_CAP];

    const int b    = blockIdx.x;
    const int tid  = threadIdx.x;
    const int wid  = tid >> 5;
    const int lane = tid & 31;
    const float tau = g_tau[b];

    int K = g_ccnt[b];
    if (K > CCAP) K = CCAP;

    // Phase A: load candidates + approx histogram over [tau, tau+8)
    for (int i = tid; i < 128; i += 1024) hist[i] = 0u;
    if (tid == 0) { s_rcnt = 0; s_r2cnt = 0; }
    __syncthreads();
    for (int c = tid; c < K; c += 1024) {
        float v = __half2float(g_cval[b][c]);
        s_av[c]  = v;
        s_idx[c] = g_cand[b][c];
        int bin = (int)((v - tau) * 16.0f);
        bin = bin < 0 ? 0 : (bin > 127 ? 127 : bin);
        atomicAdd(&hist[bin], 1u);
    }
    __syncthreads();

    // Phase B: approx 50th edge; rescore threshold = edge - 1.0
    if (tid == 0) {
        unsigned cum = 0;
        int bstar = 0;
        for (int k = 127; k >= 0; k--) {
            cum += hist[k];
            if (cum >= NSEL) { bstar = k; break; }
        }
        s_tr = tau + bstar * (1.0f / 16.0f) - 1.0f;
    }
    __syncthreads();
    const float tr = s_tr;

    // Phase C: compact rescore set
    for (int c = tid; c < K; c += 1024) {
        if (s_av[c] >= tr) {
            int p = atomicAdd(&s_rcnt, 1);
            if (p < CCAP) r_idx[p] = s_idx[c];
        }
    }
    __syncthreads();
    int R = s_rcnt < CCAP ? s_rcnt : CCAP;

    // Phase D: fp32 rescore (one warp per candidate)
    for (int c = wid; c < R; c += 32) {
        int idx = r_idx[c];
        int q = idx / L_;
        int l = idx - q * L_;
        const float4* a = reinterpret_cast<const float4*>(
            logits + (size_t)(b * Q_ + q) * T_ + lane * 8);
        const float4* p = reinterpret_cast<const float4*>(
            posmap + (size_t)l * T_ + lane * 8);
        float4 a0 = a[0], a1 = a[1], p0 = p[0], p1 = p[1];
        float s = sigf(a0.x) * p0.x + sigf(a0.y) * p0.y
                + sigf(a0.z) * p0.z + sigf(a0.w) * p0.w
                + sigf(a1.x) * p1.x + sigf(a1.y) * p1.y
                + sigf(a1.z) * p1.z + sigf(a1.w) * p1.w;
#pragma unroll
        for (int o = 16; o > 0; o >>= 1) s += __shfl_xor_sync(0xFFFFFFFFu, s, o);
        if (lane == 0) r_ev[c] = s;
    }
    __syncthreads();

    // Phase E: exact histogram over [tr-1, tr+7); exact 50th edge
    for (int i = tid; i < 128; i += 1024) hist[i] = 0u;
    __syncthreads();
    const float base = tr - 1.0f;
    for (int c = tid; c < R; c += 1024) {
        int bin = (int)((r_ev[c] - base) * 16.0f);
        bin = bin < 0 ? 0 : (bin > 127 ? 127 : bin);
        atomicAdd(&hist[bin], 1u);
    }
    __syncthreads();
    if (tid == 0) {
        unsigned cum = 0;
        int eb = 0;
        for (int k = 127; k >= 0; k--) {
            cum += hist[k];
            if (cum >= NSEL) { eb = k; break; }
        }
        s_estar = base + eb * (1.0f / 16.0f);
    }
    __syncthreads();
    const float estar = s_estar;

    // Phase F: compact exact finalists
    for (int c = tid; c < R; c += 1024) {
        if (r_ev[c] >= estar) {
            int p = atomicAdd(&s_r2cnt, 1);
            if (p < RS2_CAP) { r2_idx[p] = r_idx[c]; r2_ev[p] = r_ev[c]; }
        }
    }
    __syncthreads();
    int R2 = s_r2cnt < RS2_CAP ? s_r2cnt : RS2_CAP;

    // Phase G: exact rank (value desc, index asc) + epilogue
    for (int jj = tid; jj < R2; jj += 1024) {
        float vj = r2_ev[jj];
        int   ij = r2_idx[jj];
        int rank = 0;
        for (int i = 0; i < R2; i++) {
            float vi = r2_ev[i];
            int   ii = r2_idx[i];
            if (vi > vj || (vi == vj && ii < ij)) rank++;
        }
        if (rank < NSEL) {
            int o = b * NSEL + rank;
            out[o] = vj;
            int q = ij / L_;
            int l = ij - q * L_;
            int label = 0;
#pragma unroll
            for (int t = 0; t < 80; t++)
                if (c_tok[t] == l) label = t;
            out[B_ * NSEL + o] = (float)label;
            const float* bb = bbox + (size_t)(b * Q_ + q) * 4;
            float cx = bb[0], cy = bb[1], w = bb[2], h = bb[3];
            float ih = tsz[2 * b + 0], iw = tsz[2 * b + 1];
            float* ob = out + 2 * B_ * NSEL + (size_t)o * 4;
            ob[0] = (cx - 0.5f * w) * iw;
            ob[1] = (cy - 0.5f * h) * ih;
            ob[2] = (cx + 0.5f * w) * iw;
            ob[3] = (cy + 0.5f * h) * ih;
        }
    }
}

// ---------------------------------------------------------------------------
extern "C" void kernel_launch(void* const* d_in, const int* in_sizes, int n_in,
                              void* d_out, int out_size) {
    const float* logits = (const float*)d_in[0];
    const float* bbox   = (const float*)d_in[1];
    const float* posmap = (const float*)d_in[2];
    const float* tsz    = (const float*)d_in[3];
    float* out = (float*)d_out;

    cudaFuncSetAttribute(gemm_kernel,
        cudaFuncAttributeMaxDynamicSharedMemorySize, NBUF * STG_BYTES);
    cudaFuncSetAttribute(final_kernel,
        cudaFuncAttributeMaxDynamicSharedMemorySize, CCAP * 12);

    zero_kernel<<<(M_ + 255) / 256, 256>>>();

    const int n4 = (M_ * T_) / 4;
    sigmoid_kernel<<<(n4 + 255) / 256, 256>>>(logits, n4);
    posconv_kernel<<<(L_ * T_ / 2 + 255) / 256, 256>>>(posmap, L_ * T_ / 2);

    dim3 ggrid(M_ / 128, (L_ + 127) / 128);   // 450 x 7
    gemm_kernel<<<ggrid, 256, NBUF * STG_BYTES>>>();

    dim3 sgrid(B_, 4);
    cmax_scan_kernel<<<sgrid, 256>>>();
    pick_kernel<<<1, B_>>>();
    dim3 cgrid(B_, 12);
    collect_kernel<<<cgrid, 256>>>();
    fixup_kernel<<<B_, 1024>>>();
    final_kernel<<<B_, 1024, CCAP * 12>>>(logits, bbox, tsz, out, posmap);
}

// round 14
// speedup vs baseline: 6.9239x; 1.0581x over previous
#include <cuda_runtime.h>
#include <cuda_fp16.h>
#include <cuda_bf16.h>
#include <cstdint>

// Problem constants
#define B_    64
#define Q_    900
#define T_    256
#define L_    769
#define LP    776            // padded row stride (16B-aligned rows of half)
#define NSEL  50
#define M_    (B_ * Q_)      // 57600
#define CCAP  8192
#define NSL   32             // ladder levels (0.25 steps, down to max-8)
#define CMINC 256u           // min chunk count above tau
#define RS2_CAP 2048
#define NCH   97             // 8-wide chunks per row (769 -> 97)
#define CPAD  104            // padded cmax row stride (16B aligned)

// Scratch (static device globals; allocation-free)
__device__ __nv_bfloat16  g_sig_b[(size_t)M_ * T_];    // bf16 sigmoid, 29.5 MB
__device__ __nv_bfloat16  g_pos_b[(size_t)L_ * T_];    // bf16 posmap
__device__ __half         g_prob_h[(size_t)M_ * LP];   // approx prob fp16, 89 MB
__device__ __half         g_cmax[(size_t)M_ * CPAD];   // per-chunk max, 12 MB
__device__ unsigned       g_maxbits[B_];               // per-batch max (uint bits)
__device__ unsigned       g_scnt[B_][NSL];             // chunk ladder counts
__device__ float          g_tau[B_];
__device__ int            g_ccnt[B_];
__device__ int            g_cand[B_][CCAP];            // candidate flat idx (q*L+l)
__device__ __half         g_cval[B_][CCAP];            // candidate approx value

__constant__ int c_tok[80] = {
    0, 9, 19, 25, 38, 49, 55, 63, 71, 78, 94, 109, 121, 137, 145, 152,
    158, 164, 172, 180, 186, 197, 204, 212, 222, 233, 244, 254, 260, 271,
    281, 288, 300, 314, 321, 336, 353, 366, 378, 394, 403, 416, 422, 429,
    437, 445, 452, 461, 469, 480, 489, 500, 509, 519, 527, 535, 542, 550,
    558, 573, 579, 594, 603, 608, 617, 625, 634, 645, 658, 670, 677, 687,
    694, 709, 716, 724, 731, 742, 755, 768};

// ---------------------------------------------------------------------------
// Helpers
// ---------------------------------------------------------------------------
__device__ __forceinline__ uint32_t smem_u32(const void* p) {
    uint32_t a;
    asm("{ .reg .u64 t; cvta.to.shared.u64 t, %1; cvt.u32.u64 %0, t; }" : "=r"(a) : "l"(p));
    return a;
}
__device__ __forceinline__ void cp_async16(uint32_t dst, const void* src, bool valid) {
    int sz = valid ? 16 : 0;   // src-size 0 => zero-fill 16B
    asm volatile("cp.async.cg.shared.global [%0], [%1], 16, %2;\n"
                 :: "r"(dst), "l"(src), "r"(sz));
}
__device__ __forceinline__ void cp_commit() { asm volatile("cp.async.commit_group;"); }
template <int N> __device__ __forceinline__ void cp_wait() {
    asm volatile("cp.async.wait_group %0;" :: "n"(N));
}
__device__ __forceinline__ void ldmatrix_x4(uint32_t* f, uint32_t addr) {
    asm volatile("ldmatrix.sync.aligned.m8n8.x4.shared.b16 {%0,%1,%2,%3}, [%4];"
                 : "=r"(f[0]), "=r"(f[1]), "=r"(f[2]), "=r"(f[3]) : "r"(addr));
}
__device__ __forceinline__ void mma_bf16(float* d, const uint32_t* a,
                                         uint32_t b0, uint32_t b1) {
    asm volatile(
        "mma.sync.aligned.m16n8k16.row.col.f32.bf16.bf16.f32 "
        "{%0,%1,%2,%3}, {%4,%5,%6,%7}, {%8,%9}, {%0,%1,%2,%3};"
        : "+f"(d[0]), "+f"(d[1]), "+f"(d[2]), "+f"(d[3])
        : "r"(a[0]), "r"(a[1]), "r"(a[2]), "r"(a[3]), "r"(b0), "r"(b1));
}
__device__ __forceinline__ float sigf(float x) {
    return 1.0f / (1.0f + __expf(-x));
}

// ---------------------------------------------------------------------------
// Kernel 0: reset counters only (prob/cmax pads are fully written by the GEMM)
// ---------------------------------------------------------------------------
__global__ void zero_kernel() {
    int i = blockIdx.x * blockDim.x + threadIdx.x;
    if (i < B_) { g_ccnt[i] = 0; g_maxbits[i] = 0u; }
    if (i < B_ * NSL) ((unsigned*)g_scnt)[i] = 0u;
}

// ---------------------------------------------------------------------------
// Kernel 1: sigmoid -> bf16 ; 1b: posmap -> bf16
// ---------------------------------------------------------------------------
__global__ void sigmoid_kernel(const float* __restrict__ x, int n4) {
    int i = blockIdx.x * blockDim.x + threadIdx.x;
    if (i < n4) {
        float4 v = reinterpret_cast<const float4*>(x)[i];
        __nv_bfloat162* o = reinterpret_cast<__nv_bfloat162*>(g_sig_b) + 2 * i;
        o[0] = __floats2bfloat162_rn(sigf(v.x), sigf(v.y));
        o[1] = __floats2bfloat162_rn(sigf(v.z), sigf(v.w));
    }
}

__global__ void posconv_kernel(const float* __restrict__ p, int n2) {
    int i = blockIdx.x * blockDim.x + threadIdx.x;
    if (i < n2) {
        float2 v = reinterpret_cast<const float2*>(p)[i];
        reinterpret_cast<__nv_bfloat162*>(g_pos_b)[i] = __floats2bfloat162_rn(v.x, v.y);
    }
}

// ---------------------------------------------------------------------------
// Kernel 2: bf16 mma.sync GEMM, CTA 128x128, BK=32, 6-buffer depth-3 pipeline.
// Epilogue v2: acc -> smem stage (buffers 2..5 are dead after the mainloop)
// -> one read-back pass emits coalesced 16B prob stores, per-chunk hmax
// (cmax), and the per-batch max. No shuffles/fmax chains in the acc loop.
// ---------------------------------------------------------------------------
#define STG_BYTES 16384
#define NSTG 8   // 256/32 k-stages
#define NBUF 6
#define SSTR 136  // stage row stride in halves (272B: 4-bank shift per row)

__global__ __launch_bounds__(256) void gemm_kernel() {
    extern __shared__ char dsm[];
    const uint32_t sbase = smem_u32(dsm);
    __shared__ unsigned s_mx0, s_mx1;
    const int tid  = threadIdx.x;
    const int wid  = tid >> 5;
    const int lane = tid & 31;
    const int wm   = wid & 3;      // 0..3 (m)
    const int wn   = wid >> 2;     // 0..1 (n)
    const int m0   = blockIdx.x * 128;
    const int l0   = blockIdx.y * 128;

    if (tid == 0) { s_mx0 = 0u; s_mx1 = 0u; }

    float acc[2][8][4];
#pragma unroll
    for (int a = 0; a < 2; a++)
#pragma unroll
        for (int b = 0; b < 8; b++)
#pragma unroll
            for (int c = 0; c < 4; c++) acc[a][b][c] = 0.0f;

    auto load_stage = [&](int s) {
        const uint32_t base = sbase + (s % NBUF) * STG_BYTES;
        const int k0 = s * 32;
#pragma unroll
        for (int t = 0; t < 2; t++) {              // A
            int ch = tid + t * 256;
            int r  = ch >> 2;
            int cc = ch & 3;
            int ph = cc ^ ((r >> 1) & 3);
            cp_async16(base + r * 64 + ph * 16,
                       g_sig_b + (size_t)(m0 + r) * T_ + k0 + cc * 8, true);
        }
#pragma unroll
        for (int t = 0; t < 2; t++) {              // B
            int ch = tid + t * 256;
            int r  = ch >> 2;
            int cc = ch & 3;
            int ph = cc ^ ((r >> 1) & 3);
            bool ok = (l0 + r) < L_;
            cp_async16(base + 8192 + r * 64 + ph * 16,
                       g_pos_b + (size_t)(l0 + r) * T_ + k0 + cc * 8, ok);
        }
        cp_commit();
    };

    load_stage(0);
    load_stage(1);
    load_stage(2);

    const int j  = lane >> 3;
    const int r8 = lane & 7;

    for (int s = 0; s < NSTG; s++) {
        if (s + 3 < NSTG)      { load_stage(s + 3); cp_wait<3>(); }
        else if (s + 2 < NSTG) cp_wait<2>();
        else if (s + 1 < NSTG) cp_wait<1>();
        else                   cp_wait<0>();
        __syncthreads();

        const uint32_t ab = sbase + (s % NBUF) * STG_BYTES;
        const uint32_t bb = ab + 8192;

#pragma unroll
        for (int ks = 0; ks < 2; ks++) {
            uint32_t Af[2][4];
#pragma unroll
            for (int mt = 0; mt < 2; mt++) {
                int rl = wm * 32 + mt * 16 + ((j & 1) << 3) + r8;
                int cc = ks * 2 + (j >> 1);
                int ph = cc ^ ((rl >> 1) & 3);
                ldmatrix_x4(Af[mt], ab + rl * 64 + ph * 16);
            }
#pragma unroll
            for (int np = 0; np < 4; np++) {
                uint32_t Bf[4];
                int nl = wn * 64 + np * 16 + ((j >> 1) << 3) + r8;
                int cc = ks * 2 + (j & 1);
                int ph = cc ^ ((nl >> 1) & 3);
                ldmatrix_x4(Bf, bb + nl * 64 + ph * 16);
#pragma unroll
                for (int mt = 0; mt < 2; mt++) {
                    mma_bf16(acc[mt][2 * np],     Af[mt], Bf[0], Bf[1]);
                    mma_bf16(acc[mt][2 * np + 1], Af[mt], Bf[2], Bf[3]);
                }
            }
        }
    }

    // ---- epilogue v2 ----
    // Buffers 2..5 (offset 32K..96K) are dead: last reads at stages 2..5, and
    // live stages 6/7 use buffers 0/1. Stage tile at +32K, cmax stage at +80K.
    __half* stage = reinterpret_cast<__half*>(dsm + 2 * STG_BYTES); // [128][SSTR]
    __half* cmst  = reinterpret_cast<__half*>(dsm + 5 * STG_BYTES); // [128][16]

    const int g  = lane >> 2;
    const int t4 = lane & 3;
    const int b0  = m0 / Q_;
    const int bnd = (b0 + 1) * Q_;

    // Phase 1: acc -> stage (conflict-free: 272B row stride = 4-bank shift)
#pragma unroll
    for (int mt = 0; mt < 2; mt++) {
        const int rl = wm * 32 + mt * 16 + g;
#pragma unroll
        for (int nt = 0; nt < 8; nt++) {
            int cl = wn * 64 + nt * 8 + t4 * 2;
            *reinterpret_cast<__half2*>(stage + rl * SSTR + cl) =
                __floats2half2_rn(acc[mt][nt][0], acc[mt][nt][1]);
            *reinterpret_cast<__half2*>(stage + (rl + 8) * SSTR + cl) =
                __floats2half2_rn(acc[mt][nt][2], acc[mt][nt][3]);
        }
    }
    __syncthreads();

    // Phase 2: read back one 8-col chunk per thread-iter:
    //   coalesced 16B prob store + chunk hmax (cmax) + batch max.
    float mx0 = 0.0f, mx1 = 0.0f;   // probs > 0; 0 is a safe identity
#pragma unroll
    for (int it = 0; it < 8; it++) {
        int ci = tid + it * 256;        // 0..2047
        int r  = ci >> 4;
        int cp = ci & 15;
        uint4 v = *reinterpret_cast<uint4*>(stage + r * SSTR + cp * 8);
        const __half2* hh = reinterpret_cast<const __half2*>(&v);
        __half2 m2 = __hmax2(__hmax2(hh[0], hh[1]), __hmax2(hh[2], hh[3]));
        __half  m  = __hmax(__low2half(m2), __high2half(m2));
        cmst[ci] = m;
        float fm = __half2float(m);
        if (m0 + r >= bnd) mx1 = fmaxf(mx1, fm); else mx0 = fmaxf(mx0, fm);
        int gcol = l0 + cp * 8;
        if (gcol < LP)      // by<6: always; by=6: only cp=0 (writes 768..775)
            *reinterpret_cast<uint4*>(g_prob_h + (size_t)(m0 + r) * LP + gcol) = v;
    }
#pragma unroll
    for (int o = 16; o > 0; o >>= 1) {
        mx0 = fmaxf(mx0, __shfl_xor_sync(0xFFFFFFFFu, mx0, o));
        mx1 = fmaxf(mx1, __shfl_xor_sync(0xFFFFFFFFu, mx1, o));
    }
    __syncthreads();   // cmst complete
    if (lane == 0) {
        atomicMax(&s_mx0, __float_as_uint(mx0));
        if (bnd < m0 + 128) atomicMax(&s_mx1, __float_as_uint(mx1));
    }
    // coalesced cmax writeout: thread -> (row = tid>>1, 8-chunk half = tid&1)
    {
        int r   = tid >> 1;
        int hf  = tid & 1;
        int chb = (l0 >> 3) + hf * 8;
        if (chb + 8 <= CPAD)
            *reinterpret_cast<uint4*>(g_cmax + (size_t)(m0 + r) * CPAD + chb) =
                *reinterpret_cast<uint4*>(cmst + r * 16 + hf * 8);
    }
    __syncthreads();
    if (tid == 0) {
        atomicMax(&g_maxbits[b0], s_mx0);
        if (bnd < m0 + 128) atomicMax(&g_maxbits[b0 + 1], s_mx1);
    }
}

// ---------------------------------------------------------------------------
// Kernel 3: exact ladder over chunk-maxes (12MB). grid (64, 4).
// ---------------------------------------------------------------------------
__global__ __launch_bounds__(256) void cmax_scan_kernel() {
    const int b    = blockIdx.x;
    const int part = blockIdx.y;
    const int tid  = threadIdx.x;
    const float mx = __uint_as_float(g_maxbits[b]);
    const float lo = mx - 8.0f;
    __shared__ unsigned h[NSL];
    if (tid < NSL) h[tid] = 0u;
    __syncthreads();

    const int r0 = part * 225;                  // 4 x 225 = 900 rows
    const int n  = 225 * (CPAD / 8);            // uint4 per part (13 per row)
    for (int i = tid; i < n; i += 256) {
        int r  = i / 13;
        int c4 = i - r * 13;
        const uint4 v = reinterpret_cast<const uint4*>(
            g_cmax + (size_t)(b * Q_ + r0 + r) * CPAD)[c4];
        const __half2* hh = reinterpret_cast<const __half2*>(&v);
#pragma unroll
        for (int e = 0; e < 4; e++) {
            float2 f2 = __half22float2(hh[e]);
            float fs[2] = {f2.x, f2.y};
#pragma unroll
            for (int u = 0; u < 2; u++) {
                float f = fs[u];
                if (f > lo) {
                    int k = (int)((mx - f) * 4.0f);
                    k = k < 0 ? 0 : (k > NSL - 1 ? NSL - 1 : k);
                    atomicAdd(&h[k], 1u);
                }
            }
        }
    }
    __syncthreads();
    if (tid < NSL && h[tid]) atomicAdd(&g_scnt[b][tid], h[tid]);
}

// ---------------------------------------------------------------------------
// Kernel 3b: tau = level where cumulative chunk count >= CMINC
// ---------------------------------------------------------------------------
__global__ void pick_kernel() {
    int b = threadIdx.x;
    if (b < B_) {
        float mx = __uint_as_float(g_maxbits[b]);
        float tau = mx - 8.0f;
        unsigned cum = 0;
        for (int k = 0; k < NSL; k++) {
            cum += g_scnt[b][k];
            if (cum >= CMINC) { tau = mx - 0.25f * (k + 1); break; }
        }
        g_tau[b] = tau;
    }
}

// ---------------------------------------------------------------------------
// Kernel 4: cmax-gated collect. grid (64, 12).
// ---------------------------------------------------------------------------
#define ROWS_PER_PART 75

__global__ __launch_bounds__(256) void collect_kernel() {
    const int b    = blockIdx.x;
    const int part = blockIdx.y;
    const __half tau = __float2half_rd(g_tau[b]);

    const int n = ROWS_PER_PART * NCH;
    for (int i = threadIdx.x; i < n; i += 256) {
        int r = i / NCH;
        int c = i - r * NCH;
        int q = part * ROWS_PER_PART + r;
        __half cm = g_cmax[(size_t)(b * Q_ + q) * CPAD + c];
        if (__hge(cm, tau)) {
            const uint4 v = reinterpret_cast<const uint4*>(
                g_prob_h + (size_t)(b * Q_ + q) * LP)[c];
            const __half2* hh = reinterpret_cast<const __half2*>(&v);
#pragma unroll
            for (int e = 0; e < 4; e++) {
                __half lo = __low2half(hh[e]), hi = __high2half(hh[e]);
                if (__hge(lo, tau)) {
                    int p = atomicAdd(&g_ccnt[b], 1);
                    if (p < CCAP) {
                        g_cand[b][p] = q * L_ + c * 8 + e * 2;
                        g_cval[b][p] = lo;
                    }
                }
                if (__hge(hi, tau)) {
                    int p = atomicAdd(&g_ccnt[b], 1);
                    if (p < CCAP) {
                        g_cand[b][p] = q * L_ + c * 8 + e * 2 + 1;
                        g_cval[b][p] = hi;
                    }
                }
            }
        }
    }
}

// ---------------------------------------------------------------------------
// Kernel 4b: fixup loop — re-collect until 64 <= K <= CCAP (normally noop).
// ---------------------------------------------------------------------------
__global__ __launch_bounds__(1024) void fixup_kernel() {
    const int b   = blockIdx.x;
    const int tid = threadIdx.x;
    __shared__ float s_tau;
    for (int iter = 0; iter < 8; iter++) {
        __syncthreads();
        int K = g_ccnt[b];
        if (K >= 64 && K <= CCAP) return;
        if (tid == 0) {
            float t = g_tau[b] + (K > CCAP ? 0.25f : -2.0f);
            g_tau[b] = t;
            g_ccnt[b] = 0;
            s_tau = t;
        }
        __syncthreads();
        const __half htau = __float2half_rd(s_tau);
        for (int i = tid; i < Q_ * L_; i += 1024) {
            int q = i / L_;
            int l = i - q * L_;
            __half v = g_prob_h[(size_t)(b * Q_ + q) * LP + l];
            if (__hge(v, htau)) {
                int p = atomicAdd(&g_ccnt[b], 1);
                if (p < CCAP) { g_cand[b][p] = i; g_cval[b][p] = v; }
            }
        }
    }
}

// ---------------------------------------------------------------------------
// Kernel 5: approx-select + fp32 rescore + exact-select + rank + epilogue.
// ---------------------------------------------------------------------------
__global__ __launch_bounds__(1024) void final_kernel(
    const float* __restrict__ logits, const float* __restrict__ bbox,
    const float* __restrict__ tsz, float* __restrict__ out,
    const float* __restrict__ posmap)
{
    extern __shared__ char fsm[];
    float* s_av  = reinterpret_cast<float*>(fsm);                 // [CCAP]
    int*   s_idx = reinterpret_cast<int*>(fsm + CCAP * 4);        // [CCAP]
    int*   r_idx = reinterpret_cast<int*>(fsm + CCAP * 8);        // [CCAP]
    float* r_ev  = s_av;                                          // alias
    __shared__ unsigned hist[128];
    __shared__ int   s_rcnt, s_r2cnt;
    __shared__ float s_tr, s_estar;
    __shared__ int   r2_idx[RS2_CAP];
    __shared__ float r2_ev[RS2_CAP];

    const int b    = blockIdx.x;
    const int tid  = threadIdx.x;
    const int wid  = tid >> 5;
    const int lane = tid & 31;
    const float tau = g_tau[b];

    int K = g_ccnt[b];
    if (K > CCAP) K = CCAP;

    // Phase A: load candidates + approx histogram over [tau, tau+8)
    for (int i = tid; i < 128; i += 1024) hist[i] = 0u;
    if (tid == 0) { s_rcnt = 0; s_r2cnt = 0; }
    __syncthreads();
    for (int c = tid; c < K; c += 1024) {
        float v = __half2float(g_cval[b][c]);
        s_av[c]  = v;
        s_idx[c] = g_cand[b][c];
        int bin = (int)((v - tau) * 16.0f);
        bin = bin < 0 ? 0 : (bin > 127 ? 127 : bin);
        atomicAdd(&hist[bin], 1u);
    }
    __syncthreads();

    // Phase B: approx 50th edge; rescore threshold = edge - 1.0
    if (tid == 0) {
        unsigned cum = 0;
        int bstar = 0;
        for (int k = 127; k >= 0; k--) {
            cum += hist[k];
            if (cum >= NSEL) { bstar = k; break; }
        }
        s_tr = tau + bstar * (1.0f / 16.0f) - 1.0f;
    }
    __syncthreads();
    const float tr = s_tr;

    // Phase C: compact rescore set
    for (int c = tid; c < K; c += 1024) {
        if (s_av[c] >= tr) {
            int p = atomicAdd(&s_rcnt, 1);
            if (p < CCAP) r_idx[p] = s_idx[c];
        }
    }
    __syncthreads();
    int R = s_rcnt < CCAP ? s_rcnt : CCAP;

    // Phase D: fp32 rescore (one warp per candidate)
    for (int c = wid; c < R; c += 32) {
        int idx = r_idx[c];
        int q = idx / L_;
        int l = idx - q * L_;
        const float4* a = reinterpret_cast<const float4*>(
            logits + (size_t)(b * Q_ + q) * T_ + lane * 8);
        const float4* p = reinterpret_cast<const float4*>(
            posmap + (size_t)l * T_ + lane * 8);
        float4 a0 = a[0], a1 = a[1], p0 = p[0], p1 = p[1];
        float s = sigf(a0.x) * p0.x + sigf(a0.y) * p0.y
                + sigf(a0.z) * p0.z + sigf(a0.w) * p0.w
                + sigf(a1.x) * p1.x + sigf(a1.y) * p1.y
                + sigf(a1.z) * p1.z + sigf(a1.w) * p1.w;
#pragma unroll
        for (int o = 16; o > 0; o >>= 1) s += __shfl_xor_sync(0xFFFFFFFFu, s, o);
        if (lane == 0) r_ev[c] = s;
    }
    __syncthreads();

    // Phase E: exact histogram over [tr-1, tr+7); exact 50th edge
    for (int i = tid; i < 128; i += 1024) hist[i] = 0u;
    __syncthreads();
    const float base = tr - 1.0f;
    for (int c = tid; c < R; c += 1024) {
        int bin = (int)((r_ev[c] - base) * 16.0f);
        bin = bin < 0 ? 0 : (bin > 127 ? 127 : bin);
        atomicAdd(&hist[bin], 1u);
    }
    __syncthreads();
    if (tid == 0) {
        unsigned cum = 0;
        int eb = 0;
        for (int k = 127; k >= 0; k--) {
            cum += hist[k];
            if (cum >= NSEL) { eb = k; break; }
        }
        s_estar = base + eb * (1.0f / 16.0f);
    }
    __syncthreads();
    const float estar = s_estar;

    // Phase F: compact exact finalists
    for (int c = tid; c < R; c += 1024) {
        if (r_ev[c] >= estar) {
            int p = atomicAdd(&s_r2cnt, 1);
            if (p < RS2_CAP) { r2_idx[p] = r_idx[c]; r2_ev[p] = r_ev[c]; }
        }
    }
    __syncthreads();
    int R2 = s_r2cnt < RS2_CAP ? s_r2cnt : RS2_CAP;

    // Phase G: exact rank (value desc, index asc) + epilogue
    for (int jj = tid; jj < R2; jj += 1024) {
        float vj = r2_ev[jj];
        int   ij = r2_idx[jj];
        int rank = 0;
        for (int i = 0; i < R2; i++) {
            float vi = r2_ev[i];
            int   ii = r2_idx[i];
            if (vi > vj || (vi == vj && ii < ij)) rank++;
        }
        if (rank < NSEL) {
            int o = b * NSEL + rank;
            out[o] = vj;
            int q = ij / L_;
            int l = ij - q * L_;
            int label = 0;
#pragma unroll
            for (int t = 0; t < 80; t++)
                if (c_tok[t] == l) label = t;
            out[B_ * NSEL + o] = (float)label;
            const float* bb = bbox + (size_t)(b * Q_ + q) * 4;
            float cx = bb[0], cy = bb[1], w = bb[2], h = bb[3];
            float ih = tsz[2 * b + 0], iw = tsz[2 * b + 1];
            float* ob = out + 2 * B_ * NSEL + (size_t)o * 4;
            ob[0] = (cx - 0.5f * w) * iw;
            ob[1] = (cy - 0.5f * h) * ih;
            ob[2] = (cx + 0.5f * w) * iw;
            ob[3] = (cy + 0.5f * h) * ih;
        }
    }
}

// ---------------------------------------------------------------------------
extern "C" void kernel_launch(void* const* d_in, const int* in_sizes, int n_in,
                              void* d_out, int out_size) {
    const float* logits = (const float*)d_in[0];
    const float* bbox   = (const float*)d_in[1];
    const float* posmap = (const float*)d_in[2];
    const float* tsz    = (const float*)d_in[3];
    float* out = (float*)d_out;

    cudaFuncSetAttribute(gemm_kernel,
        cudaFuncAttributeMaxDynamicSharedMemorySize, NBUF * STG_BYTES);
    cudaFuncSetAttribute(final_kernel,
        cudaFuncAttributeMaxDynamicSharedMemorySize, CCAP * 12);

    zero_kernel<<<2, 1024>>>();

    const int n4 = (M_ * T_) / 4;
    sigmoid_kernel<<<(n4 + 255) / 256, 256>>>(logits, n4);
    posconv_kernel<<<(L_ * T_ / 2 + 255) / 256, 256>>>(posmap, L_ * T_ / 2);

    dim3 ggrid(M_ / 128, (L_ + 127) / 128);   // 450 x 7
    gemm_kernel<<<ggrid, 256, NBUF * STG_BYTES>>>();

    dim3 sgrid(B_, 4);
    cmax_scan_kernel<<<sgrid, 256>>>();
    pick_kernel<<<1, B_>>>();
    dim3 cgrid(B_, 12);
    collect_kernel<<<cgrid, 256>>>();
    fixup_kernel<<<B_, 1024>>>();
    final_kernel<<<B_, 1024, CCAP * 12>>>(logits, bbox, tsz, out, posmap);
}

// round 15
// speedup vs baseline: 6.9260x; 1.0003x over previous
#include <cuda_runtime.h>
#include <cuda_fp16.h>
#include <cuda_bf16.h>
#include <cstdint>

// Problem constants
#define B_    64
#define Q_    900
#define T_    256
#define L_    769
#define LP    776            // padded row stride (16B-aligned rows of half)
#define NSEL  50
#define M_    (B_ * Q_)      // 57600
#define CCAP  8192
#define NSL   32             // ladder levels (0.25 steps, down to max-8)
#define CMINC 256u           // min chunk count above tau
#define RS2_CAP 2048
#define NCH   97             // 8-wide chunks per row (769 -> 97)
#define CPAD  104            // padded cmax row stride (16B aligned)

// Scratch (static device globals; allocation-free)
__device__ __nv_bfloat16  g_sig_b[(size_t)M_ * T_];    // bf16 sigmoid, 29.5 MB
__device__ __nv_bfloat16  g_pos_b[(size_t)L_ * T_];    // bf16 posmap
__device__ __half         g_prob_h[(size_t)M_ * LP];   // approx prob fp16, 89 MB
__device__ __half         g_cmax[(size_t)M_ * CPAD];   // per-chunk max, 12 MB
__device__ unsigned       g_maxbits[B_];               // per-batch max (uint bits)
__device__ unsigned       g_scnt[B_][NSL];             // chunk ladder counts
__device__ float          g_tau[B_];
__device__ int            g_ccnt[B_];
__device__ int            g_cand[B_][CCAP];            // candidate flat idx (q*L+l)
__device__ __half         g_cval[B_][CCAP];            // candidate approx value

__constant__ int c_tok[80] = {
    0, 9, 19, 25, 38, 49, 55, 63, 71, 78, 94, 109, 121, 137, 145, 152,
    158, 164, 172, 180, 186, 197, 204, 212, 222, 233, 244, 254, 260, 271,
    281, 288, 300, 314, 321, 336, 353, 366, 378, 394, 403, 416, 422, 429,
    437, 445, 452, 461, 469, 480, 489, 500, 509, 519, 527, 535, 542, 550,
    558, 573, 579, 594, 603, 608, 617, 625, 634, 645, 658, 670, 677, 687,
    694, 709, 716, 724, 731, 742, 755, 768};

// ---------------------------------------------------------------------------
// Helpers
// ---------------------------------------------------------------------------
__device__ __forceinline__ uint32_t smem_u32(const void* p) {
    uint32_t a;
    asm("{ .reg .u64 t; cvta.to.shared.u64 t, %1; cvt.u32.u64 %0, t; }" : "=r"(a) : "l"(p));
    return a;
}
__device__ __forceinline__ void cp_async16(uint32_t dst, const void* src, bool valid) {
    int sz = valid ? 16 : 0;   // src-size 0 => zero-fill 16B
    asm volatile("cp.async.cg.shared.global [%0], [%1], 16, %2;\n"
                 :: "r"(dst), "l"(src), "r"(sz));
}
__device__ __forceinline__ void cp_commit() { asm volatile("cp.async.commit_group;"); }
template <int N> __device__ __forceinline__ void cp_wait() {
    asm volatile("cp.async.wait_group %0;" :: "n"(N));
}
__device__ __forceinline__ void ldmatrix_x4(uint32_t* f, uint32_t addr) {
    asm volatile("ldmatrix.sync.aligned.m8n8.x4.shared.b16 {%0,%1,%2,%3}, [%4];"
                 : "=r"(f[0]), "=r"(f[1]), "=r"(f[2]), "=r"(f[3]) : "r"(addr));
}
__device__ __forceinline__ void mma_bf16(float* d, const uint32_t* a,
                                         uint32_t b0, uint32_t b1) {
    asm volatile(
        "mma.sync.aligned.m16n8k16.row.col.f32.bf16.bf16.f32 "
        "{%0,%1,%2,%3}, {%4,%5,%6,%7}, {%8,%9}, {%0,%1,%2,%3};"
        : "+f"(d[0]), "+f"(d[1]), "+f"(d[2]), "+f"(d[3])
        : "r"(a[0]), "r"(a[1]), "r"(a[2]), "r"(a[3]), "r"(b0), "r"(b1));
}
__device__ __forceinline__ float sigf(float x) {
    return 1.0f / (1.0f + __expf(-x));
}

// ---------------------------------------------------------------------------
// Kernel 0: reset counters only (prob/cmax pads are fully written by the GEMM)
// ---------------------------------------------------------------------------
__global__ void zero_kernel() {
    int i = blockIdx.x * blockDim.x + threadIdx.x;
    if (i < B_) { g_ccnt[i] = 0; g_maxbits[i] = 0u; }
    if (i < B_ * NSL) ((unsigned*)g_scnt)[i] = 0u;
}

// ---------------------------------------------------------------------------
// Kernel 1: sigmoid -> bf16 ; 1b: posmap -> bf16
// ---------------------------------------------------------------------------
__global__ void sigmoid_kernel(const float* __restrict__ x, int n4) {
    int i = blockIdx.x * blockDim.x + threadIdx.x;
    if (i < n4) {
        float4 v = reinterpret_cast<const float4*>(x)[i];
        __nv_bfloat162* o = reinterpret_cast<__nv_bfloat162*>(g_sig_b) + 2 * i;
        o[0] = __floats2bfloat162_rn(sigf(v.x), sigf(v.y));
        o[1] = __floats2bfloat162_rn(sigf(v.z), sigf(v.w));
    }
}

__global__ void posconv_kernel(const float* __restrict__ p, int n2) {
    int i = blockIdx.x * blockDim.x + threadIdx.x;
    if (i < n2) {
        float2 v = reinterpret_cast<const float2*>(p)[i];
        reinterpret_cast<__nv_bfloat162*>(g_pos_b)[i] = __floats2bfloat162_rn(v.x, v.y);
    }
}

// ---------------------------------------------------------------------------
// Kernel 2: bf16 mma.sync GEMM, CTA 128x128, BK=32, 6-buffer depth-3 pipeline.
// Mainloop v2: per ks-halfstage, ALL 6 ldmatrix.x4 (Af[2]+Bf[4], independent)
// are issued before a burst of 16 back-to-back MMAs — overlapped LDSM latency.
// Epilogue: smem-staged coalesced prob/cmax writeout + batch max.
// ---------------------------------------------------------------------------
#define STG_BYTES 16384
#define NSTG 8   // 256/32 k-stages
#define NBUF 6
#define SSTR 136  // stage row stride in halves (272B: 4-bank shift per row)

__global__ __launch_bounds__(256) void gemm_kernel() {
    extern __shared__ char dsm[];
    const uint32_t sbase = smem_u32(dsm);
    __shared__ unsigned s_mx0, s_mx1;
    const int tid  = threadIdx.x;
    const int wid  = tid >> 5;
    const int lane = tid & 31;
    const int wm   = wid & 3;      // 0..3 (m)
    const int wn   = wid >> 2;     // 0..1 (n)
    const int m0   = blockIdx.x * 128;
    const int l0   = blockIdx.y * 128;

    if (tid == 0) { s_mx0 = 0u; s_mx1 = 0u; }

    float acc[2][8][4];
#pragma unroll
    for (int a = 0; a < 2; a++)
#pragma unroll
        for (int b = 0; b < 8; b++)
#pragma unroll
            for (int c = 0; c < 4; c++) acc[a][b][c] = 0.0f;

    auto load_stage = [&](int s) {
        const uint32_t base = sbase + (s % NBUF) * STG_BYTES;
        const int k0 = s * 32;
#pragma unroll
        for (int t = 0; t < 2; t++) {              // A
            int ch = tid + t * 256;
            int r  = ch >> 2;
            int cc = ch & 3;
            int ph = cc ^ ((r >> 1) & 3);
            cp_async16(base + r * 64 + ph * 16,
                       g_sig_b + (size_t)(m0 + r) * T_ + k0 + cc * 8, true);
        }
#pragma unroll
        for (int t = 0; t < 2; t++) {              // B
            int ch = tid + t * 256;
            int r  = ch >> 2;
            int cc = ch & 3;
            int ph = cc ^ ((r >> 1) & 3);
            bool ok = (l0 + r) < L_;
            cp_async16(base + 8192 + r * 64 + ph * 16,
                       g_pos_b + (size_t)(l0 + r) * T_ + k0 + cc * 8, ok);
        }
        cp_commit();
    };

    load_stage(0);
    load_stage(1);
    load_stage(2);

    const int j  = lane >> 3;
    const int r8 = lane & 7;

    for (int s = 0; s < NSTG; s++) {
        if (s + 3 < NSTG)      { load_stage(s + 3); cp_wait<3>(); }
        else if (s + 2 < NSTG) cp_wait<2>();
        else if (s + 1 < NSTG) cp_wait<1>();
        else                   cp_wait<0>();
        __syncthreads();

        const uint32_t ab = sbase + (s % NBUF) * STG_BYTES;
        const uint32_t bb = ab + 8192;

#pragma unroll
        for (int ks = 0; ks < 2; ks++) {
            // Issue ALL fragment loads first (6 independent LDSM.x4)
            uint32_t Af[2][4];
            uint32_t Bf[4][4];
#pragma unroll
            for (int mt = 0; mt < 2; mt++) {
                int rl = wm * 32 + mt * 16 + ((j & 1) << 3) + r8;
                int cc = ks * 2 + (j >> 1);
                int ph = cc ^ ((rl >> 1) & 3);
                ldmatrix_x4(Af[mt], ab + rl * 64 + ph * 16);
            }
#pragma unroll
            for (int np = 0; np < 4; np++) {
                int nl = wn * 64 + np * 16 + ((j >> 1) << 3) + r8;
                int cc = ks * 2 + (j & 1);
                int ph = cc ^ ((nl >> 1) & 3);
                ldmatrix_x4(Bf[np], bb + nl * 64 + ph * 16);
            }
            // Pure MMA burst: 16 back-to-back, all independent accumulators
#pragma unroll
            for (int np = 0; np < 4; np++) {
#pragma unroll
                for (int mt = 0; mt < 2; mt++) {
                    mma_bf16(acc[mt][2 * np],     Af[mt], Bf[np][0], Bf[np][1]);
                    mma_bf16(acc[mt][2 * np + 1], Af[mt], Bf[np][2], Bf[np][3]);
                }
            }
        }
    }

    // ---- epilogue: smem-staged coalesced writeout ----
    // Buffers 2..5 dead after mainloop (live stages 6/7 use buffers 0/1).
    __half* stage = reinterpret_cast<__half*>(dsm + 2 * STG_BYTES); // [128][SSTR]
    __half* cmst  = reinterpret_cast<__half*>(dsm + 5 * STG_BYTES); // [128][16]

    const int g  = lane >> 2;
    const int t4 = lane & 3;
    const int b0  = m0 / Q_;
    const int bnd = (b0 + 1) * Q_;

    // Phase 1: acc -> stage (272B row stride: conflict-free)
#pragma unroll
    for (int mt = 0; mt < 2; mt++) {
        const int rl = wm * 32 + mt * 16 + g;
#pragma unroll
        for (int nt = 0; nt < 8; nt++) {
            int cl = wn * 64 + nt * 8 + t4 * 2;
            *reinterpret_cast<__half2*>(stage + rl * SSTR + cl) =
                __floats2half2_rn(acc[mt][nt][0], acc[mt][nt][1]);
            *reinterpret_cast<__half2*>(stage + (rl + 8) * SSTR + cl) =
                __floats2half2_rn(acc[mt][nt][2], acc[mt][nt][3]);
        }
    }
    __syncthreads();

    // Phase 2: per 8-col chunk: coalesced 16B prob store + hmax + batch max
    float mx0 = 0.0f, mx1 = 0.0f;   // probs > 0; 0 is a safe identity
#pragma unroll
    for (int it = 0; it < 8; it++) {
        int ci = tid + it * 256;        // 0..2047
        int r  = ci >> 4;
        int cp = ci & 15;
        uint4 v = *reinterpret_cast<uint4*>(stage + r * SSTR + cp * 8);
        const __half2* hh = reinterpret_cast<const __half2*>(&v);
        __half2 m2 = __hmax2(__hmax2(hh[0], hh[1]), __hmax2(hh[2], hh[3]));
        __half  m  = __hmax(__low2half(m2), __high2half(m2));
        cmst[ci] = m;
        float fm = __half2float(m);
        if (m0 + r >= bnd) mx1 = fmaxf(mx1, fm); else mx0 = fmaxf(mx0, fm);
        int gcol = l0 + cp * 8;
        if (gcol < LP)      // by<6: always; by=6: only cp=0 (writes 768..775)
            *reinterpret_cast<uint4*>(g_prob_h + (size_t)(m0 + r) * LP + gcol) = v;
    }
#pragma unroll
    for (int o = 16; o > 0; o >>= 1) {
        mx0 = fmaxf(mx0, __shfl_xor_sync(0xFFFFFFFFu, mx0, o));
        mx1 = fmaxf(mx1, __shfl_xor_sync(0xFFFFFFFFu, mx1, o));
    }
    __syncthreads();   // cmst complete
    if (lane == 0) {
        atomicMax(&s_mx0, __float_as_uint(mx0));
        if (bnd < m0 + 128) atomicMax(&s_mx1, __float_as_uint(mx1));
    }
    // coalesced cmax writeout
    {
        int r   = tid >> 1;
        int hf  = tid & 1;
        int chb = (l0 >> 3) + hf * 8;
        if (chb + 8 <= CPAD)
            *reinterpret_cast<uint4*>(g_cmax + (size_t)(m0 + r) * CPAD + chb) =
                *reinterpret_cast<uint4*>(cmst + r * 16 + hf * 8);
    }
    __syncthreads();
    if (tid == 0) {
        atomicMax(&g_maxbits[b0], s_mx0);
        if (bnd < m0 + 128) atomicMax(&g_maxbits[b0 + 1], s_mx1);
    }
}

// ---------------------------------------------------------------------------
// Kernel 3: exact ladder over chunk-maxes (12MB). grid (64, 4).
// ---------------------------------------------------------------------------
__global__ __launch_bounds__(256) void cmax_scan_kernel() {
    const int b    = blockIdx.x;
    const int part = blockIdx.y;
    const int tid  = threadIdx.x;
    const float mx = __uint_as_float(g_maxbits[b]);
    const float lo = mx - 8.0f;
    __shared__ unsigned h[NSL];
    if (tid < NSL) h[tid] = 0u;
    __syncthreads();

    const int r0 = part * 225;                  // 4 x 225 = 900 rows
    const int n  = 225 * (CPAD / 8);            // uint4 per part (13 per row)
    for (int i = tid; i < n; i += 256) {
        int r  = i / 13;
        int c4 = i - r * 13;
        const uint4 v = reinterpret_cast<const uint4*>(
            g_cmax + (size_t)(b * Q_ + r0 + r) * CPAD)[c4];
        const __half2* hh = reinterpret_cast<const __half2*>(&v);
#pragma unroll
        for (int e = 0; e < 4; e++) {
            float2 f2 = __half22float2(hh[e]);
            float fs[2] = {f2.x, f2.y};
#pragma unroll
            for (int u = 0; u < 2; u++) {
                float f = fs[u];
                if (f > lo) {
                    int k = (int)((mx - f) * 4.0f);
                    k = k < 0 ? 0 : (k > NSL - 1 ? NSL - 1 : k);
                    atomicAdd(&h[k], 1u);
                }
            }
        }
    }
    __syncthreads();
    if (tid < NSL && h[tid]) atomicAdd(&g_scnt[b][tid], h[tid]);
}

// ---------------------------------------------------------------------------
// Kernel 4: cmax-gated collect (computes tau in-block from the ladder).
// grid (64, 12).
// ---------------------------------------------------------------------------
#define ROWS_PER_PART 75

__global__ __launch_bounds__(256) void collect_kernel() {
    const int b    = blockIdx.x;
    const int part = blockIdx.y;
    __shared__ float s_tauv;
    if (threadIdx.x == 0) {
        float mx = __uint_as_float(g_maxbits[b]);
        float t = mx - 8.0f;
        unsigned cum = 0;
#pragma unroll
        for (int k = 0; k < NSL; k++) {
            cum += g_scnt[b][k];
            if (cum >= CMINC) { t = mx - 0.25f * (k + 1); break; }
        }
        g_tau[b] = t;    // redundant identical writes from 12 blocks: benign
        s_tauv = t;
    }
    __syncthreads();
    const __half tau = __float2half_rd(s_tauv);

    const int n = ROWS_PER_PART * NCH;
    for (int i = threadIdx.x; i < n; i += 256) {
        int r = i / NCH;
        int c = i - r * NCH;
        int q = part * ROWS_PER_PART + r;
        __half cm = g_cmax[(size_t)(b * Q_ + q) * CPAD + c];
        if (__hge(cm, tau)) {
            const uint4 v = reinterpret_cast<const uint4*>(
                g_prob_h + (size_t)(b * Q_ + q) * LP)[c];
            const __half2* hh = reinterpret_cast<const __half2*>(&v);
#pragma unroll
            for (int e = 0; e < 4; e++) {
                __half lo = __low2half(hh[e]), hi = __high2half(hh[e]);
                if (__hge(lo, tau)) {
                    int p = atomicAdd(&g_ccnt[b], 1);
                    if (p < CCAP) {
                        g_cand[b][p] = q * L_ + c * 8 + e * 2;
                        g_cval[b][p] = lo;
                    }
                }
                if (__hge(hi, tau)) {
                    int p = atomicAdd(&g_ccnt[b], 1);
                    if (p < CCAP) {
                        g_cand[b][p] = q * L_ + c * 8 + e * 2 + 1;
                        g_cval[b][p] = hi;
                    }
                }
            }
        }
    }
}

// ---------------------------------------------------------------------------
// Kernel 4b: fixup loop — re-collect until 64 <= K <= CCAP (normally noop).
// ---------------------------------------------------------------------------
__global__ __launch_bounds__(1024) void fixup_kernel() {
    const int b   = blockIdx.x;
    const int tid = threadIdx.x;
    __shared__ float s_tau;
    for (int iter = 0; iter < 8; iter++) {
        __syncthreads();
        int K = g_ccnt[b];
        if (K >= 64 && K <= CCAP) return;
        if (tid == 0) {
            float t = g_tau[b] + (K > CCAP ? 0.25f : -2.0f);
            g_tau[b] = t;
            g_ccnt[b] = 0;
            s_tau = t;
        }
        __syncthreads();
        const __half htau = __float2half_rd(s_tau);
        for (int i = tid; i < Q_ * L_; i += 1024) {
            int q = i / L_;
            int l = i - q * L_;
            __half v = g_prob_h[(size_t)(b * Q_ + q) * LP + l];
            if (__hge(v, htau)) {
                int p = atomicAdd(&g_ccnt[b], 1);
                if (p < CCAP) { g_cand[b][p] = i; g_cval[b][p] = v; }
            }
        }
    }
}

// ---------------------------------------------------------------------------
// Kernel 5: approx-select + fp32 rescore + exact-select + rank + epilogue.
// ---------------------------------------------------------------------------
__global__ __launch_bounds__(1024) void final_kernel(
    const float* __restrict__ logits, const float* __restrict__ bbox,
    const float* __restrict__ tsz, float* __restrict__ out,
    const float* __restrict__ posmap)
{
    extern __shared__ char fsm[];
    float* s_av  = reinterpret_cast<float*>(fsm);                 // [CCAP]
    int*   s_idx = reinterpret_cast<int*>(fsm + CCAP * 4);        // [CCAP]
    int*   r_idx = reinterpret_cast<int*>(fsm + CCAP * 8);        // [CCAP]
    float* r_ev  = s_av;                                          // alias
    __shared__ unsigned hist[128];
    __shared__ int   s_rcnt, s_r2cnt;
    __shared__ float s_tr, s_estar;
    __shared__ int   r2_idx[RS2_CAP];
    __shared__ float r2_ev[RS2_CAP];

    const int b    = blockIdx.x;
    const int tid  = threadIdx.x;
    const int wid  = tid >> 5;
    const int lane = tid & 31;
    const float tau = g_tau[b];

    int K = g_ccnt[b];
    if (K > CCAP) K = CCAP;

    // Phase A: load candidates + approx histogram over [tau, tau+8)
    for (int i = tid; i < 128; i += 1024) hist[i] = 0u;
    if (tid == 0) { s_rcnt = 0; s_r2cnt = 0; }
    __syncthreads();
    for (int c = tid; c < K; c += 1024) {
        float v = __half2float(g_cval[b][c]);
        s_av[c]  = v;
        s_idx[c] = g_cand[b][c];
        int bin = (int)((v - tau) * 16.0f);
        bin = bin < 0 ? 0 : (bin > 127 ? 127 : bin);
        atomicAdd(&hist[bin], 1u);
    }
    __syncthreads();

    // Phase B: approx 50th edge; rescore threshold = edge - 1.0
    if (tid == 0) {
        unsigned cum = 0;
        int bstar = 0;
        for (int k = 127; k >= 0; k--) {
            cum += hist[k];
            if (cum >= NSEL) { bstar = k; break; }
        }
        s_tr = tau + bstar * (1.0f / 16.0f) - 1.0f;
    }
    __syncthreads();
    const float tr = s_tr;

    // Phase C: compact rescore set
    for (int c = tid; c < K; c += 1024) {
        if (s_av[c] >= tr) {
            int p = atomicAdd(&s_rcnt, 1);
            if (p < CCAP) r_idx[p] = s_idx[c];
        }
    }
    __syncthreads();
    int R = s_rcnt < CCAP ? s_rcnt : CCAP;

    // Phase D: fp32 rescore (one warp per candidate)
    for (int c = wid; c < R; c += 32) {
        int idx = r_idx[c];
        int q = idx / L_;
        int l = idx - q * L_;
        const float4* a = reinterpret_cast<const float4*>(
            logits + (size_t)(b * Q_ + q) * T_ + lane * 8);
        const float4* p = reinterpret_cast<const float4*>(
            posmap + (size_t)l * T_ + lane * 8);
        float4 a0 = a[0], a1 = a[1], p0 = p[0], p1 = p[1];
        float s = sigf(a0.x) * p0.x + sigf(a0.y) * p0.y
                + sigf(a0.z) * p0.z + sigf(a0.w) * p0.w
                + sigf(a1.x) * p1.x + sigf(a1.y) * p1.y
                + sigf(a1.z) * p1.z + sigf(a1.w) * p1.w;
#pragma unroll
        for (int o = 16; o > 0; o >>= 1) s += __shfl_xor_sync(0xFFFFFFFFu, s, o);
        if (lane == 0) r_ev[c] = s;
    }
    __syncthreads();

    // Phase E: exact histogram over [tr-1, tr+7); exact 50th edge
    for (int i = tid; i < 128; i += 1024) hist[i] = 0u;
    __syncthreads();
    const float base = tr - 1.0f;
    for (int c = tid; c < R; c += 1024) {
        int bin = (int)((r_ev[c] - base) * 16.0f);
        bin = bin < 0 ? 0 : (bin > 127 ? 127 : bin);
        atomicAdd(&hist[bin], 1u);
    }
    __syncthreads();
    if (tid == 0) {
        unsigned cum = 0;
        int eb = 0;
        for (int k = 127; k >= 0; k--) {
            cum += hist[k];
            if (cum >= NSEL) { eb = k; break; }
        }
        s_estar = base + eb * (1.0f / 16.0f);
    }
    __syncthreads();
    const float estar = s_estar;

    // Phase F: compact exact finalists
    for (int c = tid; c < R; c += 1024) {
        if (r_ev[c] >= estar) {
            int p = atomicAdd(&s_r2cnt, 1);
            if (p < RS2_CAP) { r2_idx[p] = r_idx[c]; r2_ev[p] = r_ev[c]; }
        }
    }
    __syncthreads();
    int R2 = s_r2cnt < RS2_CAP ? s_r2cnt : RS2_CAP;

    // Phase G: exact rank (value desc, index asc) + epilogue
    for (int jj = tid; jj < R2; jj += 1024) {
        float vj = r2_ev[jj];
        int   ij = r2_idx[jj];
        int rank = 0;
        for (int i = 0; i < R2; i++) {
            float vi = r2_ev[i];
            int   ii = r2_idx[i];
            if (vi > vj || (vi == vj && ii < ij)) rank++;
        }
        if (rank < NSEL) {
            int o = b * NSEL + rank;
            out[o] = vj;
            int q = ij / L_;
            int l = ij - q * L_;
            int label = 0;
#pragma unroll
            for (int t = 0; t < 80; t++)
                if (c_tok[t] == l) label = t;
            out[B_ * NSEL + o] = (float)label;
            const float* bb = bbox + (size_t)(b * Q_ + q) * 4;
            float cx = bb[0], cy = bb[1], w = bb[2], h = bb[3];
            float ih = tsz[2 * b + 0], iw = tsz[2 * b + 1];
            float* ob = out + 2 * B_ * NSEL + (size_t)o * 4;
            ob[0] = (cx - 0.5f * w) * iw;
            ob[1] = (cy - 0.5f * h) * ih;
            ob[2] = (cx + 0.5f * w) * iw;
            ob[3] = (cy + 0.5f * h) * ih;
        }
    }
}

// ---------------------------------------------------------------------------
extern "C" void kernel_launch(void* const* d_in, const int* in_sizes, int n_in,
                              void* d_out, int out_size) {
    const float* logits = (const float*)d_in[0];
    const float* bbox   = (const float*)d_in[1];
    const float* posmap = (const float*)d_in[2];
    const float* tsz    = (const float*)d_in[3];
    float* out = (float*)d_out;

    cudaFuncSetAttribute(gemm_kernel,
        cudaFuncAttributeMaxDynamicSharedMemorySize, NBUF * STG_BYTES);
    cudaFuncSetAttribute(final_kernel,
        cudaFuncAttributeMaxDynamicSharedMemorySize, CCAP * 12);

    zero_kernel<<<2, 1024>>>();

    const int n4 = (M_ * T_) / 4;
    sigmoid_kernel<<<(n4 + 255) / 256, 256>>>(logits, n4);
    posconv_kernel<<<(L_ * T_ / 2 + 255) / 256, 256>>>(posmap, L_ * T_ / 2);

    dim3 ggrid(M_ / 128, (L_ + 127) / 128);   // 450 x 7
    gemm_kernel<<<ggrid, 256, NBUF * STG_BYTES>>>();

    dim3 sgrid(B_, 4);
    cmax_scan_kernel<<<sgrid, 256>>>();
    dim3 cgrid(B_, 12);
    collect_kernel<<<cgrid, 256>>>();
    fixup_kernel<<<B_, 1024>>>();
    final_kernel<<<B_, 1024, CCAP * 12>>>(logits, bbox, tsz, out, posmap);
}